// round 1
// baseline (speedup 1.0000x reference)
#include <cuda_runtime.h>
#include <math.h>

#define BB 8
#define GG 256
#define NPTS 32
#define FEAT 273
#define CH 546
#define ENCD 384
#define DDIM 384
#define DEPTH 12
#define DIN 768
#define DSN 16
#define DCONV 4
#define DTR 24
#define GVIS 103
#define SEQL 103
#define BL (BB*GVIS)        /* 824 rows */
#define BGC (BB*GG)         /* 2048 groups */
#define NCOL (BGC*NPTS)     /* 65536 point columns */
#define NMASK 153
#define OUTH (BL*DDIM)      /* 316416 */
#define EPSV 1e-5f

/* ------------------------- scratch (device globals) ------------------------ */
__device__ float g_Xt[(size_t)FEAT * NCOL];
__device__ float g_fgT[(size_t)FEAT * BGC];
__device__ float g_biaseff[(size_t)CH * BGC];
__device__ float g_H1[(size_t)CH * NCOL];
__device__ float g_H2[(size_t)ENCD * NCOL];
__device__ float g_tokens[(size_t)BGC * ENCD];
__device__ int   g_vis[BL];
__device__ float g_h[BL * DDIM];
__device__ float g_res[BL * DDIM];
__device__ float g_hn[BL * DDIM];
__device__ float g_xz[BL * 2 * DIN];
__device__ float g_xi[BL * DIN];
__device__ float g_dbl[BL * (DTR + 2 * DSN)];
__device__ float g_dt[BL * DIN];
__device__ float g_u[BL * DIN];

/* ------------------------------ small helpers ----------------------------- */
__device__ __forceinline__ float siluf(float x) { return x / (1.f + expf(-x)); }
__device__ __forceinline__ float geluf(float x) { return 0.5f * x * (1.f + erff(x * 0.70710678118654752f)); }
__device__ __forceinline__ float softplusf(float x) {
    return (x > 20.f) ? x : log1pf(expf(x));
}

/* block (128 threads) sum-reduce of two values, result broadcast to all */
__device__ __forceinline__ void reduce2_128(float& s1, float& s2) {
    #pragma unroll
    for (int o = 16; o; o >>= 1) {
        s1 += __shfl_xor_sync(0xffffffffu, s1, o);
        s2 += __shfl_xor_sync(0xffffffffu, s2, o);
    }
    __shared__ float ra[4], rb[4];
    int w = threadIdx.x >> 5, l = threadIdx.x & 31;
    if (l == 0) { ra[w] = s1; rb[w] = s2; }
    __syncthreads();
    s1 = ra[0] + ra[1] + ra[2] + ra[3];
    s2 = rb[0] + rb[1] + rb[2] + rb[3];
    __syncthreads();
}

/* ------------------- encoder: transpose + per-group max ------------------- */
__global__ void k_trans_fg(const float* __restrict__ nb) {
    __shared__ float s[NPTS * FEAT]; /* 34944 B */
    int bg = blockIdx.x;
    const float* src = nb + (size_t)bg * NPTS * FEAT;
    for (int t = threadIdx.x; t < NPTS * FEAT; t += blockDim.x) s[t] = src[t];
    __syncthreads();
    int lane = threadIdx.x & 31, w = threadIdx.x >> 5;
    for (int c = w; c < FEAT; c += 8)
        g_Xt[(size_t)c * NCOL + bg * NPTS + lane] = s[lane * FEAT + c];
    for (int c = threadIdx.x; c < FEAT; c += blockDim.x) {
        float m = s[c];
        #pragma unroll
        for (int n = 1; n < NPTS; n++) m = fmaxf(m, s[n * FEAT + c]);
        g_fgT[(size_t)c * BGC + bg] = m;
    }
}

/* ------------------------------- generic SGEMM ----------------------------
 * C[M,N] = A[M,K](row-major, lda) * B (NN: [K,N] ldb / NT: [N,K] ldb)
 * EPI 0: none
 * EPI 1: + p0[m*BGC + (n>>5)]; BN(p1=mean,p2=var,p3=gamma,p4=beta); relu
 * EPI 2: + p0[m]
 * EPI 3: + p0[n]; softplus
 * -------------------------------------------------------------------------- */
template<int EPI, bool BT>
__global__ __launch_bounds__(256) void k_gemm(
    const float* __restrict__ A, int lda,
    const float* __restrict__ B, int ldb,
    float* __restrict__ C, int ldc,
    int M, int N, int K,
    const float* __restrict__ p0, const float* __restrict__ p1,
    const float* __restrict__ p2, const float* __restrict__ p3,
    const float* __restrict__ p4)
{
    __shared__ float As[8][128];
    __shared__ float Bs[8][128];
    int m0 = blockIdx.y * 128, n0 = blockIdx.x * 128;
    int tid = threadIdx.x;
    int tx = tid & 15, ty = tid >> 4;
    float acc[8][8];
    #pragma unroll
    for (int i = 0; i < 8; i++)
        #pragma unroll
        for (int j = 0; j < 8; j++) acc[i][j] = 0.f;

    for (int k0 = 0; k0 < K; k0 += 8) {
        #pragma unroll
        for (int i = 0; i < 4; i++) {
            int t = tid + i * 256;
            int kk = t & 7, mm = t >> 3;
            int gm = m0 + mm, gk = k0 + kk;
            As[kk][mm] = (gm < M && gk < K) ? A[(size_t)gm * lda + gk] : 0.f;
        }
        #pragma unroll
        for (int i = 0; i < 4; i++) {
            int t = tid + i * 256;
            if (!BT) {
                int kk = t >> 7, nn = t & 127;
                int gk = k0 + kk, gn = n0 + nn;
                Bs[kk][nn] = (gk < K && gn < N) ? B[(size_t)gk * ldb + gn] : 0.f;
            } else {
                int kk = t & 7, nn = t >> 3;
                int gn = n0 + nn, gk = k0 + kk;
                Bs[kk][nn] = (gn < N && gk < K) ? B[(size_t)gn * ldb + gk] : 0.f;
            }
        }
        __syncthreads();
        #pragma unroll
        for (int kk = 0; kk < 8; kk++) {
            float4 a0 = *reinterpret_cast<const float4*>(&As[kk][ty * 8]);
            float4 a1 = *reinterpret_cast<const float4*>(&As[kk][ty * 8 + 4]);
            float4 b0 = *reinterpret_cast<const float4*>(&Bs[kk][tx * 8]);
            float4 b1 = *reinterpret_cast<const float4*>(&Bs[kk][tx * 8 + 4]);
            float a[8] = {a0.x, a0.y, a0.z, a0.w, a1.x, a1.y, a1.z, a1.w};
            float b[8] = {b0.x, b0.y, b0.z, b0.w, b1.x, b1.y, b1.z, b1.w};
            #pragma unroll
            for (int i = 0; i < 8; i++)
                #pragma unroll
                for (int j = 0; j < 8; j++) acc[i][j] = fmaf(a[i], b[j], acc[i][j]);
        }
        __syncthreads();
    }

    #pragma unroll
    for (int i = 0; i < 8; i++) {
        int gm = m0 + ty * 8 + i;
        if (gm >= M) continue;
        #pragma unroll
        for (int j = 0; j < 8; j++) {
            int gn = n0 + tx * 8 + j;
            if (gn >= N) continue;
            float v = acc[i][j];
            if (EPI == 1) {
                v += p0[(size_t)gm * BGC + (gn >> 5)];
                v = (v - p1[gm]) * rsqrtf(p2[gm] + EPSV) * p3[gm] + p4[gm];
                v = fmaxf(v, 0.f);
            } else if (EPI == 2) {
                v += p0[gm];
            } else if (EPI == 3) {
                v += p0[gn];
                v = softplusf(v);
            }
            C[(size_t)gm * ldc + gn] = v;
        }
    }
}

/* ------------------------------ maxpool over n ---------------------------- */
__global__ void k_maxpool() {
    int gw = (blockIdx.x * blockDim.x + threadIdx.x) >> 5;
    int lane = threadIdx.x & 31;
    if (gw >= ENCD * BGC) return;
    int bg = gw % BGC, e = gw / BGC;
    float v = g_H2[(size_t)e * NCOL + bg * NPTS + lane];
    #pragma unroll
    for (int o = 16; o; o >>= 1) v = fmaxf(v, __shfl_xor_sync(0xffffffffu, v, o));
    if (lane == 0) g_tokens[(size_t)bg * ENCD + e] = v;
}

/* ---------------- visible-index extraction (bool width-robust) ------------ */
__global__ void k_visidx(const unsigned char* __restrict__ m8) {
    if (threadIdx.x != 0) return;
    int b = blockIdx.x;
    int c8 = 0;
    for (int g = 0; g < GG; g++) c8 += (m8[(size_t)b * GG + g] != 0);
    int cnt = 0;
    if (c8 == NMASK) {
        for (int g = 0; g < GG; g++)
            if (!m8[(size_t)b * GG + g]) { if (cnt < GVIS) g_vis[b * GVIS + cnt] = g; cnt++; }
    } else {
        const int* m32 = (const int*)m8;
        for (int g = 0; g < GG; g++)
            if (!m32[(size_t)b * GG + g]) { if (cnt < GVIS) g_vis[b * GVIS + cnt] = g; cnt++; }
    }
}

/* ------------- gather tokens/centers + pos MLP -> initial h ---------------- */
__global__ void k_pos(const float* __restrict__ center,
                      const float* __restrict__ w1, const float* __restrict__ b1,
                      const float* __restrict__ w2, const float* __restrict__ b2) {
    __shared__ float hcache[128];
    __shared__ float cc[3];
    int r = blockIdx.x;          /* r = b*103 + j */
    int b = r / GVIS;
    int g = g_vis[r];
    int tid = threadIdx.x;
    if (tid < 3) cc[tid] = center[((size_t)b * GG + g) * 3 + tid];
    __syncthreads();
    float a = w1[tid * 3] * cc[0] + w1[tid * 3 + 1] * cc[1] + w1[tid * 3 + 2] * cc[2] + b1[tid];
    hcache[tid] = geluf(a);
    __syncthreads();
    const float* tok = g_tokens + ((size_t)b * GG + g) * ENCD;
    for (int e = tid; e < DDIM; e += 128) {
        float acc = b2[e];
        const float* wr = w2 + (size_t)e * 128;
        #pragma unroll 8
        for (int k = 0; k < 128; k++) acc = fmaf(wr[k], hcache[k], acc);
        g_h[(size_t)r * DDIM + e] = acc + tok[e];
    }
}

/* ------------------- residual accumulate + LayerNorm ----------------------- */
__global__ void k_lnres(int layer, const float* __restrict__ w, const float* __restrict__ b) {
    int r = blockIdx.x, tid = threadIdx.x;
    float* res = g_res + (size_t)r * DDIM;
    const float* h = g_h + (size_t)r * DDIM;
    float v[3], s1 = 0.f, s2 = 0.f;
    #pragma unroll
    for (int i = 0; i < 3; i++) {
        int c = tid + i * 128;
        float x = h[c];
        if (layer > 0) x += res[c];
        v[i] = x; res[c] = x;
        s1 += x; s2 += x * x;
    }
    reduce2_128(s1, s2);
    float mu = s1 * (1.f / DDIM);
    float var = s2 * (1.f / DDIM) - mu * mu;
    float rstd = rsqrtf(var + EPSV);
    #pragma unroll
    for (int i = 0; i < 3; i++) {
        int c = tid + i * 128;
        g_hn[(size_t)r * DDIM + c] = (v[i] - mu) * rstd * w[c] + b[c];
    }
}

/* ---------------- depthwise causal conv (k=4) + SiLU ----------------------- */
__global__ void k_conv(const float* __restrict__ cw, const float* __restrict__ cb) {
    int idx = blockIdx.x * blockDim.x + threadIdx.x;
    if (idx >= BL * DIN) return;
    int d = idx % DIN, r = idx / DIN;
    int b = r / SEQL, l = r % SEQL;
    float acc = cb[d];
    #pragma unroll
    for (int k = 0; k < DCONV; k++) {
        int ll = l - (DCONV - 1) + k;
        if (ll >= 0) acc = fmaf(cw[d * DCONV + k], g_xz[((size_t)(b * SEQL + ll)) * (2 * DIN) + d], acc);
    }
    g_xi[idx] = siluf(acc);
}

/* --------------------------- selective scan -------------------------------- */
__global__ void k_scan(const float* __restrict__ alog, const float* __restrict__ Dp) {
    int b = blockIdx.x / 6;
    int d = (blockIdx.x % 6) * 128 + threadIdx.x;
    float A[DSN];
    #pragma unroll
    for (int s = 0; s < DSN; s++) A[s] = -expf(alog[(size_t)d * DSN + s]);
    float Dd = Dp[d];
    float h[DSN];
    #pragma unroll
    for (int s = 0; s < DSN; s++) h[s] = 0.f;
    for (int l = 0; l < SEQL; l++) {
        int r = b * SEQL + l;
        float dt = g_dt[(size_t)r * DIN + d];
        float x  = g_xi[(size_t)r * DIN + d];
        float dtx = dt * x;
        const float* bl = g_dbl + (size_t)r * (DTR + 2 * DSN);
        float y = 0.f;
        #pragma unroll
        for (int s = 0; s < DSN; s++) {
            float dA = __expf(dt * A[s]);
            h[s] = fmaf(dA, h[s], dtx * bl[DTR + s]);
            y = fmaf(h[s], bl[DTR + DSN + s], y);
        }
        float z = g_xz[(size_t)r * (2 * DIN) + DIN + d];
        g_u[(size_t)r * DIN + d] = (y + x * Dd) * siluf(z);
    }
}

/* ----------------------- final residual + double LN ------------------------ */
__global__ void k_final(float* __restrict__ out,
                        const float* __restrict__ w1, const float* __restrict__ b1,
                        const float* __restrict__ w2, const float* __restrict__ b2) {
    int r = blockIdx.x, tid = threadIdx.x;
    float v[3], s1 = 0.f, s2 = 0.f;
    #pragma unroll
    for (int i = 0; i < 3; i++) {
        int c = tid + i * 128;
        float x = g_res[(size_t)r * DDIM + c] + g_h[(size_t)r * DDIM + c];
        v[i] = x; s1 += x; s2 += x * x;
    }
    reduce2_128(s1, s2);
    float mu = s1 * (1.f / DDIM);
    float rstd = rsqrtf(s2 * (1.f / DDIM) - mu * mu + EPSV);
    s1 = 0.f; s2 = 0.f;
    #pragma unroll
    for (int i = 0; i < 3; i++) {
        int c = tid + i * 128;
        v[i] = (v[i] - mu) * rstd * w1[c] + b1[c];
        s1 += v[i]; s2 += v[i] * v[i];
    }
    reduce2_128(s1, s2);
    mu = s1 * (1.f / DDIM);
    rstd = rsqrtf(s2 * (1.f / DDIM) - mu * mu + EPSV);
    #pragma unroll
    for (int i = 0; i < 3; i++) {
        int c = tid + i * 128;
        out[(size_t)r * DDIM + c] = (v[i] - mu) * rstd * w2[c] + b2[c];
    }
}

/* -------------------------- mask -> output tail ---------------------------- */
__global__ void k_maskout(const unsigned char* __restrict__ m8, float* __restrict__ out, int out_size) {
    if (out_size < OUTH + BB * GG) return;
    __shared__ int use8;
    if (threadIdx.x == 0) {
        int c = 0;
        for (int g = 0; g < GG; g++) c += (m8[g] != 0);
        use8 = (c == NMASK);
    }
    __syncthreads();
    const int* m32 = (const int*)m8;
    for (int i = threadIdx.x; i < BB * GG; i += blockDim.x) {
        float v = use8 ? (m8[i] ? 1.f : 0.f) : (m32[i] ? 1.f : 0.f);
        out[OUTH + i] = v;
    }
}

/* ------------------------------- host driver ------------------------------- */
static inline dim3 ggrid(int M, int N) { return dim3((N + 127) / 128, (M + 127) / 128); }

extern "C" void kernel_launch(void* const* d_in, const int* in_sizes, int n_in,
                              void* d_out, int out_size) {
    (void)in_sizes; (void)n_in;
    const float* nb     = (const float*)d_in[0];
    const float* center = (const float*)d_in[1];
    const unsigned char* mask = (const unsigned char*)d_in[2];
    const float* c1w = (const float*)d_in[3];
    const float* c1b = (const float*)d_in[4];
    const float* bng = (const float*)d_in[5];
    const float* bnb = (const float*)d_in[6];
    const float* bnm = (const float*)d_in[7];
    const float* bnv = (const float*)d_in[8];
    const float* c2w = (const float*)d_in[9];
    const float* c2b = (const float*)d_in[10];
    const float* pw1 = (const float*)d_in[11];
    const float* pb1 = (const float*)d_in[12];
    const float* pw2 = (const float*)d_in[13];
    const float* pb2 = (const float*)d_in[14];
    const float* ipw = (const float*)d_in[15];
    const float* cw  = (const float*)d_in[16];
    const float* cb  = (const float*)d_in[17];
    const float* xpw = (const float*)d_in[18];
    const float* dpw = (const float*)d_in[19];
    const float* dpb = (const float*)d_in[20];
    const float* alog= (const float*)d_in[21];
    const float* Dp  = (const float*)d_in[22];
    const float* opw = (const float*)d_in[23];
    const float* lnw = (const float*)d_in[24];
    const float* lnb = (const float*)d_in[25];
    const float* nfw = (const float*)d_in[26];
    const float* nfb = (const float*)d_in[27];
    const float* n2w = (const float*)d_in[28];
    const float* n2b = (const float*)d_in[29];
    float* out = (float*)d_out;

    float *Xt, *fgT, *be, *H1, *H2, *hn, *xz, *xi, *dbl, *dt, *u, *hb;
    cudaGetSymbolAddress((void**)&Xt,  g_Xt);
    cudaGetSymbolAddress((void**)&fgT, g_fgT);
    cudaGetSymbolAddress((void**)&be,  g_biaseff);
    cudaGetSymbolAddress((void**)&H1,  g_H1);
    cudaGetSymbolAddress((void**)&H2,  g_H2);
    cudaGetSymbolAddress((void**)&hn,  g_hn);
    cudaGetSymbolAddress((void**)&xz,  g_xz);
    cudaGetSymbolAddress((void**)&xi,  g_xi);
    cudaGetSymbolAddress((void**)&dbl, g_dbl);
    cudaGetSymbolAddress((void**)&dt,  g_dt);
    cudaGetSymbolAddress((void**)&u,   g_u);
    cudaGetSymbolAddress((void**)&hb,  g_h);

    /* encoder */
    k_trans_fg<<<BGC, 256>>>(nb);
    k_gemm<2, false><<<ggrid(CH, BGC), 256>>>(c1w, CH, fgT, BGC, be, BGC,
                                              CH, BGC, FEAT, c1b, nullptr, nullptr, nullptr, nullptr);
    k_gemm<1, false><<<ggrid(CH, NCOL), 256>>>(c1w + FEAT, CH, Xt, NCOL, H1, NCOL,
                                               CH, NCOL, FEAT, be, bnm, bnv, bng, bnb);
    k_gemm<2, false><<<ggrid(ENCD, NCOL), 256>>>(c2w, CH, H1, NCOL, H2, NCOL,
                                                 ENCD, NCOL, CH, c2b, nullptr, nullptr, nullptr, nullptr);
    k_maxpool<<<(ENCD * BGC) / 8, 256>>>();

    /* gather + pos embed */
    k_visidx<<<BB, 32>>>(mask);
    k_pos<<<BL, 128>>>(center, pw1, pb1, pw2, pb2);

    /* mamba stack */
    for (int i = 0; i < DEPTH; i++) {
        k_lnres<<<BL, 128>>>(i, lnw + (size_t)i * DDIM, lnb + (size_t)i * DDIM);
        k_gemm<0, true><<<ggrid(BL, 2 * DIN), 256>>>(hn, DDIM,
            ipw + (size_t)i * 2 * DIN * DDIM, DDIM, xz, 2 * DIN,
            BL, 2 * DIN, DDIM, nullptr, nullptr, nullptr, nullptr, nullptr);
        k_conv<<<(BL * DIN + 255) / 256, 256>>>(cw + (size_t)i * DIN * DCONV, cb + (size_t)i * DIN);
        k_gemm<0, true><<<ggrid(BL, DTR + 2 * DSN), 256>>>(xi, DIN,
            xpw + (size_t)i * (DTR + 2 * DSN) * DIN, DIN, dbl, DTR + 2 * DSN,
            BL, DTR + 2 * DSN, DIN, nullptr, nullptr, nullptr, nullptr, nullptr);
        k_gemm<3, true><<<ggrid(BL, DIN), 256>>>(dbl, DTR + 2 * DSN,
            dpw + (size_t)i * DIN * DTR, DTR, dt, DIN,
            BL, DIN, DTR, dpb + (size_t)i * DIN, nullptr, nullptr, nullptr, nullptr);
        k_scan<<<BB * 6, 128>>>(alog + (size_t)i * DIN * DSN, Dp + (size_t)i * DIN);
        k_gemm<0, true><<<ggrid(BL, DDIM), 256>>>(u, DIN,
            opw + (size_t)i * DDIM * DIN, DIN, hb, DDIM,
            BL, DDIM, DIN, nullptr, nullptr, nullptr, nullptr, nullptr);
    }

    /* final norms + outputs */
    k_final<<<BL, 128>>>(out, nfw, nfb, n2w, n2b);
    k_maskout<<<1, 256>>>(mask, out, out_size);
}

// round 2
// speedup vs baseline: 1.5634x; 1.5634x over previous
#include <cuda_runtime.h>
#include <math.h>

#define BB 8
#define GG 256
#define NPTS 32
#define FEAT 273
#define CH 546
#define ENCD 384
#define DDIM 384
#define DEPTH 12
#define DIN 768
#define DSN 16
#define DCONV 4
#define DTR 24
#define GVIS 103
#define SEQL 103
#define BL (BB*GVIS)        /* 824 rows */
#define BGC (BB*GG)         /* 2048 groups */
#define NCOL (BGC*NPTS)     /* 65536 point columns */
#define NMASK 153
#define OUTH (BL*DDIM)      /* 316416 */
#define NXP (DIN + 2*DSN)   /* 800: merged xproj output width */
#define EPSV 1e-5f

/* ------------------------- scratch (device globals) ------------------------ */
__device__ float g_Xt[(size_t)FEAT * NCOL];
__device__ float g_fgT[(size_t)FEAT * BGC];
__device__ float g_biaseff[(size_t)CH * BGC];
__device__ float g_H1[(size_t)CH * NCOL];
__device__ float g_tokens[(size_t)BGC * ENCD];
__device__ float g_Wc[(size_t)DEPTH * NXP * DIN];
__device__ int   g_vis[BL];
__device__ float g_h[BL * DDIM];
__device__ float g_res[BL * DDIM];
__device__ float g_hn[BL * DDIM];
__device__ float g_xz[BL * 2 * DIN];
__device__ float g_xi[BL * DIN];
__device__ float g_dt[BL * DIN];
__device__ float g_bc[BL * 2 * DSN];
__device__ float g_u[BL * DIN];

/* ------------------------------ small helpers ----------------------------- */
__device__ __forceinline__ float siluf(float x) { return x / (1.f + expf(-x)); }
__device__ __forceinline__ float geluf(float x) { return 0.5f * x * (1.f + erff(x * 0.70710678118654752f)); }
__device__ __forceinline__ float softplusf(float x) {
    return (x > 20.f) ? x : log1pf(expf(x));
}

__device__ __forceinline__ void reduce2_128(float& s1, float& s2) {
    #pragma unroll
    for (int o = 16; o; o >>= 1) {
        s1 += __shfl_xor_sync(0xffffffffu, s1, o);
        s2 += __shfl_xor_sync(0xffffffffu, s2, o);
    }
    __shared__ float ra[4], rb[4];
    int w = threadIdx.x >> 5, l = threadIdx.x & 31;
    if (l == 0) { ra[w] = s1; rb[w] = s2; }
    __syncthreads();
    s1 = ra[0] + ra[1] + ra[2] + ra[3];
    s2 = rb[0] + rb[1] + rb[2] + rb[3];
    __syncthreads();
}

/* ------------------- encoder: transpose + per-group max ------------------- */
__global__ void k_trans_fg(const float* __restrict__ nb) {
    __shared__ float s[NPTS * FEAT];
    int bg = blockIdx.x;
    const float* src = nb + (size_t)bg * NPTS * FEAT;
    for (int t = threadIdx.x; t < NPTS * FEAT; t += blockDim.x) s[t] = src[t];
    __syncthreads();
    int lane = threadIdx.x & 31, w = threadIdx.x >> 5;
    for (int c = w; c < FEAT; c += 8)
        g_Xt[(size_t)c * NCOL + bg * NPTS + lane] = s[lane * FEAT + c];
    for (int c = threadIdx.x; c < FEAT; c += blockDim.x) {
        float m = s[c];
        #pragma unroll
        for (int n = 1; n < NPTS; n++) m = fmaxf(m, s[n * FEAT + c]);
        g_fgT[(size_t)c * BGC + bg] = m;
    }
}

/* ------------------- combined dt/x_proj weight precompute ------------------ */
__global__ void k_wcomb(const float* __restrict__ dpw, const float* __restrict__ xpw) {
    size_t idx = (size_t)blockIdx.x * 256 + threadIdx.x;
    if (idx >= (size_t)DEPTH * NXP * DIN) return;
    int col = (int)(idx % DIN);
    int rem = (int)(idx / DIN);
    int row = rem % NXP;
    int l   = rem / NXP;
    const float* xp = xpw + (size_t)l * (DTR + 2 * DSN) * DIN;
    float v;
    if (row < DIN) {
        const float* dr = dpw + (size_t)l * DIN * DTR + (size_t)row * DTR;
        v = 0.f;
        #pragma unroll
        for (int t = 0; t < DTR; t++) v = fmaf(dr[t], xp[(size_t)t * DIN + col], v);
    } else {
        v = xp[(size_t)(DTR + (row - DIN)) * DIN + col];
    }
    g_Wc[idx] = v;
}

/* ------------------------------- generic SGEMM ----------------------------
 * C[M,N] = A[M,K](row-major) * B (NN: [K,N] / NT: [N,K])
 * double-buffered smem, padded stride TILE+4, 1 sync/iter.
 * EPI 0: none
 * EPI 1: + p0[m*BGC + (n>>5)]; BN(p1=m,p2=v,p3=g,p4=b); relu      (encoder H1)
 * EPI 2: + p0[m]                                                  (bias-eff)
 * EPI 4: n<DIN -> C = softplus(v+p0[n]); else C2[m*32 + n-DIN]=v  (merged xproj)
 * EPI 5: fused group-maxpool: +p0[m], max over 32-col group -> C2 (tokens)
 * -------------------------------------------------------------------------- */
template<int EPI, bool BT, int TM>
__global__ __launch_bounds__(256) void k_gemm(
    const float* __restrict__ A, int lda,
    const float* __restrict__ B, int ldb,
    float* __restrict__ C, int ldc,
    int M, int N, int K,
    const float* __restrict__ p0, const float* __restrict__ p1,
    const float* __restrict__ p2, const float* __restrict__ p3,
    const float* __restrict__ p4, float* __restrict__ C2)
{
    constexpr int RT = TM / 16;          /* per-thread tile (8 or 4)   */
    constexpr int LD = TM + 4;           /* padded smem row stride     */
    constexpr int LA = TM * 8 / 256;     /* loads per thread per iter  */
    __shared__ __align__(16) float As[2][8 * LD];
    __shared__ __align__(16) float Bs[2][8 * LD];
    const int m0 = blockIdx.y * TM, n0 = blockIdx.x * TM;
    const int tid = threadIdx.x;
    const int tx = tid & 15, ty = tid >> 4;

    float acc[RT][RT];
    #pragma unroll
    for (int i = 0; i < RT; i++)
        #pragma unroll
        for (int j = 0; j < RT; j++) acc[i][j] = 0.f;

    float ra[LA], rb[LA];
    const int nk = (K + 7) >> 3;

    /* ---- load tile kt into registers ---- */
    auto loadT = [&](int kt) {
        int k0 = kt * 8;
        #pragma unroll
        for (int i = 0; i < LA; i++) {
            int t = tid + i * 256;
            int kk = t & 7, mm = t >> 3;
            int gm = m0 + mm, gk = k0 + kk;
            ra[i] = (gm < M && gk < K) ? A[(size_t)gm * lda + gk] : 0.f;
        }
        #pragma unroll
        for (int i = 0; i < LA; i++) {
            int t = tid + i * 256;
            if (BT) {
                int kk = t & 7, nn = t >> 3;
                int gn = n0 + nn, gk = k0 + kk;
                rb[i] = (gn < N && gk < K) ? B[(size_t)gn * ldb + gk] : 0.f;
            } else {
                int kk = t / TM, nn = t % TM;
                int gk = k0 + kk, gn = n0 + nn;
                rb[i] = (gk < K && gn < N) ? B[(size_t)gk * ldb + gn] : 0.f;
            }
        }
    };
    auto storeT = [&](int buf) {
        #pragma unroll
        for (int i = 0; i < LA; i++) {
            int t = tid + i * 256;
            As[buf][(t & 7) * LD + (t >> 3)] = ra[i];
        }
        #pragma unroll
        for (int i = 0; i < LA; i++) {
            int t = tid + i * 256;
            if (BT) Bs[buf][(t & 7) * LD + (t >> 3)] = rb[i];
            else    Bs[buf][(t / TM) * LD + (t % TM)] = rb[i];
        }
    };

    loadT(0);
    storeT(0);
    __syncthreads();

    for (int kt = 0; kt < nk; kt++) {
        int cur = kt & 1;
        if (kt + 1 < nk) loadT(kt + 1);
        #pragma unroll
        for (int kk = 0; kk < 8; kk++) {
            float a[RT], b[RT];
            #pragma unroll
            for (int v = 0; v < RT / 4; v++) {
                float4 t4 = *reinterpret_cast<const float4*>(&As[cur][kk * LD + ty * RT + v * 4]);
                a[v * 4 + 0] = t4.x; a[v * 4 + 1] = t4.y; a[v * 4 + 2] = t4.z; a[v * 4 + 3] = t4.w;
            }
            #pragma unroll
            for (int v = 0; v < RT / 4; v++) {
                float4 t4 = *reinterpret_cast<const float4*>(&Bs[cur][kk * LD + tx * RT + v * 4]);
                b[v * 4 + 0] = t4.x; b[v * 4 + 1] = t4.y; b[v * 4 + 2] = t4.z; b[v * 4 + 3] = t4.w;
            }
            #pragma unroll
            for (int i = 0; i < RT; i++)
                #pragma unroll
                for (int j = 0; j < RT; j++) acc[i][j] = fmaf(a[i], b[j], acc[i][j]);
        }
        if (kt + 1 < nk) storeT(cur ^ 1);
        __syncthreads();
    }

    if (EPI == 5) {
        /* fused maxpool epilogue (TM=128, exact tiles): group = 32 cols = 4 tx */
        #pragma unroll
        for (int i = 0; i < RT; i++) {
            int gm = m0 + ty * RT + i;
            float bias = p0[gm];
            float vmax = -INFINITY;
            #pragma unroll
            for (int j = 0; j < RT; j++) vmax = fmaxf(vmax, acc[i][j] + bias);
            vmax = fmaxf(vmax, __shfl_xor_sync(0xffffffffu, vmax, 1));
            vmax = fmaxf(vmax, __shfl_xor_sync(0xffffffffu, vmax, 2));
            if ((tx & 3) == 0)
                C2[(size_t)((n0 >> 5) + (tx >> 2)) * ENCD + gm] = vmax;
        }
        return;
    }

    #pragma unroll
    for (int i = 0; i < RT; i++) {
        int gm = m0 + ty * RT + i;
        if (gm >= M) continue;
        #pragma unroll
        for (int j = 0; j < RT; j++) {
            int gn = n0 + tx * RT + j;
            if (gn >= N) continue;
            float v = acc[i][j];
            if (EPI == 1) {
                v += p0[(size_t)gm * BGC + (gn >> 5)];
                v = (v - p1[gm]) * rsqrtf(p2[gm] + EPSV) * p3[gm] + p4[gm];
                v = fmaxf(v, 0.f);
                C[(size_t)gm * ldc + gn] = v;
            } else if (EPI == 2) {
                C[(size_t)gm * ldc + gn] = v + p0[gm];
            } else if (EPI == 4) {
                if (gn < DIN) C[(size_t)gm * ldc + gn] = softplusf(v + p0[gn]);
                else          C2[(size_t)gm * (2 * DSN) + (gn - DIN)] = v;
            } else {
                C[(size_t)gm * ldc + gn] = v;
            }
        }
    }
}

/* ---------------- visible-index extraction (bool width-robust) ------------ */
__global__ void k_visidx(const unsigned char* __restrict__ m8) {
    if (threadIdx.x != 0) return;
    int b = blockIdx.x;
    int c8 = 0;
    for (int g = 0; g < GG; g++) c8 += (m8[(size_t)b * GG + g] != 0);
    int cnt = 0;
    if (c8 == NMASK) {
        for (int g = 0; g < GG; g++)
            if (!m8[(size_t)b * GG + g]) { if (cnt < GVIS) g_vis[b * GVIS + cnt] = g; cnt++; }
    } else {
        const int* m32 = (const int*)m8;
        for (int g = 0; g < GG; g++)
            if (!m32[(size_t)b * GG + g]) { if (cnt < GVIS) g_vis[b * GVIS + cnt] = g; cnt++; }
    }
}

/* ------------- gather tokens/centers + pos MLP -> initial h ---------------- */
__global__ void k_pos(const float* __restrict__ center,
                      const float* __restrict__ w1, const float* __restrict__ b1,
                      const float* __restrict__ w2, const float* __restrict__ b2) {
    __shared__ float hcache[128];
    __shared__ float cc[3];
    int r = blockIdx.x;
    int b = r / GVIS;
    int g = g_vis[r];
    int tid = threadIdx.x;
    if (tid < 3) cc[tid] = center[((size_t)b * GG + g) * 3 + tid];
    __syncthreads();
    float a = w1[tid * 3] * cc[0] + w1[tid * 3 + 1] * cc[1] + w1[tid * 3 + 2] * cc[2] + b1[tid];
    hcache[tid] = geluf(a);
    __syncthreads();
    const float* tok = g_tokens + ((size_t)b * GG + g) * ENCD;
    for (int e = tid; e < DDIM; e += 128) {
        float acc = b2[e];
        const float* wr = w2 + (size_t)e * 128;
        #pragma unroll 8
        for (int k = 0; k < 128; k++) acc = fmaf(wr[k], hcache[k], acc);
        g_h[(size_t)r * DDIM + e] = acc + tok[e];
    }
}

/* ------------------- residual accumulate + LayerNorm ----------------------- */
__global__ void k_lnres(int layer, const float* __restrict__ w, const float* __restrict__ b) {
    int r = blockIdx.x, tid = threadIdx.x;
    float* res = g_res + (size_t)r * DDIM;
    const float* h = g_h + (size_t)r * DDIM;
    float v[3], s1 = 0.f, s2 = 0.f;
    #pragma unroll
    for (int i = 0; i < 3; i++) {
        int c = tid + i * 128;
        float x = h[c];
        if (layer > 0) x += res[c];
        v[i] = x; res[c] = x;
        s1 += x; s2 += x * x;
    }
    reduce2_128(s1, s2);
    float mu = s1 * (1.f / DDIM);
    float var = s2 * (1.f / DDIM) - mu * mu;
    float rstd = rsqrtf(var + EPSV);
    #pragma unroll
    for (int i = 0; i < 3; i++) {
        int c = tid + i * 128;
        g_hn[(size_t)r * DDIM + c] = (v[i] - mu) * rstd * w[c] + b[c];
    }
}

/* ---------------- depthwise causal conv (k=4) + SiLU ----------------------- */
__global__ void k_conv(const float* __restrict__ cw, const float* __restrict__ cb) {
    int idx = blockIdx.x * blockDim.x + threadIdx.x;
    if (idx >= BL * DIN) return;
    int d = idx % DIN, r = idx / DIN;
    int b = r / SEQL, l = r % SEQL;
    float acc = cb[d];
    #pragma unroll
    for (int k = 0; k < DCONV; k++) {
        int ll = l - (DCONV - 1) + k;
        if (ll >= 0) acc = fmaf(cw[d * DCONV + k], g_xz[((size_t)(b * SEQL + ll)) * (2 * DIN) + d], acc);
    }
    g_xi[idx] = siluf(acc);
}

/* --------------------------- selective scan -------------------------------- */
__global__ void k_scan(const float* __restrict__ alog, const float* __restrict__ Dp) {
    int b = blockIdx.x / 6;
    int d = (blockIdx.x % 6) * 128 + threadIdx.x;
    float A[DSN];
    #pragma unroll
    for (int s = 0; s < DSN; s++) A[s] = -expf(alog[(size_t)d * DSN + s]);
    float Dd = Dp[d];
    float h[DSN];
    #pragma unroll
    for (int s = 0; s < DSN; s++) h[s] = 0.f;
    for (int l = 0; l < SEQL; l++) {
        int r = b * SEQL + l;
        float dt = g_dt[(size_t)r * DIN + d];
        float x  = g_xi[(size_t)r * DIN + d];
        float dtx = dt * x;
        const float* bl = g_bc + (size_t)r * (2 * DSN);
        float y = 0.f;
        #pragma unroll
        for (int s = 0; s < DSN; s++) {
            float dA = __expf(dt * A[s]);
            h[s] = fmaf(dA, h[s], dtx * bl[s]);
            y = fmaf(h[s], bl[DSN + s], y);
        }
        float z = g_xz[(size_t)r * (2 * DIN) + DIN + d];
        g_u[(size_t)r * DIN + d] = (y + x * Dd) * siluf(z);
    }
}

/* ----------------------- final residual + double LN ------------------------ */
__global__ void k_final(float* __restrict__ out,
                        const float* __restrict__ w1, const float* __restrict__ b1,
                        const float* __restrict__ w2, const float* __restrict__ b2) {
    int r = blockIdx.x, tid = threadIdx.x;
    float v[3], s1 = 0.f, s2 = 0.f;
    #pragma unroll
    for (int i = 0; i < 3; i++) {
        int c = tid + i * 128;
        float x = g_res[(size_t)r * DDIM + c] + g_h[(size_t)r * DDIM + c];
        v[i] = x; s1 += x; s2 += x * x;
    }
    reduce2_128(s1, s2);
    float mu = s1 * (1.f / DDIM);
    float rstd = rsqrtf(s2 * (1.f / DDIM) - mu * mu + EPSV);
    s1 = 0.f; s2 = 0.f;
    #pragma unroll
    for (int i = 0; i < 3; i++) {
        int c = tid + i * 128;
        v[i] = (v[i] - mu) * rstd * w1[c] + b1[c];
        s1 += v[i]; s2 += v[i] * v[i];
    }
    reduce2_128(s1, s2);
    mu = s1 * (1.f / DDIM);
    rstd = rsqrtf(s2 * (1.f / DDIM) - mu * mu + EPSV);
    #pragma unroll
    for (int i = 0; i < 3; i++) {
        int c = tid + i * 128;
        out[(size_t)r * DDIM + c] = (v[i] - mu) * rstd * w2[c] + b2[c];
    }
}

/* -------------------------- mask -> output tail ---------------------------- */
__global__ void k_maskout(const unsigned char* __restrict__ m8, float* __restrict__ out, int out_size) {
    if (out_size < OUTH + BB * GG) return;
    __shared__ int use8;
    if (threadIdx.x == 0) {
        int c = 0;
        for (int g = 0; g < GG; g++) c += (m8[g] != 0);
        use8 = (c == NMASK);
    }
    __syncthreads();
    const int* m32 = (const int*)m8;
    for (int i = threadIdx.x; i < BB * GG; i += blockDim.x) {
        float v = use8 ? (m8[i] ? 1.f : 0.f) : (m32[i] ? 1.f : 0.f);
        out[OUTH + i] = v;
    }
}

/* ------------------------------- host driver ------------------------------- */
static inline dim3 g2(int M, int N, int T) { return dim3((N + T - 1) / T, (M + T - 1) / T); }

extern "C" void kernel_launch(void* const* d_in, const int* in_sizes, int n_in,
                              void* d_out, int out_size) {
    (void)in_sizes; (void)n_in;
    const float* nb     = (const float*)d_in[0];
    const float* center = (const float*)d_in[1];
    const unsigned char* mask = (const unsigned char*)d_in[2];
    const float* c1w = (const float*)d_in[3];
    const float* c1b = (const float*)d_in[4];
    const float* bng = (const float*)d_in[5];
    const float* bnb = (const float*)d_in[6];
    const float* bnm = (const float*)d_in[7];
    const float* bnv = (const float*)d_in[8];
    const float* c2w = (const float*)d_in[9];
    const float* c2b = (const float*)d_in[10];
    const float* pw1 = (const float*)d_in[11];
    const float* pb1 = (const float*)d_in[12];
    const float* pw2 = (const float*)d_in[13];
    const float* pb2 = (const float*)d_in[14];
    const float* ipw = (const float*)d_in[15];
    const float* cw  = (const float*)d_in[16];
    const float* cb  = (const float*)d_in[17];
    const float* xpw = (const float*)d_in[18];
    const float* dpw = (const float*)d_in[19];
    const float* dpb = (const float*)d_in[20];
    const float* alog= (const float*)d_in[21];
    const float* Dp  = (const float*)d_in[22];
    const float* opw = (const float*)d_in[23];
    const float* lnw = (const float*)d_in[24];
    const float* lnb = (const float*)d_in[25];
    const float* nfw = (const float*)d_in[26];
    const float* nfb = (const float*)d_in[27];
    const float* n2w = (const float*)d_in[28];
    const float* n2b = (const float*)d_in[29];
    float* out = (float*)d_out;

    float *Xt, *fgT, *be, *H1, *tok, *Wc, *hn, *xz, *xi, *dtb, *bc, *u, *hb;
    cudaGetSymbolAddress((void**)&Xt,  g_Xt);
    cudaGetSymbolAddress((void**)&fgT, g_fgT);
    cudaGetSymbolAddress((void**)&be,  g_biaseff);
    cudaGetSymbolAddress((void**)&H1,  g_H1);
    cudaGetSymbolAddress((void**)&tok, g_tokens);
    cudaGetSymbolAddress((void**)&Wc,  g_Wc);
    cudaGetSymbolAddress((void**)&hn,  g_hn);
    cudaGetSymbolAddress((void**)&xz,  g_xz);
    cudaGetSymbolAddress((void**)&xi,  g_xi);
    cudaGetSymbolAddress((void**)&dtb, g_dt);
    cudaGetSymbolAddress((void**)&bc,  g_bc);
    cudaGetSymbolAddress((void**)&u,   g_u);
    cudaGetSymbolAddress((void**)&hb,  g_h);

    /* combined dt/x_proj weights (independent of data path; do first) */
    k_wcomb<<<(int)(((size_t)DEPTH * NXP * DIN + 255) / 256), 256>>>(dpw, xpw);

    /* encoder */
    k_trans_fg<<<BGC, 256>>>(nb);
    k_gemm<2, false, 64><<<g2(CH, BGC, 64), 256>>>(c1w, CH, fgT, BGC, be, BGC,
        CH, BGC, FEAT, c1b, nullptr, nullptr, nullptr, nullptr, nullptr);
    k_gemm<1, false, 128><<<g2(CH, NCOL, 128), 256>>>(c1w + FEAT, CH, Xt, NCOL, H1, NCOL,
        CH, NCOL, FEAT, be, bnm, bnv, bng, bnb, nullptr);
    k_gemm<5, false, 128><<<g2(ENCD, NCOL, 128), 256>>>(c2w, CH, H1, NCOL, nullptr, 0,
        ENCD, NCOL, CH, c2b, nullptr, nullptr, nullptr, nullptr, tok);

    /* gather + pos embed */
    k_visidx<<<BB, 32>>>(mask);
    k_pos<<<BL, 128>>>(center, pw1, pb1, pw2, pb2);

    /* mamba stack */
    for (int i = 0; i < DEPTH; i++) {
        k_lnres<<<BL, 128>>>(i, lnw + (size_t)i * DDIM, lnb + (size_t)i * DDIM);
        k_gemm<0, true, 64><<<g2(BL, 2 * DIN, 64), 256>>>(hn, DDIM,
            ipw + (size_t)i * 2 * DIN * DDIM, DDIM, xz, 2 * DIN,
            BL, 2 * DIN, DDIM, nullptr, nullptr, nullptr, nullptr, nullptr, nullptr);
        k_conv<<<(BL * DIN + 255) / 256, 256>>>(cw + (size_t)i * DIN * DCONV, cb + (size_t)i * DIN);
        k_gemm<4, true, 64><<<g2(BL, NXP, 64), 256>>>(xi, DIN,
            Wc + (size_t)i * NXP * DIN, DIN, dtb, DIN,
            BL, NXP, DIN, dpb + (size_t)i * DIN, nullptr, nullptr, nullptr, nullptr, bc);
        k_scan<<<BB * 6, 128>>>(alog + (size_t)i * DIN * DSN, Dp + (size_t)i * DIN);
        k_gemm<0, true, 64><<<g2(BL, DDIM, 64), 256>>>(u, DIN,
            opw + (size_t)i * DDIM * DIN, DIN, hb, DDIM,
            BL, DDIM, DIN, nullptr, nullptr, nullptr, nullptr, nullptr, nullptr);
    }

    /* final norms + outputs */
    k_final<<<BL, 128>>>(out, nfw, nfb, n2w, n2b);
    k_maskout<<<1, 256>>>(mask, out, out_size);
}

// round 4
// speedup vs baseline: 2.3837x; 1.5247x over previous
#include <cuda_runtime.h>
#include <cuda_bf16.h>
#include <math.h>
#include <stdint.h>

#define BB 8
#define GG 256
#define NPTS 32
#define FEAT 273
#define CH 546
#define ENCD 384
#define DDIM 384
#define DEPTH 12
#define DIN 768
#define DSN 16
#define DCONV 4
#define DTR 24
#define GVIS 103
#define SEQL 103
#define BL (BB*GVIS)        /* 824 rows */
#define BLP 896             /* padded to 7*128 */
#define BGC (BB*GG)         /* 2048 groups */
#define NCOL (BGC*NPTS)     /* 65536 point columns */
#define NMASK 153
#define OUTH (BL*DDIM)      /* 316416 */
#define NXP (DIN + 2*DSN)   /* 800 */
#define NXPP 896            /* padded */
#define K1P 320             /* FEAT 273 -> padded */
#define M1P 640             /* CH 546 -> padded  */
#define K2P 576             /* CH 546 -> padded  */
#define EPSV 1e-5f

/* ------------------------- scratch (device globals) ------------------------ */
__device__ float g_fgT[(size_t)FEAT * BGC];
__device__ float g_biaseff[(size_t)CH * BGC];
__device__ float g_tokens[(size_t)BGC * ENCD];
__device__ int   g_vis[BL];
__device__ float g_h[BL * DDIM];
__device__ float g_res[BL * DDIM];
__device__ float g_xz[BL * 2 * DIN];
__device__ float g_xi[BL * DIN];
__device__ float g_dt[BL * DIN];
__device__ float g_bc[BL * 2 * DSN];

/* bf16-split operand buffers */
__device__ __align__(256) __nv_bfloat16 g_nbh[(size_t)NCOL * K1P];
__device__ __align__(256) __nv_bfloat16 g_nbl[(size_t)NCOL * K1P];
__device__ __align__(256) __nv_bfloat16 g_w1h[(size_t)M1P * K1P];
__device__ __align__(256) __nv_bfloat16 g_w1l[(size_t)M1P * K1P];
__device__ __align__(256) __nv_bfloat16 g_w2h[(size_t)ENCD * K2P];
__device__ __align__(256) __nv_bfloat16 g_w2l[(size_t)ENCD * K2P];
__device__ __align__(256) __nv_bfloat16 g_h1h[(size_t)NCOL * K2P];
__device__ __align__(256) __nv_bfloat16 g_h1l[(size_t)NCOL * K2P];
__device__ __align__(256) __nv_bfloat16 g_ipwh[(size_t)DEPTH * 2 * DIN * DDIM];
__device__ __align__(256) __nv_bfloat16 g_ipwl[(size_t)DEPTH * 2 * DIN * DDIM];
__device__ __align__(256) __nv_bfloat16 g_wch[(size_t)DEPTH * NXPP * DIN];
__device__ __align__(256) __nv_bfloat16 g_wcl[(size_t)DEPTH * NXPP * DIN];
__device__ __align__(256) __nv_bfloat16 g_opwh[(size_t)DEPTH * DDIM * DIN];
__device__ __align__(256) __nv_bfloat16 g_opwl[(size_t)DEPTH * DDIM * DIN];
__device__ __align__(256) __nv_bfloat16 g_hnh[(size_t)BLP * DDIM];
__device__ __align__(256) __nv_bfloat16 g_hnl[(size_t)BLP * DDIM];
__device__ __align__(256) __nv_bfloat16 g_xih[(size_t)BLP * DIN];
__device__ __align__(256) __nv_bfloat16 g_xil[(size_t)BLP * DIN];
__device__ __align__(256) __nv_bfloat16 g_uh[(size_t)BLP * DIN];
__device__ __align__(256) __nv_bfloat16 g_ul[(size_t)BLP * DIN];

/* ------------------------------ small helpers ----------------------------- */
__device__ __forceinline__ float siluf(float x) { return x / (1.f + expf(-x)); }
__device__ __forceinline__ float geluf(float x) { return 0.5f * x * (1.f + erff(x * 0.70710678118654752f)); }
__device__ __forceinline__ float softplusf(float x) { return (x > 20.f) ? x : log1pf(expf(x)); }
__device__ __forceinline__ void split2(float v, __nv_bfloat16* h, __nv_bfloat16* l) {
    __nv_bfloat16 hh = __float2bfloat16(v);
    *h = hh;
    *l = __float2bfloat16(v - __bfloat162float(hh));
}

__device__ __forceinline__ void reduce2_128(float& s1, float& s2) {
    #pragma unroll
    for (int o = 16; o; o >>= 1) {
        s1 += __shfl_xor_sync(0xffffffffu, s1, o);
        s2 += __shfl_xor_sync(0xffffffffu, s2, o);
    }
    __shared__ float ra[4], rb[4];
    int w = threadIdx.x >> 5, l = threadIdx.x & 31;
    if (l == 0) { ra[w] = s1; rb[w] = s2; }
    __syncthreads();
    s1 = ra[0] + ra[1] + ra[2] + ra[3];
    s2 = rb[0] + rb[1] + rb[2] + rb[3];
    __syncthreads();
}

/* --------------------------- PTX wrappers --------------------------------- */
__device__ __forceinline__ uint32_t smem_u32(const void* p) {
    uint32_t a;
    asm("{ .reg .u64 t; cvta.to.shared.u64 t, %1; cvt.u32.u64 %0, t; }" : "=r"(a) : "l"(p));
    return a;
}
#define SWZ128(o) ((o) ^ (((o) >> 3) & 0x70))
#define CP_ASYNC16(d, s) asm volatile("cp.async.cg.shared.global [%0], [%1], 16;" :: "r"(d), "l"(s))
#define CP_COMMIT()      asm volatile("cp.async.commit_group;" ::: "memory")
#define CP_WAIT1()       asm volatile("cp.async.wait_group 1;" ::: "memory")
#define CP_WAIT0()       asm volatile("cp.async.wait_group 0;" ::: "memory")

__device__ __forceinline__ void ldm_x4(uint32_t* r, uint32_t addr) {
    asm volatile("ldmatrix.sync.aligned.m8n8.x4.shared.b16 {%0,%1,%2,%3}, [%4];"
        : "=r"(r[0]), "=r"(r[1]), "=r"(r[2]), "=r"(r[3]) : "r"(addr));
}
__device__ __forceinline__ void mma16816(float* c, const uint32_t* a, uint32_t b0, uint32_t b1) {
    asm volatile("mma.sync.aligned.m16n8k16.row.col.f32.bf16.bf16.f32 "
        "{%0,%1,%2,%3}, {%4,%5,%6,%7}, {%8,%9}, {%0,%1,%2,%3};"
        : "+f"(c[0]), "+f"(c[1]), "+f"(c[2]), "+f"(c[3])
        : "r"(a[0]), "r"(a[1]), "r"(a[2]), "r"(a[3]), "r"(b0), "r"(b1));
}

/* =================== generic bf16-split mma.sync GEMM ======================
 * D[M,N] = A[M,K] * B[N,K]^T  (h/l split bf16, K-major, ld = Kpad)
 * grid = (Ntiles, Mtiles), 256 threads = 8 warps (2 m x 4 n), CTA 128x128.
 * Split: D = AhBh + AhBl + AlBh (fp32 accumulate).
 * EPI 0: C[m*ldc+n] = v               (m<Mv, n<Nv)
 * EPI 1: v+=be[m*BGC+grp]; BN+relu; split -> O1/O2[n*K2P+m]  (m<CH)
 * EPI 2: group maxpool + p0[m] -> C[grp*ENCD+m]  (tokens)
 * EPI 3: n<DIN: C[m*DIN+n]=softplus(v+p0[n]); n<NXP: C2[m*32+n-DIN]=v (m<Mv)
 * ========================================================================= */
template<int EPI>
__global__ __launch_bounds__(256) void k_mma(
    const __nv_bfloat16* __restrict__ Ah, const __nv_bfloat16* __restrict__ Al, int lda,
    const __nv_bfloat16* __restrict__ Bh, const __nv_bfloat16* __restrict__ Bl, int ldb,
    int NKC,
    const float* __restrict__ p0, const float* __restrict__ p1,
    const float* __restrict__ p2, const float* __restrict__ p3,
    const float* __restrict__ p4,
    float* __restrict__ C, int ldc, float* __restrict__ C2,
    __nv_bfloat16* __restrict__ O1, __nv_bfloat16* __restrict__ O2,
    int Mv, int Nv)
{
    extern __shared__ __align__(1024) char smem[];
    const uint32_t sb = smem_u32(smem);
    const int tid = threadIdx.x, wid = tid >> 5, lid = tid & 31;
    const int wrow = wid >> 2, wcol = wid & 3;
    const int quad = lid >> 2, tq = lid & 3;
    const int m0 = blockIdx.y * 128, n0 = blockIdx.x * 128;

    /* ldmatrix lane address pattern: row+= (L&7)+8*((L>>3)&1), k += 8*(L>>4) */
    const int lrow = (lid & 7) + 8 * ((lid >> 3) & 1);
    const int lk   = 8 * (lid >> 4);

    float acc[4][4][4];
    #pragma unroll
    for (int i = 0; i < 4; i++)
        #pragma unroll
        for (int j = 0; j < 4; j++)
            #pragma unroll
            for (int k = 0; k < 4; k++) acc[i][j][k] = 0.f;

    /* chunk loader: 4 tiles (Ah,Al,Bh,Bl) of 128x64 bf16 = 16KB each */
    auto loadChunk = [&](int kc, int c) {
        const uint32_t bufb = sb + c * 65536;
        #pragma unroll
        for (int q = 0; q < 4; q++) {
            const __nv_bfloat16* base = (q == 0) ? Ah : (q == 1) ? Al : (q == 2) ? Bh : Bl;
            const int ld = (q < 2) ? lda : ldb;
            const int r0 = (q < 2) ? m0 : n0;
            const uint32_t tb = bufb + q * 16384;
            #pragma unroll
            for (int p = 0; p < 4; p++) {
                int idx = tid + p * 256;
                int row = idx >> 3, c16 = idx & 7;
                const void* g = base + (size_t)(r0 + row) * ld + kc * 64 + c16 * 8;
                uint32_t d = tb + SWZ128((uint32_t)(row * 128 + c16 * 16));
                CP_ASYNC16(d, g);
            }
        }
        CP_COMMIT();
    };

    loadChunk(0, 0);
    if (NKC > 1) loadChunk(1, 1); else CP_COMMIT();

    for (int kc = 0; kc < NKC; kc++) {
        const int c = kc & 1;
        if (kc + 1 < NKC) CP_WAIT1(); else CP_WAIT0();
        __syncthreads();
        const uint32_t ahb = sb + c * 65536;
        const uint32_t alb = ahb + 16384;
        const uint32_t bhb = ahb + 32768;
        const uint32_t blb = ahb + 49152;
        #pragma unroll
        for (int ks = 0; ks < 4; ks++) {
            const int k0 = ks * 16 + lk;
            uint32_t fah[4][4], fal[4][4], fbh[2][4], fbl[2][4];
            #pragma unroll
            for (int bi = 0; bi < 4; bi++) {
                int r = wrow * 64 + bi * 16 + lrow;
                ldm_x4(fah[bi], ahb + SWZ128((uint32_t)(r * 128 + k0 * 2)));
                ldm_x4(fal[bi], alb + SWZ128((uint32_t)(r * 128 + k0 * 2)));
            }
            #pragma unroll
            for (int bj2 = 0; bj2 < 2; bj2++) {
                int r = wcol * 32 + bj2 * 16 + lrow;
                ldm_x4(fbh[bj2], bhb + SWZ128((uint32_t)(r * 128 + k0 * 2)));
                ldm_x4(fbl[bj2], blb + SWZ128((uint32_t)(r * 128 + k0 * 2)));
            }
            #pragma unroll
            for (int bi = 0; bi < 4; bi++) {
                #pragma unroll
                for (int bj = 0; bj < 4; bj++) {
                    uint32_t bh0 = fbh[bj >> 1][bj & 1], bh1 = fbh[bj >> 1][2 + (bj & 1)];
                    uint32_t bl0 = fbl[bj >> 1][bj & 1], bl1 = fbl[bj >> 1][2 + (bj & 1)];
                    mma16816(acc[bi][bj], fah[bi], bh0, bh1);
                    mma16816(acc[bi][bj], fah[bi], bl0, bl1);
                    mma16816(acc[bi][bj], fal[bi], bh0, bh1);
                }
            }
        }
        __syncthreads();
        if (kc + 2 < NKC) loadChunk(kc + 2, c);
    }

    /* -------- epilogues -------- */
    const int grp = (n0 >> 5) + wcol;  /* point-group for this warp's 32 cols */
    #pragma unroll
    for (int bi = 0; bi < 4; bi++) {
        #pragma unroll
        for (int h0 = 0; h0 < 2; h0++) {
            const int m = m0 + wrow * 64 + bi * 16 + quad + 8 * h0;
            if (EPI == 2) {
                float vm = -INFINITY;
                #pragma unroll
                for (int bj = 0; bj < 4; bj++) {
                    vm = fmaxf(vm, acc[bi][bj][h0 * 2]);
                    vm = fmaxf(vm, acc[bi][bj][h0 * 2 + 1]);
                }
                vm = fmaxf(vm, __shfl_xor_sync(0xffffffffu, vm, 1));
                vm = fmaxf(vm, __shfl_xor_sync(0xffffffffu, vm, 2));
                if (tq == 0) C[(size_t)grp * ENCD + m] = vm + p0[m];
            } else if (EPI == 1) {
                if (m < CH) {
                    const float be = p0[(size_t)m * BGC + grp];
                    const float bnm = p1[m];
                    const float sc  = rsqrtf(p2[m] + EPSV) * p3[m];
                    const float bb  = p4[m];
                    #pragma unroll
                    for (int bj = 0; bj < 4; bj++) {
                        #pragma unroll
                        for (int e = 0; e < 2; e++) {
                            int n = n0 + wcol * 32 + bj * 8 + 2 * tq + e;
                            float v = acc[bi][bj][h0 * 2 + e] + be;
                            v = fmaxf((v - bnm) * sc + bb, 0.f);
                            split2(v, &O1[(size_t)n * K2P + m], &O2[(size_t)n * K2P + m]);
                        }
                    }
                }
            } else if (EPI == 0) {
                if (m < Mv) {
                    #pragma unroll
                    for (int bj = 0; bj < 4; bj++) {
                        #pragma unroll
                        for (int e = 0; e < 2; e++) {
                            int n = n0 + wcol * 32 + bj * 8 + 2 * tq + e;
                            if (n < Nv) C[(size_t)m * ldc + n] = acc[bi][bj][h0 * 2 + e];
                        }
                    }
                }
            } else { /* EPI 3 */
                if (m < Mv) {
                    #pragma unroll
                    for (int bj = 0; bj < 4; bj++) {
                        #pragma unroll
                        for (int e = 0; e < 2; e++) {
                            int n = n0 + wcol * 32 + bj * 8 + 2 * tq + e;
                            float v = acc[bi][bj][h0 * 2 + e];
                            if (n < DIN) C[(size_t)m * DIN + n] = softplusf(v + p0[n]);
                            else if (n < NXP) C2[(size_t)m * (2 * DSN) + (n - DIN)] = v;
                        }
                    }
                }
            }
        }
    }
}

/* --------------------------- split prepass kernels ------------------------- */
__global__ void k_split(const float* __restrict__ src, int sld, int soff,
                        int R, int K, __nv_bfloat16* __restrict__ dh,
                        __nv_bfloat16* __restrict__ dl, int Kp, long long total) {
    long long i = (long long)blockIdx.x * 256 + threadIdx.x;
    if (i >= total) return;
    int k = (int)(i % Kp);
    long long r = i / Kp;
    float v = (r < R && k < K) ? src[r * sld + soff + k] : 0.f;
    split2(v, &dh[i], &dl[i]);
}

/* combined dt/x_proj weights, split to bf16, padded rows zeroed */
__global__ void k_wcomb(const float* __restrict__ dpw, const float* __restrict__ xpw) {
    long long idx = (long long)blockIdx.x * 256 + threadIdx.x;
    if (idx >= (long long)DEPTH * NXPP * DIN) return;
    int col = (int)(idx % DIN);
    int rem = (int)(idx / DIN);
    int row = rem % NXPP;
    int l   = rem / NXPP;
    const float* xp = xpw + (size_t)l * (DTR + 2 * DSN) * DIN;
    float v = 0.f;
    if (row < DIN) {
        const float* dr = dpw + (size_t)l * DIN * DTR + (size_t)row * DTR;
        #pragma unroll
        for (int t = 0; t < DTR; t++) v = fmaf(dr[t], xp[(size_t)t * DIN + col], v);
    } else if (row < NXP) {
        v = xp[(size_t)(DTR + (row - DIN)) * DIN + col];
    }
    split2(v, &g_wch[idx], &g_wcl[idx]);
}

/* zero the K-pad columns of H1T (546..575) */
__global__ void k_h1pad() {
    int n = blockIdx.x * 8 + (threadIdx.x >> 5);
    int j = threadIdx.x & 31;
    if (j < (K2P - CH)) {
        g_h1h[(size_t)n * K2P + CH + j] = __float2bfloat16(0.f);
        g_h1l[(size_t)n * K2P + CH + j] = __float2bfloat16(0.f);
    }
}

/* ------------------- encoder: per-group feature max ------------------------ */
__global__ void k_fg(const float* __restrict__ nb) {
    __shared__ float s[NPTS * FEAT];
    int bg = blockIdx.x;
    const float* src = nb + (size_t)bg * NPTS * FEAT;
    for (int t = threadIdx.x; t < NPTS * FEAT; t += blockDim.x) s[t] = src[t];
    __syncthreads();
    for (int c = threadIdx.x; c < FEAT; c += blockDim.x) {
        float m = s[c];
        #pragma unroll
        for (int n = 1; n < NPTS; n++) m = fmaxf(m, s[n * FEAT + c]);
        g_fgT[(size_t)c * BGC + bg] = m;
    }
}

/* ------------------------- SIMT GEMM (bias GEMM only) ---------------------- */
__global__ __launch_bounds__(256) void k_gemm_bias(
    const float* __restrict__ A, int lda,
    const float* __restrict__ B, int ldb,
    float* __restrict__ C, int ldc,
    int M, int N, int K, const float* __restrict__ p0)
{
    const int TM = 64, RT = 4, LD = 68, LA = 2;
    __shared__ __align__(16) float As[2][8 * LD];
    __shared__ __align__(16) float Bs[2][8 * LD];
    int m0 = blockIdx.y * TM, n0 = blockIdx.x * TM;
    int tid = threadIdx.x, tx = tid & 15, ty = tid >> 4;
    float acc[RT][RT];
    #pragma unroll
    for (int i = 0; i < RT; i++)
        #pragma unroll
        for (int j = 0; j < RT; j++) acc[i][j] = 0.f;
    float ra[LA], rb[LA];
    const int nk = (K + 7) >> 3;
    auto loadT = [&](int kt) {
        int k0 = kt * 8;
        #pragma unroll
        for (int i = 0; i < LA; i++) {
            int t = tid + i * 256;
            int kk = t & 7, mm = t >> 3;
            int gm = m0 + mm, gk = k0 + kk;
            ra[i] = (gm < M && gk < K) ? A[(size_t)gm * lda + gk] : 0.f;
        }
        #pragma unroll
        for (int i = 0; i < LA; i++) {
            int t = tid + i * 256;
            int kk = t / TM, nn = t % TM;
            int gk = k0 + kk, gn = n0 + nn;
            rb[i] = (gk < K && gn < N) ? B[(size_t)gk * ldb + gn] : 0.f;
        }
    };
    auto storeT = [&](int buf) {
        #pragma unroll
        for (int i = 0; i < LA; i++) {
            int t = tid + i * 256;
            As[buf][(t & 7) * LD + (t >> 3)] = ra[i];
        }
        #pragma unroll
        for (int i = 0; i < LA; i++) {
            int t = tid + i * 256;
            Bs[buf][(t / TM) * LD + (t % TM)] = rb[i];
        }
    };
    loadT(0); storeT(0); __syncthreads();
    for (int kt = 0; kt < nk; kt++) {
        int cur = kt & 1;
        if (kt + 1 < nk) loadT(kt + 1);
        #pragma unroll
        for (int kk = 0; kk < 8; kk++) {
            float4 a4 = *reinterpret_cast<const float4*>(&As[cur][kk * LD + ty * RT]);
            float4 b4 = *reinterpret_cast<const float4*>(&Bs[cur][kk * LD + tx * RT]);
            float a[4] = {a4.x, a4.y, a4.z, a4.w};
            float b[4] = {b4.x, b4.y, b4.z, b4.w};
            #pragma unroll
            for (int i = 0; i < RT; i++)
                #pragma unroll
                for (int j = 0; j < RT; j++) acc[i][j] = fmaf(a[i], b[j], acc[i][j]);
        }
        if (kt + 1 < nk) storeT(cur ^ 1);
        __syncthreads();
    }
    #pragma unroll
    for (int i = 0; i < RT; i++) {
        int gm = m0 + ty * RT + i;
        if (gm >= M) continue;
        #pragma unroll
        for (int j = 0; j < RT; j++) {
            int gn = n0 + tx * RT + j;
            if (gn >= N) continue;
            C[(size_t)gm * ldc + gn] = acc[i][j] + p0[gm];
        }
    }
}

/* ---------------- visible-index extraction (bool width-robust) ------------ */
__global__ void k_visidx(const unsigned char* __restrict__ m8) {
    if (threadIdx.x != 0) return;
    int b = blockIdx.x;
    int c8 = 0;
    for (int g = 0; g < GG; g++) c8 += (m8[(size_t)b * GG + g] != 0);
    int cnt = 0;
    if (c8 == NMASK) {
        for (int g = 0; g < GG; g++)
            if (!m8[(size_t)b * GG + g]) { if (cnt < GVIS) g_vis[b * GVIS + cnt] = g; cnt++; }
    } else {
        const int* m32 = (const int*)m8;
        for (int g = 0; g < GG; g++)
            if (!m32[(size_t)b * GG + g]) { if (cnt < GVIS) g_vis[b * GVIS + cnt] = g; cnt++; }
    }
}

/* ------------- gather tokens/centers + pos MLP -> initial h ---------------- */
__global__ void k_pos(const float* __restrict__ center,
                      const float* __restrict__ w1, const float* __restrict__ b1,
                      const float* __restrict__ w2, const float* __restrict__ b2) {
    __shared__ float hcache[128];
    __shared__ float cc[3];
    int r = blockIdx.x;
    int b = r / GVIS;
    int g = g_vis[r];
    int tid = threadIdx.x;
    if (tid < 3) cc[tid] = center[((size_t)b * GG + g) * 3 + tid];
    __syncthreads();
    float a = w1[tid * 3] * cc[0] + w1[tid * 3 + 1] * cc[1] + w1[tid * 3 + 2] * cc[2] + b1[tid];
    hcache[tid] = geluf(a);
    __syncthreads();
    const float* tok = g_tokens + ((size_t)b * GG + g) * ENCD;
    for (int e = tid; e < DDIM; e += 128) {
        float acc = b2[e];
        const float* wr = w2 + (size_t)e * 128;
        #pragma unroll 8
        for (int k = 0; k < 128; k++) acc = fmaf(wr[k], hcache[k], acc);
        g_h[(size_t)r * DDIM + e] = acc + tok[e];
    }
}

/* ------------- residual accumulate + LayerNorm -> split bf16 --------------- */
__global__ void k_lnres(int layer, const float* __restrict__ w, const float* __restrict__ b) {
    int r = blockIdx.x, tid = threadIdx.x;
    float* res = g_res + (size_t)r * DDIM;
    const float* h = g_h + (size_t)r * DDIM;
    float v[3], s1 = 0.f, s2 = 0.f;
    #pragma unroll
    for (int i = 0; i < 3; i++) {
        int c = tid + i * 128;
        float x = h[c];
        if (layer > 0) x += res[c];
        v[i] = x; res[c] = x;
        s1 += x; s2 += x * x;
    }
    reduce2_128(s1, s2);
    float mu = s1 * (1.f / DDIM);
    float rstd = rsqrtf(s2 * (1.f / DDIM) - mu * mu + EPSV);
    #pragma unroll
    for (int i = 0; i < 3; i++) {
        int c = tid + i * 128;
        float y = (v[i] - mu) * rstd * w[c] + b[c];
        split2(y, &g_hnh[(size_t)r * DDIM + c], &g_hnl[(size_t)r * DDIM + c]);
    }
}

/* ---------------- depthwise causal conv (k=4) + SiLU -> split -------------- */
__global__ void k_conv(const float* __restrict__ cw, const float* __restrict__ cb) {
    int idx = blockIdx.x * blockDim.x + threadIdx.x;
    if (idx >= BL * DIN) return;
    int d = idx % DIN, r = idx / DIN;
    int b = r / SEQL, l = r % SEQL;
    float acc = cb[d];
    #pragma unroll
    for (int k = 0; k < DCONV; k++) {
        int ll = l - (DCONV - 1) + k;
        if (ll >= 0) acc = fmaf(cw[d * DCONV + k], g_xz[((size_t)(b * SEQL + ll)) * (2 * DIN) + d], acc);
    }
    float y = siluf(acc);
    g_xi[idx] = y;
    split2(y, &g_xih[idx], &g_xil[idx]);
}

/* --------------------------- selective scan -> split ------------------------ */
__global__ void k_scan(const float* __restrict__ alog, const float* __restrict__ Dp) {
    int b = blockIdx.x / 6;
    int d = (blockIdx.x % 6) * 128 + threadIdx.x;
    float A[DSN];
    #pragma unroll
    for (int s = 0; s < DSN; s++) A[s] = -expf(alog[(size_t)d * DSN + s]);
    float Dd = Dp[d];
    float h[DSN];
    #pragma unroll
    for (int s = 0; s < DSN; s++) h[s] = 0.f;
    for (int l = 0; l < SEQL; l++) {
        int r = b * SEQL + l;
        float dt = g_dt[(size_t)r * DIN + d];
        float x  = g_xi[(size_t)r * DIN + d];
        float dtx = dt * x;
        const float* bl = g_bc + (size_t)r * (2 * DSN);
        float y = 0.f;
        #pragma unroll
        for (int s = 0; s < DSN; s++) {
            float dA = __expf(dt * A[s]);
            h[s] = fmaf(dA, h[s], dtx * bl[s]);
            y = fmaf(h[s], bl[DSN + s], y);
        }
        float z = g_xz[(size_t)r * (2 * DIN) + DIN + d];
        float u = (y + x * Dd) * siluf(z);
        split2(u, &g_uh[(size_t)r * DIN + d], &g_ul[(size_t)r * DIN + d]);
    }
}

/* ----------------------- final residual + double LN ------------------------ */
__global__ void k_final(float* __restrict__ out,
                        const float* __restrict__ w1, const float* __restrict__ b1,
                        const float* __restrict__ w2, const float* __restrict__ b2) {
    int r = blockIdx.x, tid = threadIdx.x;
    float v[3], s1 = 0.f, s2 = 0.f;
    #pragma unroll
    for (int i = 0; i < 3; i++) {
        int c = tid + i * 128;
        float x = g_res[(size_t)r * DDIM + c] + g_h[(size_t)r * DDIM + c];
        v[i] = x; s1 += x; s2 += x * x;
    }
    reduce2_128(s1, s2);
    float mu = s1 * (1.f / DDIM);
    float rstd = rsqrtf(s2 * (1.f / DDIM) - mu * mu + EPSV);
    s1 = 0.f; s2 = 0.f;
    #pragma unroll
    for (int i = 0; i < 3; i++) {
        int c = tid + i * 128;
        v[i] = (v[i] - mu) * rstd * w1[c] + b1[c];
        s1 += v[i]; s2 += v[i] * v[i];
    }
    reduce2_128(s1, s2);
    mu = s1 * (1.f / DDIM);
    rstd = rsqrtf(s2 * (1.f / DDIM) - mu * mu + EPSV);
    #pragma unroll
    for (int i = 0; i < 3; i++) {
        int c = tid + i * 128;
        out[(size_t)r * DDIM + c] = (v[i] - mu) * rstd * w2[c] + b2[c];
    }
}

/* -------------------------- mask -> output tail ---------------------------- */
__global__ void k_maskout(const unsigned char* __restrict__ m8, float* __restrict__ out, int out_size) {
    if (out_size < OUTH + BB * GG) return;
    __shared__ int use8;
    if (threadIdx.x == 0) {
        int c = 0;
        for (int g = 0; g < GG; g++) c += (m8[g] != 0);
        use8 = (c == NMASK);
    }
    __syncthreads();
    const int* m32 = (const int*)m8;
    for (int i = threadIdx.x; i < BB * GG; i += blockDim.x) {
        float v = use8 ? (m8[i] ? 1.f : 0.f) : (m32[i] ? 1.f : 0.f);
        out[OUTH + i] = v;
    }
}

/* ------------------------------- host driver ------------------------------- */
#define SMEM_MMA (2 * 65536)

extern "C" void kernel_launch(void* const* d_in, const int* in_sizes, int n_in,
                              void* d_out, int out_size) {
    (void)in_sizes; (void)n_in;
    const float* nb     = (const float*)d_in[0];
    const float* center = (const float*)d_in[1];
    const unsigned char* mask = (const unsigned char*)d_in[2];
    const float* c1w = (const float*)d_in[3];
    const float* c1b = (const float*)d_in[4];
    const float* bng = (const float*)d_in[5];
    const float* bnb = (const float*)d_in[6];
    const float* bnm = (const float*)d_in[7];
    const float* bnv = (const float*)d_in[8];
    const float* c2w = (const float*)d_in[9];
    const float* c2b = (const float*)d_in[10];
    const float* pw1 = (const float*)d_in[11];
    const float* pb1 = (const float*)d_in[12];
    const float* pw2 = (const float*)d_in[13];
    const float* pb2 = (const float*)d_in[14];
    const float* ipw = (const float*)d_in[15];
    const float* cw  = (const float*)d_in[16];
    const float* cb  = (const float*)d_in[17];
    const float* xpw = (const float*)d_in[18];
    const float* dpw = (const float*)d_in[19];
    const float* dpb = (const float*)d_in[20];
    const float* alog= (const float*)d_in[21];
    const float* Dp  = (const float*)d_in[22];
    const float* opw = (const float*)d_in[23];
    const float* lnw = (const float*)d_in[24];
    const float* lnb = (const float*)d_in[25];
    const float* nfw = (const float*)d_in[26];
    const float* nfb = (const float*)d_in[27];
    const float* n2w = (const float*)d_in[28];
    const float* n2b = (const float*)d_in[29];
    float* out = (float*)d_out;

    cudaFuncSetAttribute(k_mma<0>, cudaFuncAttributeMaxDynamicSharedMemorySize, SMEM_MMA);
    cudaFuncSetAttribute(k_mma<1>, cudaFuncAttributeMaxDynamicSharedMemorySize, SMEM_MMA);
    cudaFuncSetAttribute(k_mma<2>, cudaFuncAttributeMaxDynamicSharedMemorySize, SMEM_MMA);
    cudaFuncSetAttribute(k_mma<3>, cudaFuncAttributeMaxDynamicSharedMemorySize, SMEM_MMA);

    float *fgT, *be, *tok, *xz, *xi, *dtb, *bc, *hb;
    cudaGetSymbolAddress((void**)&fgT, g_fgT);
    cudaGetSymbolAddress((void**)&be,  g_biaseff);
    cudaGetSymbolAddress((void**)&tok, g_tokens);
    cudaGetSymbolAddress((void**)&xz,  g_xz);
    cudaGetSymbolAddress((void**)&xi,  g_xi);
    cudaGetSymbolAddress((void**)&dtb, g_dt);
    cudaGetSymbolAddress((void**)&bc,  g_bc);
    cudaGetSymbolAddress((void**)&hb,  g_h);
    __nv_bfloat16 *nbh, *nbl, *w1h, *w1l, *w2h, *w2l, *h1h, *h1l;
    __nv_bfloat16 *ipwh, *ipwl, *wch, *wcl, *opwh, *opwl;
    __nv_bfloat16 *hnh, *hnl, *xih, *xil, *uh, *ul;
    cudaGetSymbolAddress((void**)&nbh, g_nbh);  cudaGetSymbolAddress((void**)&nbl, g_nbl);
    cudaGetSymbolAddress((void**)&w1h, g_w1h);  cudaGetSymbolAddress((void**)&w1l, g_w1l);
    cudaGetSymbolAddress((void**)&w2h, g_w2h);  cudaGetSymbolAddress((void**)&w2l, g_w2l);
    cudaGetSymbolAddress((void**)&h1h, g_h1h);  cudaGetSymbolAddress((void**)&h1l, g_h1l);
    cudaGetSymbolAddress((void**)&ipwh, g_ipwh); cudaGetSymbolAddress((void**)&ipwl, g_ipwl);
    cudaGetSymbolAddress((void**)&wch, g_wch);  cudaGetSymbolAddress((void**)&wcl, g_wcl);
    cudaGetSymbolAddress((void**)&opwh, g_opwh); cudaGetSymbolAddress((void**)&opwl, g_opwl);
    cudaGetSymbolAddress((void**)&hnh, g_hnh);  cudaGetSymbolAddress((void**)&hnl, g_hnl);
    cudaGetSymbolAddress((void**)&xih, g_xih);  cudaGetSymbolAddress((void**)&xil, g_xil);
    cudaGetSymbolAddress((void**)&uh,  g_uh);   cudaGetSymbolAddress((void**)&ul,  g_ul);

    /* -------- weight & input split prepasses -------- */
    auto splitN = [](long long total) { return (int)((total + 255) / 256); };
    long long tNB = (long long)NCOL * K1P;
    k_split<<<splitN(tNB), 256>>>(nb, FEAT, 0, NCOL, FEAT, nbh, nbl, K1P, tNB);
    long long tW1 = (long long)M1P * K1P;
    k_split<<<splitN(tW1), 256>>>(c1w, CH, FEAT, CH, FEAT, w1h, w1l, K1P, tW1);
    long long tW2 = (long long)ENCD * K2P;
    k_split<<<splitN(tW2), 256>>>(c2w, CH, 0, ENCD, CH, w2h, w2l, K2P, tW2);
    long long tIP = (long long)DEPTH * 2 * DIN * DDIM;
    k_split<<<splitN(tIP), 256>>>(ipw, DDIM, 0, DEPTH * 2 * DIN, DDIM, ipwh, ipwl, DDIM, tIP);
    long long tOP = (long long)DEPTH * DDIM * DIN;
    k_split<<<splitN(tOP), 256>>>(opw, DIN, 0, DEPTH * DDIM, DIN, opwh, opwl, DIN, tOP);
    k_wcomb<<<splitN((long long)DEPTH * NXPP * DIN), 256>>>(dpw, xpw);
    k_h1pad<<<NCOL / 8, 256>>>();

    /* -------- encoder -------- */
    k_fg<<<BGC, 256>>>(nb);
    k_gemm_bias<<<dim3((BGC + 63) / 64, (CH + 63) / 64), 256>>>(
        c1w, CH, fgT, BGC, be, BGC, CH, BGC, FEAT, c1b);
    /* GEMM1: D[640,65536] -> H1T split */
    k_mma<1><<<dim3(NCOL / 128, M1P / 128), 256, SMEM_MMA>>>(
        w1h, w1l, K1P, nbh, nbl, K1P, K1P / 64,
        be, bnm, bnv, bng, bnb, nullptr, 0, nullptr, h1h, h1l, CH, NCOL);
    /* GEMM2: D[384,65536] -> tokens (fused maxpool) */
    k_mma<2><<<dim3(NCOL / 128, ENCD / 128), 256, SMEM_MMA>>>(
        w2h, w2l, K2P, h1h, h1l, K2P, K2P / 64,
        c2b, nullptr, nullptr, nullptr, nullptr, tok, 0, nullptr, nullptr, nullptr, ENCD, NCOL);

    /* -------- gather + pos embed -------- */
    k_visidx<<<BB, 32>>>(mask);
    k_pos<<<BL, 128>>>(center, pw1, pb1, pw2, pb2);

    /* -------- mamba stack -------- */
    for (int i = 0; i < DEPTH; i++) {
        k_lnres<<<BL, 128>>>(i, lnw + (size_t)i * DDIM, lnb + (size_t)i * DDIM);
        /* in_proj: xz[824,1536] = hn @ ipw^T */
        k_mma<0><<<dim3(2 * DIN / 128, BLP / 128), 256, SMEM_MMA>>>(
            hnh, hnl, DDIM, ipwh + (size_t)i * 2 * DIN * DDIM, ipwl + (size_t)i * 2 * DIN * DDIM, DDIM,
            DDIM / 64, nullptr, nullptr, nullptr, nullptr, nullptr,
            xz, 2 * DIN, nullptr, nullptr, nullptr, BL, 2 * DIN);
        k_conv<<<(BL * DIN + 255) / 256, 256>>>(cw + (size_t)i * DIN * DCONV, cb + (size_t)i * DIN);
        /* merged x_proj+dt_proj: dt[824,768], bc[824,32] */
        k_mma<3><<<dim3(NXPP / 128, BLP / 128), 256, SMEM_MMA>>>(
            xih, xil, DIN, wch + (size_t)i * NXPP * DIN, wcl + (size_t)i * NXPP * DIN, DIN,
            DIN / 64, dpb + (size_t)i * DIN, nullptr, nullptr, nullptr, nullptr,
            dtb, DIN, bc, nullptr, nullptr, BL, NXP);
        k_scan<<<BB * 6, 128>>>(alog + (size_t)i * DIN * DSN, Dp + (size_t)i * DIN);
        /* out_proj: h[824,384] = u @ opw^T */
        k_mma<0><<<dim3(DDIM / 128, BLP / 128), 256, SMEM_MMA>>>(
            uh, ul, DIN, opwh + (size_t)i * DDIM * DIN, opwl + (size_t)i * DDIM * DIN, DIN,
            DIN / 64, nullptr, nullptr, nullptr, nullptr, nullptr,
            hb, DDIM, nullptr, nullptr, nullptr, BL, DDIM);
    }

    /* -------- final norms + outputs -------- */
    k_final<<<BL, 128>>>(out, nfw, nfb, n2w, n2b);
    k_maskout<<<1, 256>>>(mask, out, out_size);
}

// round 5
// speedup vs baseline: 2.4306x; 1.0197x over previous
#include <cuda_runtime.h>
#include <cuda_bf16.h>
#include <math.h>
#include <stdint.h>

#define BB 8
#define GG 256
#define NPTS 32
#define FEAT 273
#define CH 546
#define ENCD 384
#define DDIM 384
#define DEPTH 12
#define DIN 768
#define DSN 16
#define DCONV 4
#define DTR 24
#define GVIS 103
#define SEQL 103
#define BL (BB*GVIS)        /* 824 rows */
#define BLP 896             /* padded to 7*128 */
#define BGC (BB*GG)         /* 2048 groups */
#define NCOL (BGC*NPTS)     /* 65536 point columns */
#define NMASK 153
#define OUTH (BL*DDIM)      /* 316416 */
#define NXP (DIN + 2*DSN)   /* 800 */
#define NXPP 896            /* padded */
#define K1P 320             /* FEAT 273 -> padded */
#define M1P 640             /* CH 546 -> padded  */
#define K2P 576             /* CH 546 -> padded  */
#define EPSV 1e-5f

/* ------------------------- scratch (device globals) ------------------------ */
__device__ float g_biaseff[(size_t)CH * BGC];
__device__ float g_tokens[(size_t)BGC * ENCD];
__device__ int   g_vis[BL];
__device__ float g_h[BL * DDIM];
__device__ float g_res[BL * DDIM];
__device__ float g_xz[BL * 2 * DIN];
__device__ float g_xi[BL * DIN];
__device__ float g_dt[BL * DIN];
__device__ float g_bc[BL * 2 * DSN];

/* bf16-split operand buffers */
__device__ __align__(256) __nv_bfloat16 g_fgh[(size_t)BGC * K1P];
__device__ __align__(256) __nv_bfloat16 g_fgl[(size_t)BGC * K1P];
__device__ __align__(256) __nv_bfloat16 g_w0h[(size_t)M1P * K1P];
__device__ __align__(256) __nv_bfloat16 g_w0l[(size_t)M1P * K1P];
__device__ __align__(256) __nv_bfloat16 g_nbh[(size_t)NCOL * K1P];
__device__ __align__(256) __nv_bfloat16 g_nbl[(size_t)NCOL * K1P];
__device__ __align__(256) __nv_bfloat16 g_w1h[(size_t)M1P * K1P];
__device__ __align__(256) __nv_bfloat16 g_w1l[(size_t)M1P * K1P];
__device__ __align__(256) __nv_bfloat16 g_w2h[(size_t)ENCD * K2P];
__device__ __align__(256) __nv_bfloat16 g_w2l[(size_t)ENCD * K2P];
__device__ __align__(256) __nv_bfloat16 g_h1h[(size_t)NCOL * K2P];
__device__ __align__(256) __nv_bfloat16 g_h1l[(size_t)NCOL * K2P];
__device__ __align__(256) __nv_bfloat16 g_ipwh[(size_t)DEPTH * 2 * DIN * DDIM];
__device__ __align__(256) __nv_bfloat16 g_ipwl[(size_t)DEPTH * 2 * DIN * DDIM];
__device__ __align__(256) __nv_bfloat16 g_wch[(size_t)DEPTH * NXPP * DIN];
__device__ __align__(256) __nv_bfloat16 g_wcl[(size_t)DEPTH * NXPP * DIN];
__device__ __align__(256) __nv_bfloat16 g_opwh[(size_t)DEPTH * DDIM * DIN];
__device__ __align__(256) __nv_bfloat16 g_opwl[(size_t)DEPTH * DDIM * DIN];
__device__ __align__(256) __nv_bfloat16 g_hnh[(size_t)BLP * DDIM];
__device__ __align__(256) __nv_bfloat16 g_hnl[(size_t)BLP * DDIM];
__device__ __align__(256) __nv_bfloat16 g_xih[(size_t)BLP * DIN];
__device__ __align__(256) __nv_bfloat16 g_xil[(size_t)BLP * DIN];
__device__ __align__(256) __nv_bfloat16 g_uh[(size_t)BLP * DIN];
__device__ __align__(256) __nv_bfloat16 g_ul[(size_t)BLP * DIN];

/* ------------------------------ small helpers ----------------------------- */
__device__ __forceinline__ float siluf(float x) { return x / (1.f + expf(-x)); }
__device__ __forceinline__ float geluf(float x) { return 0.5f * x * (1.f + erff(x * 0.70710678118654752f)); }
__device__ __forceinline__ float softplusf(float x) { return (x > 20.f) ? x : log1pf(expf(x)); }
__device__ __forceinline__ void split2(float v, __nv_bfloat16* h, __nv_bfloat16* l) {
    __nv_bfloat16 hh = __float2bfloat16(v);
    *h = hh;
    *l = __float2bfloat16(v - __bfloat162float(hh));
}

__device__ __forceinline__ void reduce2_128(float& s1, float& s2) {
    #pragma unroll
    for (int o = 16; o; o >>= 1) {
        s1 += __shfl_xor_sync(0xffffffffu, s1, o);
        s2 += __shfl_xor_sync(0xffffffffu, s2, o);
    }
    __shared__ float ra[4], rb[4];
    int w = threadIdx.x >> 5, l = threadIdx.x & 31;
    if (l == 0) { ra[w] = s1; rb[w] = s2; }
    __syncthreads();
    s1 = ra[0] + ra[1] + ra[2] + ra[3];
    s2 = rb[0] + rb[1] + rb[2] + rb[3];
    __syncthreads();
}

/* --------------------------- PTX wrappers --------------------------------- */
__device__ __forceinline__ uint32_t smem_u32(const void* p) {
    uint32_t a;
    asm("{ .reg .u64 t; cvta.to.shared.u64 t, %1; cvt.u32.u64 %0, t; }" : "=r"(a) : "l"(p));
    return a;
}
#define SWZ128(o) ((o) ^ (((o) >> 3) & 0x70))
#define CP_ASYNC16(d, s) asm volatile("cp.async.cg.shared.global [%0], [%1], 16;" :: "r"(d), "l"(s))
#define CP_COMMIT()      asm volatile("cp.async.commit_group;" ::: "memory")
#define CP_WAIT1()       asm volatile("cp.async.wait_group 1;" ::: "memory")
#define CP_WAIT0()       asm volatile("cp.async.wait_group 0;" ::: "memory")

__device__ __forceinline__ void ldm_x4(uint32_t* r, uint32_t addr) {
    asm volatile("ldmatrix.sync.aligned.m8n8.x4.shared.b16 {%0,%1,%2,%3}, [%4];"
        : "=r"(r[0]), "=r"(r[1]), "=r"(r[2]), "=r"(r[3]) : "r"(addr));
}
__device__ __forceinline__ void mma16816(float* c, const uint32_t* a, uint32_t b0, uint32_t b1) {
    asm volatile("mma.sync.aligned.m16n8k16.row.col.f32.bf16.bf16.f32 "
        "{%0,%1,%2,%3}, {%4,%5,%6,%7}, {%8,%9}, {%0,%1,%2,%3};"
        : "+f"(c[0]), "+f"(c[1]), "+f"(c[2]), "+f"(c[3])
        : "r"(a[0]), "r"(a[1]), "r"(a[2]), "r"(a[3]), "r"(b0), "r"(b1));
}

/* =================== generic bf16-split mma.sync GEMM ======================
 * D[M,N] = A[M,K] * B[N,K]^T  (h/l split bf16, K-major, ld = Kpad)
 * grid = (Mtiles, Ntiles) -- M fastest so consecutive CTAs share the B tile.
 * 256 threads = 8 warps (2 m x 4 n), CTA 128x128.
 * Split: D = AhBh + AhBl + AlBh (fp32 accumulate).
 * EPI 0: C[m*ldc+n] = v               (m<Mv, n<Nv)
 * EPI 1: v+=be[m*BGC+grp]; BN+relu; split -> O1/O2[n*K2P+m] (staged, m<CH)
 * EPI 2: group maxpool + p0[m] -> C[grp*ENCD+m]  (tokens)
 * EPI 3: n<DIN: C[m*DIN+n]=softplus(v+p0[n]); n<NXP: C2[m*32+n-DIN]=v (m<Mv)
 * ========================================================================= */
template<int EPI>
__global__ __launch_bounds__(256) void k_mma(
    const __nv_bfloat16* __restrict__ Ah, const __nv_bfloat16* __restrict__ Al, int lda,
    const __nv_bfloat16* __restrict__ Bh, const __nv_bfloat16* __restrict__ Bl, int ldb,
    int NKC,
    const float* __restrict__ p0, const float* __restrict__ p1,
    const float* __restrict__ p2, const float* __restrict__ p3,
    const float* __restrict__ p4,
    float* __restrict__ C, int ldc, float* __restrict__ C2,
    __nv_bfloat16* __restrict__ O1, __nv_bfloat16* __restrict__ O2,
    int Mv, int Nv)
{
    extern __shared__ __align__(1024) char smem[];
    const uint32_t sb = smem_u32(smem);
    const int tid = threadIdx.x, wid = tid >> 5, lid = tid & 31;
    const int wrow = wid >> 2, wcol = wid & 3;
    const int quad = lid >> 2, tq = lid & 3;
    const int m0 = blockIdx.x * 128, n0 = blockIdx.y * 128;

    const int lrow = (lid & 7) + 8 * ((lid >> 3) & 1);
    const int lk   = 8 * (lid >> 4);

    float acc[4][4][4];
    #pragma unroll
    for (int i = 0; i < 4; i++)
        #pragma unroll
        for (int j = 0; j < 4; j++)
            #pragma unroll
            for (int k = 0; k < 4; k++) acc[i][j][k] = 0.f;

    /* chunk loader: 4 tiles (Ah,Al,Bh,Bl) of 128x64 bf16 = 16KB each */
    auto loadChunk = [&](int kc, int c) {
        const uint32_t bufb = sb + c * 65536;
        #pragma unroll
        for (int q = 0; q < 4; q++) {
            const __nv_bfloat16* base = (q == 0) ? Ah : (q == 1) ? Al : (q == 2) ? Bh : Bl;
            const int ld = (q < 2) ? lda : ldb;
            const int r0 = (q < 2) ? m0 : n0;
            const uint32_t tb = bufb + q * 16384;
            #pragma unroll
            for (int p = 0; p < 4; p++) {
                int idx = tid + p * 256;
                int row = idx >> 3, c16 = idx & 7;
                const void* g = base + (size_t)(r0 + row) * ld + kc * 64 + c16 * 8;
                uint32_t d = tb + SWZ128((uint32_t)(row * 128 + c16 * 16));
                CP_ASYNC16(d, g);
            }
        }
        CP_COMMIT();
    };

    loadChunk(0, 0);
    if (NKC > 1) loadChunk(1, 1); else CP_COMMIT();

    for (int kc = 0; kc < NKC; kc++) {
        const int c = kc & 1;
        if (kc + 1 < NKC) CP_WAIT1(); else CP_WAIT0();
        __syncthreads();
        const uint32_t ahb = sb + c * 65536;
        const uint32_t alb = ahb + 16384;
        const uint32_t bhb = ahb + 32768;
        const uint32_t blb = ahb + 49152;
        #pragma unroll
        for (int ks = 0; ks < 4; ks++) {
            const int k0 = ks * 16 + lk;
            uint32_t fah[4][4], fal[4][4], fbh[2][4], fbl[2][4];
            #pragma unroll
            for (int bi = 0; bi < 4; bi++) {
                int r = wrow * 64 + bi * 16 + lrow;
                ldm_x4(fah[bi], ahb + SWZ128((uint32_t)(r * 128 + k0 * 2)));
                ldm_x4(fal[bi], alb + SWZ128((uint32_t)(r * 128 + k0 * 2)));
            }
            #pragma unroll
            for (int bj2 = 0; bj2 < 2; bj2++) {
                int r = wcol * 32 + bj2 * 16 + lrow;
                ldm_x4(fbh[bj2], bhb + SWZ128((uint32_t)(r * 128 + k0 * 2)));
                ldm_x4(fbl[bj2], blb + SWZ128((uint32_t)(r * 128 + k0 * 2)));
            }
            #pragma unroll
            for (int bi = 0; bi < 4; bi++) {
                #pragma unroll
                for (int bj = 0; bj < 4; bj++) {
                    uint32_t bh0 = fbh[bj >> 1][bj & 1], bh1 = fbh[bj >> 1][2 + (bj & 1)];
                    uint32_t bl0 = fbl[bj >> 1][bj & 1], bl1 = fbl[bj >> 1][2 + (bj & 1)];
                    mma16816(acc[bi][bj], fah[bi], bh0, bh1);
                    mma16816(acc[bi][bj], fah[bi], bl0, bl1);
                    mma16816(acc[bi][bj], fal[bi], bh0, bh1);
                }
            }
        }
        __syncthreads();
        if (kc + 2 < NKC) loadChunk(kc + 2, c);
    }

    const int grp = (n0 >> 5) + wcol;  /* point-group for this warp's 32 cols */

    if (EPI == 1) {
        /* staged transposed split store: smem 128(n) x 136(m-padded) for h & l */
        const int LDE = 136;
        __nv_bfloat16* sh = (__nv_bfloat16*)smem;
        __nv_bfloat16* sl = (__nv_bfloat16*)(smem + 128 * LDE * 2);
        const int mlim = (CH - m0 < 128) ? (CH - m0) : 128;
        #pragma unroll
        for (int bi = 0; bi < 4; bi++) {
            #pragma unroll
            for (int h0 = 0; h0 < 2; h0++) {
                const int ml = wrow * 64 + bi * 16 + quad + 8 * h0;
                const int m = m0 + ml;
                if (m < CH) {
                    const float be = p0[(size_t)m * BGC + grp];
                    const float bnm = p1[m];
                    const float sc  = rsqrtf(p2[m] + EPSV) * p3[m];
                    const float bb  = p4[m];
                    #pragma unroll
                    for (int bj = 0; bj < 4; bj++) {
                        #pragma unroll
                        for (int e = 0; e < 2; e++) {
                            int nl = wcol * 32 + bj * 8 + 2 * tq + e;
                            float v = acc[bi][bj][h0 * 2 + e] + be;
                            v = fmaxf((v - bnm) * sc + bb, 0.f);
                            split2(v, &sh[nl * LDE + ml], &sl[nl * LDE + ml]);
                        }
                    }
                }
            }
        }
        __syncthreads();
        for (int idx = tid; idx < 128 * 16; idx += 256) {
            int nl = idx >> 4, ch = idx & 15;
            int mbeg = ch * 8;
            if (mbeg < mlim) {
                size_t gbase = (size_t)(n0 + nl) * K2P + m0 + mbeg;
                if (mbeg + 8 <= mlim) {
                    *(uint4*)(&O1[gbase]) = *(const uint4*)(&sh[nl * LDE + mbeg]);
                    *(uint4*)(&O2[gbase]) = *(const uint4*)(&sl[nl * LDE + mbeg]);
                } else {
                    for (int t = 0; t < mlim - mbeg; t++) {
                        O1[gbase + t] = sh[nl * LDE + mbeg + t];
                        O2[gbase + t] = sl[nl * LDE + mbeg + t];
                    }
                }
            }
        }
        return;
    }

    #pragma unroll
    for (int bi = 0; bi < 4; bi++) {
        #pragma unroll
        for (int h0 = 0; h0 < 2; h0++) {
            const int m = m0 + wrow * 64 + bi * 16 + quad + 8 * h0;
            if (EPI == 2) {
                float vm = -INFINITY;
                #pragma unroll
                for (int bj = 0; bj < 4; bj++) {
                    vm = fmaxf(vm, acc[bi][bj][h0 * 2]);
                    vm = fmaxf(vm, acc[bi][bj][h0 * 2 + 1]);
                }
                vm = fmaxf(vm, __shfl_xor_sync(0xffffffffu, vm, 1));
                vm = fmaxf(vm, __shfl_xor_sync(0xffffffffu, vm, 2));
                if (tq == 0) C[(size_t)grp * ENCD + m] = vm + p0[m];
            } else if (EPI == 0) {
                if (m < Mv) {
                    #pragma unroll
                    for (int bj = 0; bj < 4; bj++) {
                        #pragma unroll
                        for (int e = 0; e < 2; e++) {
                            int n = n0 + wcol * 32 + bj * 8 + 2 * tq + e;
                            if (n < Nv) C[(size_t)m * ldc + n] = acc[bi][bj][h0 * 2 + e];
                        }
                    }
                }
            } else { /* EPI 3 */
                if (m < Mv) {
                    #pragma unroll
                    for (int bj = 0; bj < 4; bj++) {
                        #pragma unroll
                        for (int e = 0; e < 2; e++) {
                            int n = n0 + wcol * 32 + bj * 8 + 2 * tq + e;
                            float v = acc[bi][bj][h0 * 2 + e];
                            if (n < DIN) C[(size_t)m * DIN + n] = softplusf(v + p0[n]);
                            else if (n < NXP) C2[(size_t)m * (2 * DSN) + (n - DIN)] = v;
                        }
                    }
                }
            }
        }
    }
}

/* --------------------------- split prepass kernels ------------------------- */
__global__ void k_split(const float* __restrict__ src, int sld, int soff,
                        int R, int K, __nv_bfloat16* __restrict__ dh,
                        __nv_bfloat16* __restrict__ dl, int Kp, long long total) {
    long long i = (long long)blockIdx.x * 256 + threadIdx.x;
    if (i >= total) return;
    int k = (int)(i % Kp);
    long long r = i / Kp;
    float v = (r < R && k < K) ? src[r * sld + soff + k] : 0.f;
    split2(v, &dh[i], &dl[i]);
}

/* combined dt/x_proj weights, split to bf16, padded rows zeroed */
__global__ void k_wcomb(const float* __restrict__ dpw, const float* __restrict__ xpw) {
    long long idx = (long long)blockIdx.x * 256 + threadIdx.x;
    if (idx >= (long long)DEPTH * NXPP * DIN) return;
    int col = (int)(idx % DIN);
    int rem = (int)(idx / DIN);
    int row = rem % NXPP;
    int l   = rem / NXPP;
    const float* xp = xpw + (size_t)l * (DTR + 2 * DSN) * DIN;
    float v = 0.f;
    if (row < DIN) {
        const float* dr = dpw + (size_t)l * DIN * DTR + (size_t)row * DTR;
        #pragma unroll
        for (int t = 0; t < DTR; t++) v = fmaf(dr[t], xp[(size_t)t * DIN + col], v);
    } else if (row < NXP) {
        v = xp[(size_t)(DTR + (row - DIN)) * DIN + col];
    }
    split2(v, &g_wch[idx], &g_wcl[idx]);
}

/* zero the K-pad columns of H1T (546..575) */
__global__ void k_h1pad() {
    int n = blockIdx.x * 8 + (threadIdx.x >> 5);
    int j = threadIdx.x & 31;
    if (j < (K2P - CH)) {
        g_h1h[(size_t)n * K2P + CH + j] = __float2bfloat16(0.f);
        g_h1l[(size_t)n * K2P + CH + j] = __float2bfloat16(0.f);
    }
}

/* ---------- encoder: per-group feature max -> split bf16 [bg][K1P] --------- */
__global__ void k_fg(const float* __restrict__ nb) {
    __shared__ float s[NPTS * FEAT];
    int bg = blockIdx.x;
    const float* src = nb + (size_t)bg * NPTS * FEAT;
    for (int t = threadIdx.x; t < NPTS * FEAT; t += blockDim.x) s[t] = src[t];
    __syncthreads();
    for (int c = threadIdx.x; c < K1P; c += blockDim.x) {
        float m = 0.f;
        if (c < FEAT) {
            m = s[c];
            #pragma unroll
            for (int n = 1; n < NPTS; n++) m = fmaxf(m, s[n * FEAT + c]);
        }
        split2(m, &g_fgh[(size_t)bg * K1P + c], &g_fgl[(size_t)bg * K1P + c]);
    }
}

/* ---------------- visible-index extraction (bool width-robust) ------------ */
__global__ void k_visidx(const unsigned char* __restrict__ m8) {
    if (threadIdx.x != 0) return;
    int b = blockIdx.x;
    int c8 = 0;
    for (int g = 0; g < GG; g++) c8 += (m8[(size_t)b * GG + g] != 0);
    int cnt = 0;
    if (c8 == NMASK) {
        for (int g = 0; g < GG; g++)
            if (!m8[(size_t)b * GG + g]) { if (cnt < GVIS) g_vis[b * GVIS + cnt] = g; cnt++; }
    } else {
        const int* m32 = (const int*)m8;
        for (int g = 0; g < GG; g++)
            if (!m32[(size_t)b * GG + g]) { if (cnt < GVIS) g_vis[b * GVIS + cnt] = g; cnt++; }
    }
}

/* ------------- gather tokens/centers + pos MLP -> initial h ---------------- */
__global__ void k_pos(const float* __restrict__ center,
                      const float* __restrict__ w1, const float* __restrict__ b1,
                      const float* __restrict__ w2, const float* __restrict__ b2) {
    __shared__ float hcache[128];
    __shared__ float cc[3];
    int r = blockIdx.x;
    int b = r / GVIS;
    int g = g_vis[r];
    int tid = threadIdx.x;
    if (tid < 3) cc[tid] = center[((size_t)b * GG + g) * 3 + tid];
    __syncthreads();
    float a = w1[tid * 3] * cc[0] + w1[tid * 3 + 1] * cc[1] + w1[tid * 3 + 2] * cc[2] + b1[tid];
    hcache[tid] = geluf(a);
    __syncthreads();
    const float* tok = g_tokens + ((size_t)b * GG + g) * ENCD;
    for (int e = tid; e < DDIM; e += 128) {
        float acc = b2[e];
        const float* wr = w2 + (size_t)e * 128;
        #pragma unroll 8
        for (int k = 0; k < 128; k++) acc = fmaf(wr[k], hcache[k], acc);
        g_h[(size_t)r * DDIM + e] = acc + tok[e];
    }
}

/* ------------- residual accumulate + LayerNorm -> split bf16 --------------- */
__global__ void k_lnres(int layer, const float* __restrict__ w, const float* __restrict__ b) {
    int r = blockIdx.x, tid = threadIdx.x;
    float* res = g_res + (size_t)r * DDIM;
    const float* h = g_h + (size_t)r * DDIM;
    float v[3], s1 = 0.f, s2 = 0.f;
    #pragma unroll
    for (int i = 0; i < 3; i++) {
        int c = tid + i * 128;
        float x = h[c];
        if (layer > 0) x += res[c];
        v[i] = x; res[c] = x;
        s1 += x; s2 += x * x;
    }
    reduce2_128(s1, s2);
    float mu = s1 * (1.f / DDIM);
    float rstd = rsqrtf(s2 * (1.f / DDIM) - mu * mu + EPSV);
    #pragma unroll
    for (int i = 0; i < 3; i++) {
        int c = tid + i * 128;
        float y = (v[i] - mu) * rstd * w[c] + b[c];
        split2(y, &g_hnh[(size_t)r * DDIM + c], &g_hnl[(size_t)r * DDIM + c]);
    }
}

/* ---------------- depthwise causal conv (k=4) + SiLU -> split -------------- */
__global__ void k_conv(const float* __restrict__ cw, const float* __restrict__ cb) {
    int idx = blockIdx.x * blockDim.x + threadIdx.x;
    if (idx >= BL * DIN) return;
    int d = idx % DIN, r = idx / DIN;
    int b = r / SEQL, l = r % SEQL;
    float acc = cb[d];
    #pragma unroll
    for (int k = 0; k < DCONV; k++) {
        int ll = l - (DCONV - 1) + k;
        if (ll >= 0) acc = fmaf(cw[d * DCONV + k], g_xz[((size_t)(b * SEQL + ll)) * (2 * DIN) + d], acc);
    }
    float y = siluf(acc);
    g_xi[idx] = y;
    split2(y, &g_xih[idx], &g_xil[idx]);
}

/* --------------------------- selective scan -> split ------------------------ */
__global__ void k_scan(const float* __restrict__ alog, const float* __restrict__ Dp) {
    int b = blockIdx.x / 6;
    int d = (blockIdx.x % 6) * 128 + threadIdx.x;
    float A[DSN];
    #pragma unroll
    for (int s = 0; s < DSN; s++) A[s] = -expf(alog[(size_t)d * DSN + s]);
    float Dd = Dp[d];
    float h[DSN];
    #pragma unroll
    for (int s = 0; s < DSN; s++) h[s] = 0.f;
    for (int l = 0; l < SEQL; l++) {
        int r = b * SEQL + l;
        float dt = g_dt[(size_t)r * DIN + d];
        float x  = g_xi[(size_t)r * DIN + d];
        float dtx = dt * x;
        const float* bl = g_bc + (size_t)r * (2 * DSN);
        float y = 0.f;
        #pragma unroll
        for (int s = 0; s < DSN; s++) {
            float dA = __expf(dt * A[s]);
            h[s] = fmaf(dA, h[s], dtx * bl[s]);
            y = fmaf(h[s], bl[DSN + s], y);
        }
        float z = g_xz[(size_t)r * (2 * DIN) + DIN + d];
        float u = (y + x * Dd) * siluf(z);
        split2(u, &g_uh[(size_t)r * DIN + d], &g_ul[(size_t)r * DIN + d]);
    }
}

/* ----------------------- final residual + double LN ------------------------ */
__global__ void k_final(float* __restrict__ out,
                        const float* __restrict__ w1, const float* __restrict__ b1,
                        const float* __restrict__ w2, const float* __restrict__ b2) {
    int r = blockIdx.x, tid = threadIdx.x;
    float v[3], s1 = 0.f, s2 = 0.f;
    #pragma unroll
    for (int i = 0; i < 3; i++) {
        int c = tid + i * 128;
        float x = g_res[(size_t)r * DDIM + c] + g_h[(size_t)r * DDIM + c];
        v[i] = x; s1 += x; s2 += x * x;
    }
    reduce2_128(s1, s2);
    float mu = s1 * (1.f / DDIM);
    float rstd = rsqrtf(s2 * (1.f / DDIM) - mu * mu + EPSV);
    s1 = 0.f; s2 = 0.f;
    #pragma unroll
    for (int i = 0; i < 3; i++) {
        int c = tid + i * 128;
        v[i] = (v[i] - mu) * rstd * w1[c] + b1[c];
        s1 += v[i]; s2 += v[i] * v[i];
    }
    reduce2_128(s1, s2);
    mu = s1 * (1.f / DDIM);
    rstd = rsqrtf(s2 * (1.f / DDIM) - mu * mu + EPSV);
    #pragma unroll
    for (int i = 0; i < 3; i++) {
        int c = tid + i * 128;
        out[(size_t)r * DDIM + c] = (v[i] - mu) * rstd * w2[c] + b2[c];
    }
}

/* -------------------------- mask -> output tail ---------------------------- */
__global__ void k_maskout(const unsigned char* __restrict__ m8, float* __restrict__ out, int out_size) {
    if (out_size < OUTH + BB * GG) return;
    __shared__ int use8;
    if (threadIdx.x == 0) {
        int c = 0;
        for (int g = 0; g < GG; g++) c += (m8[g] != 0);
        use8 = (c == NMASK);
    }
    __syncthreads();
    const int* m32 = (const int*)m8;
    for (int i = threadIdx.x; i < BB * GG; i += blockDim.x) {
        float v = use8 ? (m8[i] ? 1.f : 0.f) : (m32[i] ? 1.f : 0.f);
        out[OUTH + i] = v;
    }
}

/* ------------------------------- host driver ------------------------------- */
#define SMEM_MMA (2 * 65536)

extern "C" void kernel_launch(void* const* d_in, const int* in_sizes, int n_in,
                              void* d_out, int out_size) {
    (void)in_sizes; (void)n_in;
    const float* nb     = (const float*)d_in[0];
    const float* center = (const float*)d_in[1];
    const unsigned char* mask = (const unsigned char*)d_in[2];
    const float* c1w = (const float*)d_in[3];
    const float* c1b = (const float*)d_in[4];
    const float* bng = (const float*)d_in[5];
    const float* bnb = (const float*)d_in[6];
    const float* bnm = (const float*)d_in[7];
    const float* bnv = (const float*)d_in[8];
    const float* c2w = (const float*)d_in[9];
    const float* c2b = (const float*)d_in[10];
    const float* pw1 = (const float*)d_in[11];
    const float* pb1 = (const float*)d_in[12];
    const float* pw2 = (const float*)d_in[13];
    const float* pb2 = (const float*)d_in[14];
    const float* ipw = (const float*)d_in[15];
    const float* cw  = (const float*)d_in[16];
    const float* cb  = (const float*)d_in[17];
    const float* xpw = (const float*)d_in[18];
    const float* dpw = (const float*)d_in[19];
    const float* dpb = (const float*)d_in[20];
    const float* alog= (const float*)d_in[21];
    const float* Dp  = (const float*)d_in[22];
    const float* opw = (const float*)d_in[23];
    const float* lnw = (const float*)d_in[24];
    const float* lnb = (const float*)d_in[25];
    const float* nfw = (const float*)d_in[26];
    const float* nfb = (const float*)d_in[27];
    const float* n2w = (const float*)d_in[28];
    const float* n2b = (const float*)d_in[29];
    float* out = (float*)d_out;

    cudaFuncSetAttribute(k_mma<0>, cudaFuncAttributeMaxDynamicSharedMemorySize, SMEM_MMA);
    cudaFuncSetAttribute(k_mma<1>, cudaFuncAttributeMaxDynamicSharedMemorySize, SMEM_MMA);
    cudaFuncSetAttribute(k_mma<2>, cudaFuncAttributeMaxDynamicSharedMemorySize, SMEM_MMA);
    cudaFuncSetAttribute(k_mma<3>, cudaFuncAttributeMaxDynamicSharedMemorySize, SMEM_MMA);

    float *be, *tok, *xz, *xi, *dtb, *bc, *hb;
    cudaGetSymbolAddress((void**)&be,  g_biaseff);
    cudaGetSymbolAddress((void**)&tok, g_tokens);
    cudaGetSymbolAddress((void**)&xz,  g_xz);
    cudaGetSymbolAddress((void**)&xi,  g_xi);
    cudaGetSymbolAddress((void**)&dtb, g_dt);
    cudaGetSymbolAddress((void**)&bc,  g_bc);
    cudaGetSymbolAddress((void**)&hb,  g_h);
    __nv_bfloat16 *fgh, *fgl, *w0h, *w0l, *nbh, *nbl, *w1h, *w1l, *w2h, *w2l, *h1h, *h1l;
    __nv_bfloat16 *ipwh, *ipwl, *wch, *wcl, *opwh, *opwl;
    __nv_bfloat16 *hnh, *hnl, *xih, *xil, *uh, *ul;
    cudaGetSymbolAddress((void**)&fgh, g_fgh);  cudaGetSymbolAddress((void**)&fgl, g_fgl);
    cudaGetSymbolAddress((void**)&w0h, g_w0h);  cudaGetSymbolAddress((void**)&w0l, g_w0l);
    cudaGetSymbolAddress((void**)&nbh, g_nbh);  cudaGetSymbolAddress((void**)&nbl, g_nbl);
    cudaGetSymbolAddress((void**)&w1h, g_w1h);  cudaGetSymbolAddress((void**)&w1l, g_w1l);
    cudaGetSymbolAddress((void**)&w2h, g_w2h);  cudaGetSymbolAddress((void**)&w2l, g_w2l);
    cudaGetSymbolAddress((void**)&h1h, g_h1h);  cudaGetSymbolAddress((void**)&h1l, g_h1l);
    cudaGetSymbolAddress((void**)&ipwh, g_ipwh); cudaGetSymbolAddress((void**)&ipwl, g_ipwl);
    cudaGetSymbolAddress((void**)&wch, g_wch);  cudaGetSymbolAddress((void**)&wcl, g_wcl);
    cudaGetSymbolAddress((void**)&opwh, g_opwh); cudaGetSymbolAddress((void**)&opwl, g_opwl);
    cudaGetSymbolAddress((void**)&hnh, g_hnh);  cudaGetSymbolAddress((void**)&hnl, g_hnl);
    cudaGetSymbolAddress((void**)&xih, g_xih);  cudaGetSymbolAddress((void**)&xil, g_xil);
    cudaGetSymbolAddress((void**)&uh,  g_uh);   cudaGetSymbolAddress((void**)&ul,  g_ul);

    /* -------- weight & input split prepasses -------- */
    auto splitN = [](long long total) { return (int)((total + 255) / 256); };
    long long tNB = (long long)NCOL * K1P;
    k_split<<<splitN(tNB), 256>>>(nb, FEAT, 0, NCOL, FEAT, nbh, nbl, K1P, tNB);
    long long tW1 = (long long)M1P * K1P;
    k_split<<<splitN(tW1), 256>>>(c1w, 2 * FEAT, 0, CH, FEAT, w0h, w0l, K1P, tW1);
    k_split<<<splitN(tW1), 256>>>(c1w, 2 * FEAT, FEAT, CH, FEAT, w1h, w1l, K1P, tW1);
    long long tW2 = (long long)ENCD * K2P;
    k_split<<<splitN(tW2), 256>>>(c2w, CH, 0, ENCD, CH, w2h, w2l, K2P, tW2);
    long long tIP = (long long)DEPTH * 2 * DIN * DDIM;
    k_split<<<splitN(tIP), 256>>>(ipw, DDIM, 0, DEPTH * 2 * DIN, DDIM, ipwh, ipwl, DDIM, tIP);
    long long tOP = (long long)DEPTH * DDIM * DIN;
    k_split<<<splitN(tOP), 256>>>(opw, DIN, 0, DEPTH * DDIM, DIN, opwh, opwl, DIN, tOP);
    k_wcomb<<<splitN((long long)DEPTH * NXPP * DIN), 256>>>(dpw, xpw);
    k_h1pad<<<NCOL / 8, 256>>>();

    /* -------- encoder -------- */
    k_fg<<<BGC, 256>>>(nb);
    /* bias-eff: be[546,2048] = c1w[:, :273] @ fg^T  (tensor path) */
    k_mma<0><<<dim3(M1P / 128, BGC / 128), 256, SMEM_MMA>>>(
        w0h, w0l, K1P, fgh, fgl, K1P, K1P / 64,
        nullptr, nullptr, nullptr, nullptr, nullptr,
        be, BGC, nullptr, nullptr, nullptr, CH, BGC);
    /* GEMM1: D[640,65536] -> H1T split (staged coalesced epilogue) */
    k_mma<1><<<dim3(M1P / 128, NCOL / 128), 256, SMEM_MMA>>>(
        w1h, w1l, K1P, nbh, nbl, K1P, K1P / 64,
        be, bnm, bnv, bng, bnb, nullptr, 0, nullptr, h1h, h1l, CH, NCOL);
    /* GEMM2: D[384,65536] -> tokens (fused maxpool) */
    k_mma<2><<<dim3(ENCD / 128, NCOL / 128), 256, SMEM_MMA>>>(
        w2h, w2l, K2P, h1h, h1l, K2P, K2P / 64,
        c2b, nullptr, nullptr, nullptr, nullptr, tok, 0, nullptr, nullptr, nullptr, ENCD, NCOL);

    /* -------- gather + pos embed -------- */
    k_visidx<<<BB, 32>>>(mask);
    k_pos<<<BL, 128>>>(center, pw1, pb1, pw2, pb2);

    /* -------- mamba stack -------- */
    for (int i = 0; i < DEPTH; i++) {
        k_lnres<<<BL, 128>>>(i, lnw + (size_t)i * DDIM, lnb + (size_t)i * DDIM);
        /* in_proj: xz[824,1536] = hn @ ipw^T */
        k_mma<0><<<dim3(BLP / 128, 2 * DIN / 128), 256, SMEM_MMA>>>(
            hnh, hnl, DDIM, ipwh + (size_t)i * 2 * DIN * DDIM, ipwl + (size_t)i * 2 * DIN * DDIM, DDIM,
            DDIM / 64, nullptr, nullptr, nullptr, nullptr, nullptr,
            xz, 2 * DIN, nullptr, nullptr, nullptr, BL, 2 * DIN);
        k_conv<<<(BL * DIN + 255) / 256, 256>>>(cw + (size_t)i * DIN * DCONV, cb + (size_t)i * DIN);
        /* merged x_proj+dt_proj: dt[824,768], bc[824,32] */
        k_mma<3><<<dim3(BLP / 128, NXPP / 128), 256, SMEM_MMA>>>(
            xih, xil, DIN, wch + (size_t)i * NXPP * DIN, wcl + (size_t)i * NXPP * DIN, DIN,
            DIN / 64, dpb + (size_t)i * DIN, nullptr, nullptr, nullptr, nullptr,
            dtb, DIN, bc, nullptr, nullptr, BL, NXP);
        k_scan<<<BB * 6, 128>>>(alog + (size_t)i * DIN * DSN, Dp + (size_t)i * DIN);
        /* out_proj: h[824,384] = u @ opw^T */
        k_mma<0><<<dim3(BLP / 128, DDIM / 128), 256, SMEM_MMA>>>(
            uh, ul, DIN, opwh + (size_t)i * DDIM * DIN, opwl + (size_t)i * DDIM * DIN, DIN,
            DIN / 64, nullptr, nullptr, nullptr, nullptr, nullptr,
            hb, DDIM, nullptr, nullptr, nullptr, BL, DDIM);
    }

    /* -------- final norms + outputs -------- */
    k_final<<<BL, 128>>>(out, nfw, nfb, n2w, n2b);
    k_maskout<<<1, 256>>>(mask, out, out_size);
}

// round 6
// speedup vs baseline: 2.8103x; 1.1562x over previous
#include <cuda_runtime.h>
#include <cuda_bf16.h>
#include <math.h>
#include <stdint.h>

#define BB 8
#define GG 256
#define NPTS 32
#define FEAT 273
#define CH 546
#define ENCD 384
#define DDIM 384
#define DEPTH 12
#define DIN 768
#define DSN 16
#define DCONV 4
#define DTR 24
#define GVIS 103
#define SEQL 103
#define BL (BB*GVIS)        /* 824 rows */
#define BLP 896             /* buffer pad */
#define BGC (BB*GG)         /* 2048 groups */
#define NCOL (BGC*NPTS)     /* 65536 point columns */
#define NMASK 153
#define OUTH (BL*DDIM)      /* 316416 */
#define NXP (DIN + 2*DSN)   /* 800 */
#define NXPP 896            /* padded */
#define K1P 320             /* FEAT 273 -> padded */
#define M1P 640             /* CH 546 -> padded  */
#define K2P 576             /* CH 546 -> padded  */
#define EPSV 1e-5f

/* ------------------------- scratch (device globals) ------------------------ */
__device__ float g_biaseff[(size_t)CH * BGC];
__device__ float g_tokens[(size_t)BGC * ENCD];
__device__ int   g_vis[BL];
__device__ float g_h[BL * DDIM];
__device__ float g_res[BL * DDIM];
__device__ float g_xz[BL * 2 * DIN];
__device__ float g_xi[BL * DIN];
__device__ float g_dt[BL * DIN];
__device__ float g_bc[BL * 2 * DSN];

/* bf16-split operand buffers */
__device__ __align__(256) __nv_bfloat16 g_fgh[(size_t)BGC * K1P];
__device__ __align__(256) __nv_bfloat16 g_fgl[(size_t)BGC * K1P];
__device__ __align__(256) __nv_bfloat16 g_w0h[(size_t)M1P * K1P];
__device__ __align__(256) __nv_bfloat16 g_w0l[(size_t)M1P * K1P];
__device__ __align__(256) __nv_bfloat16 g_nbh[(size_t)NCOL * K1P];
__device__ __align__(256) __nv_bfloat16 g_nbl[(size_t)NCOL * K1P];
__device__ __align__(256) __nv_bfloat16 g_w1h[(size_t)M1P * K1P];
__device__ __align__(256) __nv_bfloat16 g_w1l[(size_t)M1P * K1P];
__device__ __align__(256) __nv_bfloat16 g_w2h[(size_t)ENCD * K2P];
__device__ __align__(256) __nv_bfloat16 g_w2l[(size_t)ENCD * K2P];
__device__ __align__(256) __nv_bfloat16 g_h1h[(size_t)NCOL * K2P];
__device__ __align__(256) __nv_bfloat16 g_h1l[(size_t)NCOL * K2P];
__device__ __align__(256) __nv_bfloat16 g_ipwh[(size_t)DEPTH * 2 * DIN * DDIM];
__device__ __align__(256) __nv_bfloat16 g_ipwl[(size_t)DEPTH * 2 * DIN * DDIM];
__device__ __align__(256) __nv_bfloat16 g_wch[(size_t)DEPTH * NXPP * DIN];
__device__ __align__(256) __nv_bfloat16 g_wcl[(size_t)DEPTH * NXPP * DIN];
__device__ __align__(256) __nv_bfloat16 g_opwh[(size_t)DEPTH * DDIM * DIN];
__device__ __align__(256) __nv_bfloat16 g_opwl[(size_t)DEPTH * DDIM * DIN];
__device__ __align__(256) __nv_bfloat16 g_hnh[(size_t)BLP * DDIM];
__device__ __align__(256) __nv_bfloat16 g_hnl[(size_t)BLP * DDIM];
__device__ __align__(256) __nv_bfloat16 g_xih[(size_t)BLP * DIN];
__device__ __align__(256) __nv_bfloat16 g_xil[(size_t)BLP * DIN];
__device__ __align__(256) __nv_bfloat16 g_uh[(size_t)BLP * DIN];
__device__ __align__(256) __nv_bfloat16 g_ul[(size_t)BLP * DIN];

/* ------------------------------ small helpers ----------------------------- */
__device__ __forceinline__ float siluf(float x) { return x / (1.f + expf(-x)); }
__device__ __forceinline__ float geluf(float x) { return 0.5f * x * (1.f + erff(x * 0.70710678118654752f)); }
__device__ __forceinline__ float softplusf(float x) { return (x > 20.f) ? x : log1pf(expf(x)); }
__device__ __forceinline__ void split2(float v, __nv_bfloat16* h, __nv_bfloat16* l) {
    __nv_bfloat16 hh = __float2bfloat16(v);
    *h = hh;
    *l = __float2bfloat16(v - __bfloat162float(hh));
}

__device__ __forceinline__ void reduce2_128(float& s1, float& s2) {
    #pragma unroll
    for (int o = 16; o; o >>= 1) {
        s1 += __shfl_xor_sync(0xffffffffu, s1, o);
        s2 += __shfl_xor_sync(0xffffffffu, s2, o);
    }
    __shared__ float ra[4], rb[4];
    int w = threadIdx.x >> 5, l = threadIdx.x & 31;
    if (l == 0) { ra[w] = s1; rb[w] = s2; }
    __syncthreads();
    s1 = ra[0] + ra[1] + ra[2] + ra[3];
    s2 = rb[0] + rb[1] + rb[2] + rb[3];
    __syncthreads();
}

/* --------------------------- PTX wrappers --------------------------------- */
__device__ __forceinline__ uint32_t smem_u32(const void* p) {
    uint32_t a;
    asm("{ .reg .u64 t; cvta.to.shared.u64 t, %1; cvt.u32.u64 %0, t; }" : "=r"(a) : "l"(p));
    return a;
}
#define SWZ128(o) ((o) ^ (((o) >> 3) & 0x70))
#define CP_ASYNC16(d, s) asm volatile("cp.async.cg.shared.global [%0], [%1], 16;" :: "r"(d), "l"(s))
#define CP_COMMIT()      asm volatile("cp.async.commit_group;" ::: "memory")
#define CP_WAIT1()       asm volatile("cp.async.wait_group 1;" ::: "memory")
#define CP_WAIT0()       asm volatile("cp.async.wait_group 0;" ::: "memory")

__device__ __forceinline__ void ldm_x4(uint32_t* r, uint32_t addr) {
    asm volatile("ldmatrix.sync.aligned.m8n8.x4.shared.b16 {%0,%1,%2,%3}, [%4];"
        : "=r"(r[0]), "=r"(r[1]), "=r"(r[2]), "=r"(r[3]) : "r"(addr));
}
__device__ __forceinline__ void mma16816(float* c, const uint32_t* a, uint32_t b0, uint32_t b1) {
    asm volatile("mma.sync.aligned.m16n8k16.row.col.f32.bf16.bf16.f32 "
        "{%0,%1,%2,%3}, {%4,%5,%6,%7}, {%8,%9}, {%0,%1,%2,%3};"
        : "+f"(c[0]), "+f"(c[1]), "+f"(c[2]), "+f"(c[3])
        : "r"(a[0]), "r"(a[1]), "r"(a[2]), "r"(a[3]), "r"(b0), "r"(b1));
}

/* =================== generic bf16-split mma.sync GEMM ======================
 * D[M,N] = A[M,K] * B[N,K]^T  (h/l split bf16, K-major, ld = Kpad)
 * grid = (Mtiles, Ntiles) -- M fastest so consecutive CTAs share the B tile.
 * 256 threads = 8 warps (2 m x 4 n). CTA tile TM x TN (template).
 * Split: D = AhBh + AhBl + AlBh (fp32 accumulate).
 * EPI 0: C[m*ldc+n] = v               (m<Mv, n<Nv)
 * EPI 1: v+=be[m*BGC+grp]; BN+relu; split -> O1/O2[n*K2P+m] (staged, m<CH)
 * EPI 2: group maxpool + p0[m] -> C[grp*ENCD+m]  (tokens; TN=128 only)
 * EPI 3: n<DIN: C[m*DIN+n]=softplus(v+p0[n]); n<NXP: C2[m*32+n-DIN]=v (m<Mv)
 * ========================================================================= */
template<int EPI, int TM, int TN>
__global__ __launch_bounds__(256) void k_mma(
    const __nv_bfloat16* __restrict__ Ah, const __nv_bfloat16* __restrict__ Al, int lda,
    const __nv_bfloat16* __restrict__ Bh, const __nv_bfloat16* __restrict__ Bl, int ldb,
    int NKC,
    const float* __restrict__ p0, const float* __restrict__ p1,
    const float* __restrict__ p2, const float* __restrict__ p3,
    const float* __restrict__ p4,
    float* __restrict__ C, int ldc, float* __restrict__ C2,
    __nv_bfloat16* __restrict__ O1, __nv_bfloat16* __restrict__ O2,
    int Mv, int Nv)
{
    constexpr int MI = TM / 32;          /* 16-row frags per warp (m) */
    constexpr int NJ = TN / 32;          /* 8-col frags per warp (n)  */
    constexpr int NB2 = (NJ + 1) / 2;    /* b ldmatrix calls          */
    constexpr int LA = TM / 32;          /* A 16B-loads per thread    */
    constexpr int LB = TN / 32;
    constexpr uint32_t ABY = TM * 128;   /* one A tile bytes          */
    constexpr uint32_t BBY = TN * 128;
    constexpr uint32_t BUFSZ = 2 * ABY + 2 * BBY;

    extern __shared__ __align__(1024) char smem[];
    const uint32_t sb = smem_u32(smem);
    const int tid = threadIdx.x, wid = tid >> 5, lid = tid & 31;
    const int wrow = wid >> 2, wcol = wid & 3;
    const int quad = lid >> 2, tq = lid & 3;
    const int m0 = blockIdx.x * TM, n0 = blockIdx.y * TN;

    const int lrow = (lid & 7) + 8 * ((lid >> 3) & 1);
    const int lk   = 8 * (lid >> 4);

    float acc[MI][NJ][4];
    #pragma unroll
    for (int i = 0; i < MI; i++)
        #pragma unroll
        for (int j = 0; j < NJ; j++)
            #pragma unroll
            for (int k = 0; k < 4; k++) acc[i][j][k] = 0.f;

    auto loadChunk = [&](int kc, int c) {
        const uint32_t bufb = sb + c * BUFSZ;
        #pragma unroll
        for (int p = 0; p < LA; p++) {
            int idx = tid + p * 256;
            int row = idx >> 3, c16 = idx & 7;
            uint32_t sw = SWZ128((uint32_t)(row * 128 + c16 * 16));
            const void* gh = Ah + (size_t)(m0 + row) * lda + kc * 64 + c16 * 8;
            const void* gl = Al + (size_t)(m0 + row) * lda + kc * 64 + c16 * 8;
            CP_ASYNC16(bufb + sw, gh);
            CP_ASYNC16(bufb + ABY + sw, gl);
        }
        #pragma unroll
        for (int p = 0; p < LB; p++) {
            int idx = tid + p * 256;
            int row = idx >> 3, c16 = idx & 7;
            uint32_t sw = SWZ128((uint32_t)(row * 128 + c16 * 16));
            const void* gh = Bh + (size_t)(n0 + row) * ldb + kc * 64 + c16 * 8;
            const void* gl = Bl + (size_t)(n0 + row) * ldb + kc * 64 + c16 * 8;
            CP_ASYNC16(bufb + 2 * ABY + sw, gh);
            CP_ASYNC16(bufb + 2 * ABY + BBY + sw, gl);
        }
        CP_COMMIT();
    };

    loadChunk(0, 0);
    if (NKC > 1) loadChunk(1, 1); else CP_COMMIT();

    for (int kc = 0; kc < NKC; kc++) {
        const int c = kc & 1;
        if (kc + 1 < NKC) CP_WAIT1(); else CP_WAIT0();
        __syncthreads();
        const uint32_t ahb = sb + c * BUFSZ;
        const uint32_t alb = ahb + ABY;
        const uint32_t bhb = ahb + 2 * ABY;
        const uint32_t blb = bhb + BBY;
        #pragma unroll
        for (int ks = 0; ks < 4; ks++) {
            const int k0 = ks * 16 + lk;
            uint32_t fah[MI][4], fal[MI][4], fbh[NB2][4], fbl[NB2][4];
            #pragma unroll
            for (int bi = 0; bi < MI; bi++) {
                int r = wrow * (TM / 2) + bi * 16 + lrow;
                ldm_x4(fah[bi], ahb + SWZ128((uint32_t)(r * 128 + k0 * 2)));
                ldm_x4(fal[bi], alb + SWZ128((uint32_t)(r * 128 + k0 * 2)));
            }
            #pragma unroll
            for (int bj2 = 0; bj2 < NB2; bj2++) {
                int r = wcol * (TN / 4) + bj2 * 16 + lrow;
                ldm_x4(fbh[bj2], bhb + SWZ128((uint32_t)(r * 128 + k0 * 2)));
                ldm_x4(fbl[bj2], blb + SWZ128((uint32_t)(r * 128 + k0 * 2)));
            }
            #pragma unroll
            for (int bi = 0; bi < MI; bi++) {
                #pragma unroll
                for (int bj = 0; bj < NJ; bj++) {
                    uint32_t bh0 = fbh[bj >> 1][bj & 1], bh1 = fbh[bj >> 1][2 + (bj & 1)];
                    uint32_t bl0 = fbl[bj >> 1][bj & 1], bl1 = fbl[bj >> 1][2 + (bj & 1)];
                    mma16816(acc[bi][bj], fah[bi], bh0, bh1);
                    mma16816(acc[bi][bj], fah[bi], bl0, bl1);
                    mma16816(acc[bi][bj], fal[bi], bh0, bh1);
                }
            }
        }
        __syncthreads();
        if (kc + 2 < NKC) loadChunk(kc + 2, c);
    }

    const int grp = (n0 >> 5) + wcol;  /* point-group (TN=128 epilogues) */

    if (EPI == 1) {
        /* staged transposed split store (TM=TN=128 only) */
        const int LDE = 136;
        __nv_bfloat16* sh = (__nv_bfloat16*)smem;
        __nv_bfloat16* sl = (__nv_bfloat16*)(smem + 128 * LDE * 2);
        const int mlim = (CH - m0 < 128) ? (CH - m0) : 128;
        #pragma unroll
        for (int bi = 0; bi < MI; bi++) {
            #pragma unroll
            for (int h0 = 0; h0 < 2; h0++) {
                const int ml = wrow * (TM / 2) + bi * 16 + quad + 8 * h0;
                const int m = m0 + ml;
                if (m < CH) {
                    const float be = p0[(size_t)m * BGC + grp];
                    const float bnm = p1[m];
                    const float sc  = rsqrtf(p2[m] + EPSV) * p3[m];
                    const float bb  = p4[m];
                    #pragma unroll
                    for (int bj = 0; bj < NJ; bj++) {
                        #pragma unroll
                        for (int e = 0; e < 2; e++) {
                            int nl = wcol * (TN / 4) + bj * 8 + 2 * tq + e;
                            float v = acc[bi][bj][h0 * 2 + e] + be;
                            v = fmaxf((v - bnm) * sc + bb, 0.f);
                            split2(v, &sh[nl * LDE + ml], &sl[nl * LDE + ml]);
                        }
                    }
                }
            }
        }
        __syncthreads();
        for (int idx = tid; idx < 128 * 16; idx += 256) {
            int nl = idx >> 4, ch = idx & 15;
            int mbeg = ch * 8;
            if (mbeg < mlim) {
                size_t gbase = (size_t)(n0 + nl) * K2P + m0 + mbeg;
                if (mbeg + 8 <= mlim) {
                    *(uint4*)(&O1[gbase]) = *(const uint4*)(&sh[nl * LDE + mbeg]);
                    *(uint4*)(&O2[gbase]) = *(const uint4*)(&sl[nl * LDE + mbeg]);
                } else {
                    for (int t = 0; t < mlim - mbeg; t++) {
                        O1[gbase + t] = sh[nl * LDE + mbeg + t];
                        O2[gbase + t] = sl[nl * LDE + mbeg + t];
                    }
                }
            }
        }
        return;
    }

    #pragma unroll
    for (int bi = 0; bi < MI; bi++) {
        #pragma unroll
        for (int h0 = 0; h0 < 2; h0++) {
            const int m = m0 + wrow * (TM / 2) + bi * 16 + quad + 8 * h0;
            if (EPI == 2) {
                float vm = -INFINITY;
                #pragma unroll
                for (int bj = 0; bj < NJ; bj++) {
                    vm = fmaxf(vm, acc[bi][bj][h0 * 2]);
                    vm = fmaxf(vm, acc[bi][bj][h0 * 2 + 1]);
                }
                vm = fmaxf(vm, __shfl_xor_sync(0xffffffffu, vm, 1));
                vm = fmaxf(vm, __shfl_xor_sync(0xffffffffu, vm, 2));
                if (tq == 0) C[(size_t)grp * ENCD + m] = vm + p0[m];
            } else if (EPI == 0) {
                if (m < Mv) {
                    #pragma unroll
                    for (int bj = 0; bj < NJ; bj++) {
                        #pragma unroll
                        for (int e = 0; e < 2; e++) {
                            int n = n0 + wcol * (TN / 4) + bj * 8 + 2 * tq + e;
                            if (n < Nv) C[(size_t)m * ldc + n] = acc[bi][bj][h0 * 2 + e];
                        }
                    }
                }
            } else { /* EPI 3 */
                if (m < Mv) {
                    #pragma unroll
                    for (int bj = 0; bj < NJ; bj++) {
                        #pragma unroll
                        for (int e = 0; e < 2; e++) {
                            int n = n0 + wcol * (TN / 4) + bj * 8 + 2 * tq + e;
                            float v = acc[bi][bj][h0 * 2 + e];
                            if (n < DIN) C[(size_t)m * DIN + n] = softplusf(v + p0[n]);
                            else if (n < NXP) C2[(size_t)m * (2 * DSN) + (n - DIN)] = v;
                        }
                    }
                }
            }
        }
    }
}

/* --------------------------- split prepass kernels ------------------------- */
__global__ void k_split(const float* __restrict__ src, int sld, int soff,
                        int R, int K, __nv_bfloat16* __restrict__ dh,
                        __nv_bfloat16* __restrict__ dl, int Kp, long long total) {
    long long i = (long long)blockIdx.x * 256 + threadIdx.x;
    if (i >= total) return;
    int k = (int)(i % Kp);
    long long r = i / Kp;
    float v = (r < R && k < K) ? src[r * sld + soff + k] : 0.f;
    split2(v, &dh[i], &dl[i]);
}

__global__ void k_wcomb(const float* __restrict__ dpw, const float* __restrict__ xpw) {
    long long idx = (long long)blockIdx.x * 256 + threadIdx.x;
    if (idx >= (long long)DEPTH * NXPP * DIN) return;
    int col = (int)(idx % DIN);
    int rem = (int)(idx / DIN);
    int row = rem % NXPP;
    int l   = rem / NXPP;
    const float* xp = xpw + (size_t)l * (DTR + 2 * DSN) * DIN;
    float v = 0.f;
    if (row < DIN) {
        const float* dr = dpw + (size_t)l * DIN * DTR + (size_t)row * DTR;
        #pragma unroll
        for (int t = 0; t < DTR; t++) v = fmaf(dr[t], xp[(size_t)t * DIN + col], v);
    } else if (row < NXP) {
        v = xp[(size_t)(DTR + (row - DIN)) * DIN + col];
    }
    split2(v, &g_wch[idx], &g_wcl[idx]);
}

__global__ void k_h1pad() {
    int n = blockIdx.x * 8 + (threadIdx.x >> 5);
    int j = threadIdx.x & 31;
    if (j < (K2P - CH)) {
        g_h1h[(size_t)n * K2P + CH + j] = __float2bfloat16(0.f);
        g_h1l[(size_t)n * K2P + CH + j] = __float2bfloat16(0.f);
    }
}

/* ---------- encoder: per-group feature max -> split bf16 [bg][K1P] --------- */
__global__ void k_fg(const float* __restrict__ nb) {
    __shared__ float s[NPTS * FEAT];
    int bg = blockIdx.x;
    const float* src = nb + (size_t)bg * NPTS * FEAT;
    for (int t = threadIdx.x; t < NPTS * FEAT; t += blockDim.x) s[t] = src[t];
    __syncthreads();
    for (int c = threadIdx.x; c < K1P; c += blockDim.x) {
        float m = 0.f;
        if (c < FEAT) {
            m = s[c];
            #pragma unroll
            for (int n = 1; n < NPTS; n++) m = fmaxf(m, s[n * FEAT + c]);
        }
        split2(m, &g_fgh[(size_t)bg * K1P + c], &g_fgl[(size_t)bg * K1P + c]);
    }
}

/* ---------------- visible-index extraction (bool width-robust) ------------ */
__global__ void k_visidx(const unsigned char* __restrict__ m8) {
    if (threadIdx.x != 0) return;
    int b = blockIdx.x;
    int c8 = 0;
    for (int g = 0; g < GG; g++) c8 += (m8[(size_t)b * GG + g] != 0);
    int cnt = 0;
    if (c8 == NMASK) {
        for (int g = 0; g < GG; g++)
            if (!m8[(size_t)b * GG + g]) { if (cnt < GVIS) g_vis[b * GVIS + cnt] = g; cnt++; }
    } else {
        const int* m32 = (const int*)m8;
        for (int g = 0; g < GG; g++)
            if (!m32[(size_t)b * GG + g]) { if (cnt < GVIS) g_vis[b * GVIS + cnt] = g; cnt++; }
    }
}

/* ------------- gather tokens/centers + pos MLP -> initial h ---------------- */
__global__ void k_pos(const float* __restrict__ center,
                      const float* __restrict__ w1, const float* __restrict__ b1,
                      const float* __restrict__ w2, const float* __restrict__ b2) {
    __shared__ float hcache[128];
    __shared__ float cc[3];
    int r = blockIdx.x;
    int b = r / GVIS;
    int g = g_vis[r];
    int tid = threadIdx.x;
    if (tid < 3) cc[tid] = center[((size_t)b * GG + g) * 3 + tid];
    __syncthreads();
    float a = w1[tid * 3] * cc[0] + w1[tid * 3 + 1] * cc[1] + w1[tid * 3 + 2] * cc[2] + b1[tid];
    hcache[tid] = geluf(a);
    __syncthreads();
    const float* tok = g_tokens + ((size_t)b * GG + g) * ENCD;
    for (int e = tid; e < DDIM; e += 128) {
        float acc = b2[e];
        const float* wr = w2 + (size_t)e * 128;
        #pragma unroll 8
        for (int k = 0; k < 128; k++) acc = fmaf(wr[k], hcache[k], acc);
        g_h[(size_t)r * DDIM + e] = acc + tok[e];
    }
}

/* ------------- residual accumulate + LayerNorm -> split bf16 --------------- */
__global__ void k_lnres(int layer, const float* __restrict__ w, const float* __restrict__ b) {
    int r = blockIdx.x, tid = threadIdx.x;
    float* res = g_res + (size_t)r * DDIM;
    const float* h = g_h + (size_t)r * DDIM;
    float v[3], s1 = 0.f, s2 = 0.f;
    #pragma unroll
    for (int i = 0; i < 3; i++) {
        int c = tid + i * 128;
        float x = h[c];
        if (layer > 0) x += res[c];
        v[i] = x; res[c] = x;
        s1 += x; s2 += x * x;
    }
    reduce2_128(s1, s2);
    float mu = s1 * (1.f / DDIM);
    float rstd = rsqrtf(s2 * (1.f / DDIM) - mu * mu + EPSV);
    #pragma unroll
    for (int i = 0; i < 3; i++) {
        int c = tid + i * 128;
        float y = (v[i] - mu) * rstd * w[c] + b[c];
        split2(y, &g_hnh[(size_t)r * DDIM + c], &g_hnl[(size_t)r * DDIM + c]);
    }
}

/* ---------------- depthwise causal conv (k=4) + SiLU -> split -------------- */
__global__ void k_conv(const float* __restrict__ cw, const float* __restrict__ cb) {
    int idx = blockIdx.x * blockDim.x + threadIdx.x;
    if (idx >= BL * DIN) return;
    int d = idx % DIN, r = idx / DIN;
    int b = r / SEQL, l = r % SEQL;
    float acc = cb[d];
    #pragma unroll
    for (int k = 0; k < DCONV; k++) {
        int ll = l - (DCONV - 1) + k;
        if (ll >= 0) acc = fmaf(cw[d * DCONV + k], g_xz[((size_t)(b * SEQL + ll)) * (2 * DIN) + d], acc);
    }
    float y = siluf(acc);
    g_xi[idx] = y;
    split2(y, &g_xih[idx], &g_xil[idx]);
}

/* --------------------------- selective scan -> split ------------------------ */
__global__ void k_scan(const float* __restrict__ alog, const float* __restrict__ Dp) {
    int b = blockIdx.x / 6;
    int d = (blockIdx.x % 6) * 128 + threadIdx.x;
    float A[DSN];
    #pragma unroll
    for (int s = 0; s < DSN; s++) A[s] = -expf(alog[(size_t)d * DSN + s]);
    float Dd = Dp[d];
    float h[DSN];
    #pragma unroll
    for (int s = 0; s < DSN; s++) h[s] = 0.f;
    for (int l = 0; l < SEQL; l++) {
        int r = b * SEQL + l;
        float dt = g_dt[(size_t)r * DIN + d];
        float x  = g_xi[(size_t)r * DIN + d];
        float dtx = dt * x;
        const float* bl = g_bc + (size_t)r * (2 * DSN);
        float y = 0.f;
        #pragma unroll
        for (int s = 0; s < DSN; s++) {
            float dA = __expf(dt * A[s]);
            h[s] = fmaf(dA, h[s], dtx * bl[s]);
            y = fmaf(h[s], bl[DSN + s], y);
        }
        float z = g_xz[(size_t)r * (2 * DIN) + DIN + d];
        float u = (y + x * Dd) * siluf(z);
        split2(u, &g_uh[(size_t)r * DIN + d], &g_ul[(size_t)r * DIN + d]);
    }
}

/* ----------------------- final residual + double LN ------------------------ */
__global__ void k_final(float* __restrict__ out,
                        const float* __restrict__ w1, const float* __restrict__ b1,
                        const float* __restrict__ w2, const float* __restrict__ b2) {
    int r = blockIdx.x, tid = threadIdx.x;
    float v[3], s1 = 0.f, s2 = 0.f;
    #pragma unroll
    for (int i = 0; i < 3; i++) {
        int c = tid + i * 128;
        float x = g_res[(size_t)r * DDIM + c] + g_h[(size_t)r * DDIM + c];
        v[i] = x; s1 += x; s2 += x * x;
    }
    reduce2_128(s1, s2);
    float mu = s1 * (1.f / DDIM);
    float rstd = rsqrtf(s2 * (1.f / DDIM) - mu * mu + EPSV);
    s1 = 0.f; s2 = 0.f;
    #pragma unroll
    for (int i = 0; i < 3; i++) {
        int c = tid + i * 128;
        v[i] = (v[i] - mu) * rstd * w1[c] + b1[c];
        s1 += v[i]; s2 += v[i] * v[i];
    }
    reduce2_128(s1, s2);
    mu = s1 * (1.f / DDIM);
    rstd = rsqrtf(s2 * (1.f / DDIM) - mu * mu + EPSV);
    #pragma unroll
    for (int i = 0; i < 3; i++) {
        int c = tid + i * 128;
        out[(size_t)r * DDIM + c] = (v[i] - mu) * rstd * w2[c] + b2[c];
    }
}

/* -------------------------- mask -> output tail ---------------------------- */
__global__ void k_maskout(const unsigned char* __restrict__ m8, float* __restrict__ out, int out_size) {
    if (out_size < OUTH + BB * GG) return;
    __shared__ int use8;
    if (threadIdx.x == 0) {
        int c = 0;
        for (int g = 0; g < GG; g++) c += (m8[g] != 0);
        use8 = (c == NMASK);
    }
    __syncthreads();
    const int* m32 = (const int*)m8;
    for (int i = threadIdx.x; i < BB * GG; i += blockDim.x) {
        float v = use8 ? (m8[i] ? 1.f : 0.f) : (m32[i] ? 1.f : 0.f);
        out[OUTH + i] = v;
    }
}

/* ------------------------------- host driver ------------------------------- */
#define SMEM_128 (2 * 65536)          /* 128x128 double buffer */
#define SMEM_64x128 (2 * 49152)
#define SMEM_64x64 (2 * 32768)
#define MT64 13                        /* ceil(824/64) M tiles for mamba */

extern "C" void kernel_launch(void* const* d_in, const int* in_sizes, int n_in,
                              void* d_out, int out_size) {
    (void)in_sizes; (void)n_in;
    const float* nb     = (const float*)d_in[0];
    const float* center = (const float*)d_in[1];
    const unsigned char* mask = (const unsigned char*)d_in[2];
    const float* c1w = (const float*)d_in[3];
    const float* c1b = (const float*)d_in[4];
    const float* bng = (const float*)d_in[5];
    const float* bnb = (const float*)d_in[6];
    const float* bnm = (const float*)d_in[7];
    const float* bnv = (const float*)d_in[8];
    const float* c2w = (const float*)d_in[9];
    const float* c2b = (const float*)d_in[10];
    const float* pw1 = (const float*)d_in[11];
    const float* pb1 = (const float*)d_in[12];
    const float* pw2 = (const float*)d_in[13];
    const float* pb2 = (const float*)d_in[14];
    const float* ipw = (const float*)d_in[15];
    const float* cw  = (const float*)d_in[16];
    const float* cb  = (const float*)d_in[17];
    const float* xpw = (const float*)d_in[18];
    const float* dpw = (const float*)d_in[19];
    const float* dpb = (const float*)d_in[20];
    const float* alog= (const float*)d_in[21];
    const float* Dp  = (const float*)d_in[22];
    const float* opw = (const float*)d_in[23];
    const float* lnw = (const float*)d_in[24];
    const float* lnb = (const float*)d_in[25];
    const float* nfw = (const float*)d_in[26];
    const float* nfb = (const float*)d_in[27];
    const float* n2w = (const float*)d_in[28];
    const float* n2b = (const float*)d_in[29];
    float* out = (float*)d_out;

    cudaFuncSetAttribute(k_mma<1, 128, 128>, cudaFuncAttributeMaxDynamicSharedMemorySize, SMEM_128);
    cudaFuncSetAttribute(k_mma<2, 128, 128>, cudaFuncAttributeMaxDynamicSharedMemorySize, SMEM_128);
    cudaFuncSetAttribute(k_mma<0, 64, 128>,  cudaFuncAttributeMaxDynamicSharedMemorySize, SMEM_64x128);
    cudaFuncSetAttribute(k_mma<0, 64, 64>,   cudaFuncAttributeMaxDynamicSharedMemorySize, SMEM_64x64);
    cudaFuncSetAttribute(k_mma<3, 64, 64>,   cudaFuncAttributeMaxDynamicSharedMemorySize, SMEM_64x64);

    float *be, *tok, *xz, *xi, *dtb, *bc, *hb;
    cudaGetSymbolAddress((void**)&be,  g_biaseff);
    cudaGetSymbolAddress((void**)&tok, g_tokens);
    cudaGetSymbolAddress((void**)&xz,  g_xz);
    cudaGetSymbolAddress((void**)&xi,  g_xi);
    cudaGetSymbolAddress((void**)&dtb, g_dt);
    cudaGetSymbolAddress((void**)&bc,  g_bc);
    cudaGetSymbolAddress((void**)&hb,  g_h);
    __nv_bfloat16 *fgh, *fgl, *w0h, *w0l, *nbh, *nbl, *w1h, *w1l, *w2h, *w2l, *h1h, *h1l;
    __nv_bfloat16 *ipwh, *ipwl, *wch, *wcl, *opwh, *opwl;
    __nv_bfloat16 *hnh, *hnl, *xih, *xil, *uh, *ul;
    cudaGetSymbolAddress((void**)&fgh, g_fgh);  cudaGetSymbolAddress((void**)&fgl, g_fgl);
    cudaGetSymbolAddress((void**)&w0h, g_w0h);  cudaGetSymbolAddress((void**)&w0l, g_w0l);
    cudaGetSymbolAddress((void**)&nbh, g_nbh);  cudaGetSymbolAddress((void**)&nbl, g_nbl);
    cudaGetSymbolAddress((void**)&w1h, g_w1h);  cudaGetSymbolAddress((void**)&w1l, g_w1l);
    cudaGetSymbolAddress((void**)&w2h, g_w2h);  cudaGetSymbolAddress((void**)&w2l, g_w2l);
    cudaGetSymbolAddress((void**)&h1h, g_h1h);  cudaGetSymbolAddress((void**)&h1l, g_h1l);
    cudaGetSymbolAddress((void**)&ipwh, g_ipwh); cudaGetSymbolAddress((void**)&ipwl, g_ipwl);
    cudaGetSymbolAddress((void**)&wch, g_wch);  cudaGetSymbolAddress((void**)&wcl, g_wcl);
    cudaGetSymbolAddress((void**)&opwh, g_opwh); cudaGetSymbolAddress((void**)&opwl, g_opwl);
    cudaGetSymbolAddress((void**)&hnh, g_hnh);  cudaGetSymbolAddress((void**)&hnl, g_hnl);
    cudaGetSymbolAddress((void**)&xih, g_xih);  cudaGetSymbolAddress((void**)&xil, g_xil);
    cudaGetSymbolAddress((void**)&uh,  g_uh);   cudaGetSymbolAddress((void**)&ul,  g_ul);

    /* -------- weight & input split prepasses -------- */
    auto splitN = [](long long total) { return (int)((total + 255) / 256); };
    long long tNB = (long long)NCOL * K1P;
    k_split<<<splitN(tNB), 256>>>(nb, FEAT, 0, NCOL, FEAT, nbh, nbl, K1P, tNB);
    long long tW1 = (long long)M1P * K1P;
    k_split<<<splitN(tW1), 256>>>(c1w, 2 * FEAT, 0, CH, FEAT, w0h, w0l, K1P, tW1);
    k_split<<<splitN(tW1), 256>>>(c1w, 2 * FEAT, FEAT, CH, FEAT, w1h, w1l, K1P, tW1);
    long long tW2 = (long long)ENCD * K2P;
    k_split<<<splitN(tW2), 256>>>(c2w, CH, 0, ENCD, CH, w2h, w2l, K2P, tW2);
    long long tIP = (long long)DEPTH * 2 * DIN * DDIM;
    k_split<<<splitN(tIP), 256>>>(ipw, DDIM, 0, DEPTH * 2 * DIN, DDIM, ipwh, ipwl, DDIM, tIP);
    long long tOP = (long long)DEPTH * DDIM * DIN;
    k_split<<<splitN(tOP), 256>>>(opw, DIN, 0, DEPTH * DDIM, DIN, opwh, opwl, DIN, tOP);
    k_wcomb<<<splitN((long long)DEPTH * NXPP * DIN), 256>>>(dpw, xpw);
    k_h1pad<<<NCOL / 8, 256>>>();

    /* -------- encoder -------- */
    k_fg<<<BGC, 256>>>(nb);
    /* bias-eff: be[546,2048] = c1w[:, :273] @ fg^T */
    k_mma<0, 64, 128><<<dim3(M1P / 64, BGC / 128), 256, SMEM_64x128>>>(
        w0h, w0l, K1P, fgh, fgl, K1P, K1P / 64,
        nullptr, nullptr, nullptr, nullptr, nullptr,
        be, BGC, nullptr, nullptr, nullptr, CH, BGC);
    /* GEMM1: D[640,65536] -> H1T split (staged coalesced epilogue) */
    k_mma<1, 128, 128><<<dim3(M1P / 128, NCOL / 128), 256, SMEM_128>>>(
        w1h, w1l, K1P, nbh, nbl, K1P, K1P / 64,
        be, bnm, bnv, bng, bnb, nullptr, 0, nullptr, h1h, h1l, CH, NCOL);
    /* GEMM2: D[384,65536] -> tokens (fused maxpool) */
    k_mma<2, 128, 128><<<dim3(ENCD / 128, NCOL / 128), 256, SMEM_128>>>(
        w2h, w2l, K2P, h1h, h1l, K2P, K2P / 64,
        c2b, nullptr, nullptr, nullptr, nullptr, tok, 0, nullptr, nullptr, nullptr, ENCD, NCOL);

    /* -------- gather + pos embed -------- */
    k_visidx<<<BB, 32>>>(mask);
    k_pos<<<BL, 128>>>(center, pw1, pb1, pw2, pb2);

    /* -------- mamba stack -------- */
    for (int i = 0; i < DEPTH; i++) {
        k_lnres<<<BL, 128>>>(i, lnw + (size_t)i * DDIM, lnb + (size_t)i * DDIM);
        /* in_proj: xz[824,1536] = hn @ ipw^T  (64x128 tiles, 156 CTAs) */
        k_mma<0, 64, 128><<<dim3(MT64, 2 * DIN / 128), 256, SMEM_64x128>>>(
            hnh, hnl, DDIM, ipwh + (size_t)i * 2 * DIN * DDIM, ipwl + (size_t)i * 2 * DIN * DDIM, DDIM,
            DDIM / 64, nullptr, nullptr, nullptr, nullptr, nullptr,
            xz, 2 * DIN, nullptr, nullptr, nullptr, BL, 2 * DIN);
        k_conv<<<(BL * DIN + 255) / 256, 256>>>(cw + (size_t)i * DIN * DCONV, cb + (size_t)i * DIN);
        /* merged x_proj+dt_proj (64x64 tiles, 182 CTAs) */
        k_mma<3, 64, 64><<<dim3(MT64, NXPP / 64), 256, SMEM_64x64>>>(
            xih, xil, DIN, wch + (size_t)i * NXPP * DIN, wcl + (size_t)i * NXPP * DIN, DIN,
            DIN / 64, dpb + (size_t)i * DIN, nullptr, nullptr, nullptr, nullptr,
            dtb, DIN, bc, nullptr, nullptr, BL, NXP);
        k_scan<<<BB * 6, 128>>>(alog + (size_t)i * DIN * DSN, Dp + (size_t)i * DIN);
        /* out_proj (64x64 tiles, 78 CTAs) */
        k_mma<0, 64, 64><<<dim3(MT64, DDIM / 64), 256, SMEM_64x64>>>(
            uh, ul, DIN, opwh + (size_t)i * DDIM * DIN, opwl + (size_t)i * DDIM * DIN, DIN,
            DIN / 64, nullptr, nullptr, nullptr, nullptr, nullptr,
            hb, DDIM, nullptr, nullptr, nullptr, BL, DDIM);
    }

    /* -------- final norms + outputs -------- */
    k_final<<<BL, 128>>>(out, nfw, nfb, n2w, n2b);
    k_maskout<<<1, 256>>>(mask, out, out_size);
}

// round 7
// speedup vs baseline: 2.8405x; 1.0108x over previous
#include <cuda_runtime.h>
#include <cuda_bf16.h>
#include <math.h>
#include <stdint.h>

#define BB 8
#define GG 256
#define NPTS 32
#define FEAT 273
#define CH 546
#define ENCD 384
#define DDIM 384
#define DEPTH 12
#define DIN 768
#define DSN 16
#define DCONV 4
#define DTR 24
#define GVIS 103
#define SEQL 103
#define BL (BB*GVIS)        /* 824 rows */
#define BLP 896             /* buffer pad */
#define BGC (BB*GG)         /* 2048 groups */
#define NCOL (BGC*NPTS)     /* 65536 point columns */
#define NMASK 153
#define OUTH (BL*DDIM)      /* 316416 */
#define NXP (DIN + 2*DSN)   /* 800 */
#define NXPP 896            /* padded */
#define K1P 320             /* FEAT 273 -> padded */
#define M1P 640             /* CH 546 -> padded  */
#define K2P 576             /* CH 546 -> padded  */
#define EPSV 1e-5f

/* ------------------------- scratch (device globals) ------------------------ */
__device__ float g_biaseff[(size_t)CH * BGC];
__device__ float g_tokens[(size_t)BGC * ENCD];
__device__ int   g_vis[BL];
__device__ float g_h[BL * DDIM];
__device__ float g_res[BL * DDIM];
__device__ float g_xz[BL * 2 * DIN];
__device__ float g_xi[BL * DIN];
__device__ float g_dt[BL * DIN];
__device__ float g_bc[BL * 2 * DSN];

/* bf16-split operand buffers */
__device__ __align__(256) __nv_bfloat16 g_fgh[(size_t)BGC * K1P];
__device__ __align__(256) __nv_bfloat16 g_fgl[(size_t)BGC * K1P];
__device__ __align__(256) __nv_bfloat16 g_w0h[(size_t)M1P * K1P];
__device__ __align__(256) __nv_bfloat16 g_w0l[(size_t)M1P * K1P];
__device__ __align__(256) __nv_bfloat16 g_nbh[(size_t)NCOL * K1P];
__device__ __align__(256) __nv_bfloat16 g_nbl[(size_t)NCOL * K1P];
__device__ __align__(256) __nv_bfloat16 g_w1h[(size_t)M1P * K1P];
__device__ __align__(256) __nv_bfloat16 g_w1l[(size_t)M1P * K1P];
__device__ __align__(256) __nv_bfloat16 g_w2h[(size_t)ENCD * K2P];
__device__ __align__(256) __nv_bfloat16 g_w2l[(size_t)ENCD * K2P];
__device__ __align__(256) __nv_bfloat16 g_h1h[(size_t)NCOL * K2P];
__device__ __align__(256) __nv_bfloat16 g_h1l[(size_t)NCOL * K2P];
__device__ __align__(256) __nv_bfloat16 g_ipwh[(size_t)DEPTH * 2 * DIN * DDIM];
__device__ __align__(256) __nv_bfloat16 g_ipwl[(size_t)DEPTH * 2 * DIN * DDIM];
__device__ __align__(256) __nv_bfloat16 g_wch[(size_t)DEPTH * NXPP * DIN];
__device__ __align__(256) __nv_bfloat16 g_wcl[(size_t)DEPTH * NXPP * DIN];
__device__ __align__(256) __nv_bfloat16 g_opwh[(size_t)DEPTH * DDIM * DIN];
__device__ __align__(256) __nv_bfloat16 g_opwl[(size_t)DEPTH * DDIM * DIN];
__device__ __align__(256) __nv_bfloat16 g_hnh[(size_t)BLP * DDIM];
__device__ __align__(256) __nv_bfloat16 g_hnl[(size_t)BLP * DDIM];
__device__ __align__(256) __nv_bfloat16 g_xih[(size_t)BLP * DIN];
__device__ __align__(256) __nv_bfloat16 g_xil[(size_t)BLP * DIN];
__device__ __align__(256) __nv_bfloat16 g_uh[(size_t)BLP * DIN];
__device__ __align__(256) __nv_bfloat16 g_ul[(size_t)BLP * DIN];

/* ------------------------------ small helpers ----------------------------- */
__device__ __forceinline__ float siluf(float x) { return x / (1.f + expf(-x)); }
__device__ __forceinline__ float geluf(float x) { return 0.5f * x * (1.f + erff(x * 0.70710678118654752f)); }
__device__ __forceinline__ float softplusf(float x) { return (x > 20.f) ? x : log1pf(expf(x)); }
__device__ __forceinline__ void split2(float v, __nv_bfloat16* h, __nv_bfloat16* l) {
    __nv_bfloat16 hh = __float2bfloat16(v);
    *h = hh;
    *l = __float2bfloat16(v - __bfloat162float(hh));
}

__device__ __forceinline__ void reduce2_128(float& s1, float& s2) {
    #pragma unroll
    for (int o = 16; o; o >>= 1) {
        s1 += __shfl_xor_sync(0xffffffffu, s1, o);
        s2 += __shfl_xor_sync(0xffffffffu, s2, o);
    }
    __shared__ float ra[4], rb[4];
    int w = threadIdx.x >> 5, l = threadIdx.x & 31;
    if (l == 0) { ra[w] = s1; rb[w] = s2; }
    __syncthreads();
    s1 = ra[0] + ra[1] + ra[2] + ra[3];
    s2 = rb[0] + rb[1] + rb[2] + rb[3];
    __syncthreads();
}

/* --------------------------- PTX wrappers --------------------------------- */
__device__ __forceinline__ uint32_t smem_u32(const void* p) {
    uint32_t a;
    asm("{ .reg .u64 t; cvta.to.shared.u64 t, %1; cvt.u32.u64 %0, t; }" : "=r"(a) : "l"(p));
    return a;
}
#define SWZ128(o) ((o) ^ (((o) >> 3) & 0x70))
#define CP_ASYNC16(d, s) asm volatile("cp.async.cg.shared.global [%0], [%1], 16;" :: "r"(d), "l"(s))
#define CP_COMMIT()      asm volatile("cp.async.commit_group;" ::: "memory")
#define CP_WAIT1()       asm volatile("cp.async.wait_group 1;" ::: "memory")
#define CP_WAIT0()       asm volatile("cp.async.wait_group 0;" ::: "memory")

__device__ __forceinline__ void ldm_x4(uint32_t* r, uint32_t addr) {
    asm volatile("ldmatrix.sync.aligned.m8n8.x4.shared.b16 {%0,%1,%2,%3}, [%4];"
        : "=r"(r[0]), "=r"(r[1]), "=r"(r[2]), "=r"(r[3]) : "r"(addr));
}
__device__ __forceinline__ void mma16816(float* c, const uint32_t* a, uint32_t b0, uint32_t b1) {
    asm volatile("mma.sync.aligned.m16n8k16.row.col.f32.bf16.bf16.f32 "
        "{%0,%1,%2,%3}, {%4,%5,%6,%7}, {%8,%9}, {%0,%1,%2,%3};"
        : "+f"(c[0]), "+f"(c[1]), "+f"(c[2]), "+f"(c[3])
        : "r"(a[0]), "r"(a[1]), "r"(a[2]), "r"(a[3]), "r"(b0), "r"(b1));
}

/* =================== generic bf16-split mma.sync GEMM ======================
 * D[M,N] = A[M,K] * B[N,K]^T  (h/l split bf16, K-major, ld = Kpad)
 * grid = (Mtiles, Ntiles) -- M fastest so consecutive CTAs share the B tile.
 * NW warps (8: 2x4 grid, 16: 4x4 grid). CTA tile TM x TN (template).
 * Split: D = AhBh + AhBl + AlBh (fp32 accumulate).
 * EPI 0: C[m*ldc+n] = v               (m<Mv, n<Nv)
 * EPI 1: v+=be[m*BGC+grp]; BN+relu; split -> O1/O2[n*K2P+m] (staged, m<CH)
 * EPI 2: group maxpool + p0[m] -> C[grp*ENCD+m]  (tokens; TN=128 only)
 * EPI 3: n<DIN: C[m*DIN+n]=softplus(v+p0[n]); n<NXP: C2[m*32+n-DIN]=v (m<Mv)
 * ========================================================================= */
template<int EPI, int TM, int TN, int NW>
__global__ __launch_bounds__(NW * 32) void k_mma(
    const __nv_bfloat16* __restrict__ Ah, const __nv_bfloat16* __restrict__ Al, int lda,
    const __nv_bfloat16* __restrict__ Bh, const __nv_bfloat16* __restrict__ Bl, int ldb,
    int NKC,
    const float* __restrict__ p0, const float* __restrict__ p1,
    const float* __restrict__ p2, const float* __restrict__ p3,
    const float* __restrict__ p4,
    float* __restrict__ C, int ldc, float* __restrict__ C2,
    __nv_bfloat16* __restrict__ O1, __nv_bfloat16* __restrict__ O2,
    int Mv, int Nv)
{
    constexpr int THREADS = NW * 32;
    constexpr int WR = NW / 4;           /* warp rows (2 or 4)        */
    constexpr int WC = 4;                /* warp cols                 */
    constexpr int WM = TM / WR;          /* per-warp m extent         */
    constexpr int WN = TN / WC;          /* per-warp n extent         */
    constexpr int MI = WM / 16;          /* 16-row frags per warp     */
    constexpr int NJ = WN / 8;           /* 8-col frags per warp      */
    constexpr int NB2 = (NJ + 1) / 2;    /* b ldmatrix calls          */
    constexpr int LA = TM * 8 / THREADS; /* A 16B-loads per thread    */
    constexpr int LB = TN * 8 / THREADS;
    constexpr uint32_t ABY = TM * 128;   /* one A tile bytes          */
    constexpr uint32_t BBY = TN * 128;
    constexpr uint32_t BUFSZ = 2 * ABY + 2 * BBY;

    extern __shared__ __align__(1024) char smem[];
    const uint32_t sb = smem_u32(smem);
    const int tid = threadIdx.x, wid = tid >> 5, lid = tid & 31;
    const int wrow = wid >> 2, wcol = wid & 3;
    const int quad = lid >> 2, tq = lid & 3;
    const int m0 = blockIdx.x * TM, n0 = blockIdx.y * TN;

    const int lrow = (lid & 7) + 8 * ((lid >> 3) & 1);
    const int lk   = 8 * (lid >> 4);

    float acc[MI][NJ][4];
    #pragma unroll
    for (int i = 0; i < MI; i++)
        #pragma unroll
        for (int j = 0; j < NJ; j++)
            #pragma unroll
            for (int k = 0; k < 4; k++) acc[i][j][k] = 0.f;

    auto loadChunk = [&](int kc, int c) {
        const uint32_t bufb = sb + c * BUFSZ;
        #pragma unroll
        for (int p = 0; p < LA; p++) {
            int idx = tid + p * THREADS;
            int row = idx >> 3, c16 = idx & 7;
            uint32_t sw = SWZ128((uint32_t)(row * 128 + c16 * 16));
            const void* gh = Ah + (size_t)(m0 + row) * lda + kc * 64 + c16 * 8;
            const void* gl = Al + (size_t)(m0 + row) * lda + kc * 64 + c16 * 8;
            CP_ASYNC16(bufb + sw, gh);
            CP_ASYNC16(bufb + ABY + sw, gl);
        }
        #pragma unroll
        for (int p = 0; p < LB; p++) {
            int idx = tid + p * THREADS;
            int row = idx >> 3, c16 = idx & 7;
            uint32_t sw = SWZ128((uint32_t)(row * 128 + c16 * 16));
            const void* gh = Bh + (size_t)(n0 + row) * ldb + kc * 64 + c16 * 8;
            const void* gl = Bl + (size_t)(n0 + row) * ldb + kc * 64 + c16 * 8;
            CP_ASYNC16(bufb + 2 * ABY + sw, gh);
            CP_ASYNC16(bufb + 2 * ABY + BBY + sw, gl);
        }
        CP_COMMIT();
    };

    loadChunk(0, 0);
    if (NKC > 1) loadChunk(1, 1); else CP_COMMIT();

    for (int kc = 0; kc < NKC; kc++) {
        const int c = kc & 1;
        if (kc + 1 < NKC) CP_WAIT1(); else CP_WAIT0();
        __syncthreads();
        const uint32_t ahb = sb + c * BUFSZ;
        const uint32_t alb = ahb + ABY;
        const uint32_t bhb = ahb + 2 * ABY;
        const uint32_t blb = bhb + BBY;
        #pragma unroll
        for (int ks = 0; ks < 4; ks++) {
            const int k0 = ks * 16 + lk;
            uint32_t fah[MI][4], fal[MI][4], fbh[NB2][4], fbl[NB2][4];
            #pragma unroll
            for (int bi = 0; bi < MI; bi++) {
                int r = wrow * WM + bi * 16 + lrow;
                ldm_x4(fah[bi], ahb + SWZ128((uint32_t)(r * 128 + k0 * 2)));
                ldm_x4(fal[bi], alb + SWZ128((uint32_t)(r * 128 + k0 * 2)));
            }
            #pragma unroll
            for (int bj2 = 0; bj2 < NB2; bj2++) {
                int r = wcol * WN + bj2 * 16 + lrow;
                ldm_x4(fbh[bj2], bhb + SWZ128((uint32_t)(r * 128 + k0 * 2)));
                ldm_x4(fbl[bj2], blb + SWZ128((uint32_t)(r * 128 + k0 * 2)));
            }
            #pragma unroll
            for (int bi = 0; bi < MI; bi++) {
                #pragma unroll
                for (int bj = 0; bj < NJ; bj++) {
                    uint32_t bh0 = fbh[bj >> 1][bj & 1], bh1 = fbh[bj >> 1][2 + (bj & 1)];
                    uint32_t bl0 = fbl[bj >> 1][bj & 1], bl1 = fbl[bj >> 1][2 + (bj & 1)];
                    mma16816(acc[bi][bj], fah[bi], bh0, bh1);
                    mma16816(acc[bi][bj], fah[bi], bl0, bl1);
                    mma16816(acc[bi][bj], fal[bi], bh0, bh1);
                }
            }
        }
        __syncthreads();
        if (kc + 2 < NKC) loadChunk(kc + 2, c);
    }

    const int grp = (n0 >> 5) + wcol;  /* point-group (TN=128, WN=32) */

    if (EPI == 1) {
        /* staged transposed split store (TM=TN=128 only) */
        const int LDE = 136;
        __nv_bfloat16* sh = (__nv_bfloat16*)smem;
        __nv_bfloat16* sl = (__nv_bfloat16*)(smem + 128 * LDE * 2);
        const int mlim = (CH - m0 < 128) ? (CH - m0) : 128;
        #pragma unroll
        for (int bi = 0; bi < MI; bi++) {
            #pragma unroll
            for (int h0 = 0; h0 < 2; h0++) {
                const int ml = wrow * WM + bi * 16 + quad + 8 * h0;
                const int m = m0 + ml;
                if (m < CH) {
                    const float be = p0[(size_t)m * BGC + grp];
                    const float bnm = p1[m];
                    const float sc  = rsqrtf(p2[m] + EPSV) * p3[m];
                    const float bb  = p4[m];
                    #pragma unroll
                    for (int bj = 0; bj < NJ; bj++) {
                        #pragma unroll
                        for (int e = 0; e < 2; e++) {
                            int nl = wcol * WN + bj * 8 + 2 * tq + e;
                            float v = acc[bi][bj][h0 * 2 + e] + be;
                            v = fmaxf((v - bnm) * sc + bb, 0.f);
                            split2(v, &sh[nl * LDE + ml], &sl[nl * LDE + ml]);
                        }
                    }
                }
            }
        }
        __syncthreads();
        for (int idx = tid; idx < 128 * 16; idx += THREADS) {
            int nl = idx >> 4, ch = idx & 15;
            int mbeg = ch * 8;
            if (mbeg < mlim) {
                size_t gbase = (size_t)(n0 + nl) * K2P + m0 + mbeg;
                if (mbeg + 8 <= mlim) {
                    *(uint4*)(&O1[gbase]) = *(const uint4*)(&sh[nl * LDE + mbeg]);
                    *(uint4*)(&O2[gbase]) = *(const uint4*)(&sl[nl * LDE + mbeg]);
                } else {
                    for (int t = 0; t < mlim - mbeg; t++) {
                        O1[gbase + t] = sh[nl * LDE + mbeg + t];
                        O2[gbase + t] = sl[nl * LDE + mbeg + t];
                    }
                }
            }
        }
        return;
    }

    #pragma unroll
    for (int bi = 0; bi < MI; bi++) {
        #pragma unroll
        for (int h0 = 0; h0 < 2; h0++) {
            const int m = m0 + wrow * WM + bi * 16 + quad + 8 * h0;
            if (EPI == 2) {
                float vm = -INFINITY;
                #pragma unroll
                for (int bj = 0; bj < NJ; bj++) {
                    vm = fmaxf(vm, acc[bi][bj][h0 * 2]);
                    vm = fmaxf(vm, acc[bi][bj][h0 * 2 + 1]);
                }
                vm = fmaxf(vm, __shfl_xor_sync(0xffffffffu, vm, 1));
                vm = fmaxf(vm, __shfl_xor_sync(0xffffffffu, vm, 2));
                if (tq == 0) C[(size_t)grp * ENCD + m] = vm + p0[m];
            } else if (EPI == 0) {
                if (m < Mv) {
                    #pragma unroll
                    for (int bj = 0; bj < NJ; bj++) {
                        #pragma unroll
                        for (int e = 0; e < 2; e++) {
                            int n = n0 + wcol * WN + bj * 8 + 2 * tq + e;
                            if (n < Nv) C[(size_t)m * ldc + n] = acc[bi][bj][h0 * 2 + e];
                        }
                    }
                }
            } else { /* EPI 3 */
                if (m < Mv) {
                    #pragma unroll
                    for (int bj = 0; bj < NJ; bj++) {
                        #pragma unroll
                        for (int e = 0; e < 2; e++) {
                            int n = n0 + wcol * WN + bj * 8 + 2 * tq + e;
                            float v = acc[bi][bj][h0 * 2 + e];
                            if (n < DIN) C[(size_t)m * DIN + n] = softplusf(v + p0[n]);
                            else if (n < NXP) C2[(size_t)m * (2 * DSN) + (n - DIN)] = v;
                        }
                    }
                }
            }
        }
    }
}

/* --------------------------- split prepass kernels ------------------------- */
__global__ void k_split(const float* __restrict__ src, int sld, int soff,
                        int R, int K, __nv_bfloat16* __restrict__ dh,
                        __nv_bfloat16* __restrict__ dl, int Kp, long long total) {
    long long i = (long long)blockIdx.x * 256 + threadIdx.x;
    if (i >= total) return;
    int k = (int)(i % Kp);
    long long r = i / Kp;
    float v = (r < R && k < K) ? src[r * sld + soff + k] : 0.f;
    split2(v, &dh[i], &dl[i]);
}

__global__ void k_wcomb(const float* __restrict__ dpw, const float* __restrict__ xpw) {
    long long idx = (long long)blockIdx.x * 256 + threadIdx.x;
    if (idx >= (long long)DEPTH * NXPP * DIN) return;
    int col = (int)(idx % DIN);
    int rem = (int)(idx / DIN);
    int row = rem % NXPP;
    int l   = rem / NXPP;
    const float* xp = xpw + (size_t)l * (DTR + 2 * DSN) * DIN;
    float v = 0.f;
    if (row < DIN) {
        const float* dr = dpw + (size_t)l * DIN * DTR + (size_t)row * DTR;
        #pragma unroll
        for (int t = 0; t < DTR; t++) v = fmaf(dr[t], xp[(size_t)t * DIN + col], v);
    } else if (row < NXP) {
        v = xp[(size_t)(DTR + (row - DIN)) * DIN + col];
    }
    split2(v, &g_wch[idx], &g_wcl[idx]);
}

__global__ void k_h1pad() {
    int n = blockIdx.x * 8 + (threadIdx.x >> 5);
    int j = threadIdx.x & 31;
    if (j < (K2P - CH)) {
        g_h1h[(size_t)n * K2P + CH + j] = __float2bfloat16(0.f);
        g_h1l[(size_t)n * K2P + CH + j] = __float2bfloat16(0.f);
    }
}

/* ---------- encoder: per-group feature max -> split bf16 [bg][K1P] --------- */
__global__ void k_fg(const float* __restrict__ nb) {
    __shared__ float s[NPTS * FEAT];
    int bg = blockIdx.x;
    const float* src = nb + (size_t)bg * NPTS * FEAT;
    for (int t = threadIdx.x; t < NPTS * FEAT; t += blockDim.x) s[t] = src[t];
    __syncthreads();
    for (int c = threadIdx.x; c < K1P; c += blockDim.x) {
        float m = 0.f;
        if (c < FEAT) {
            m = s[c];
            #pragma unroll
            for (int n = 1; n < NPTS; n++) m = fmaxf(m, s[n * FEAT + c]);
        }
        split2(m, &g_fgh[(size_t)bg * K1P + c], &g_fgl[(size_t)bg * K1P + c]);
    }
}

/* ---------------- visible-index extraction (bool width-robust) ------------ */
__global__ void k_visidx(const unsigned char* __restrict__ m8) {
    if (threadIdx.x != 0) return;
    int b = blockIdx.x;
    int c8 = 0;
    for (int g = 0; g < GG; g++) c8 += (m8[(size_t)b * GG + g] != 0);
    int cnt = 0;
    if (c8 == NMASK) {
        for (int g = 0; g < GG; g++)
            if (!m8[(size_t)b * GG + g]) { if (cnt < GVIS) g_vis[b * GVIS + cnt] = g; cnt++; }
    } else {
        const int* m32 = (const int*)m8;
        for (int g = 0; g < GG; g++)
            if (!m32[(size_t)b * GG + g]) { if (cnt < GVIS) g_vis[b * GVIS + cnt] = g; cnt++; }
    }
}

/* ------------- gather tokens/centers + pos MLP -> initial h ---------------- */
__global__ void k_pos(const float* __restrict__ center,
                      const float* __restrict__ w1, const float* __restrict__ b1,
                      const float* __restrict__ w2, const float* __restrict__ b2) {
    __shared__ float hcache[128];
    __shared__ float cc[3];
    int r = blockIdx.x;
    int b = r / GVIS;
    int g = g_vis[r];
    int tid = threadIdx.x;
    if (tid < 3) cc[tid] = center[((size_t)b * GG + g) * 3 + tid];
    __syncthreads();
    float a = w1[tid * 3] * cc[0] + w1[tid * 3 + 1] * cc[1] + w1[tid * 3 + 2] * cc[2] + b1[tid];
    hcache[tid] = geluf(a);
    __syncthreads();
    const float* tok = g_tokens + ((size_t)b * GG + g) * ENCD;
    for (int e = tid; e < DDIM; e += 128) {
        float acc = b2[e];
        const float* wr = w2 + (size_t)e * 128;
        #pragma unroll 8
        for (int k = 0; k < 128; k++) acc = fmaf(wr[k], hcache[k], acc);
        g_h[(size_t)r * DDIM + e] = acc + tok[e];
    }
}

/* ------------- residual accumulate + LayerNorm -> split bf16 --------------- */
__global__ void k_lnres(int layer, const float* __restrict__ w, const float* __restrict__ b) {
    int r = blockIdx.x, tid = threadIdx.x;
    float* res = g_res + (size_t)r * DDIM;
    const float* h = g_h + (size_t)r * DDIM;
    float v[3], s1 = 0.f, s2 = 0.f;
    #pragma unroll
    for (int i = 0; i < 3; i++) {
        int c = tid + i * 128;
        float x = h[c];
        if (layer > 0) x += res[c];
        v[i] = x; res[c] = x;
        s1 += x; s2 += x * x;
    }
    reduce2_128(s1, s2);
    float mu = s1 * (1.f / DDIM);
    float rstd = rsqrtf(s2 * (1.f / DDIM) - mu * mu + EPSV);
    #pragma unroll
    for (int i = 0; i < 3; i++) {
        int c = tid + i * 128;
        float y = (v[i] - mu) * rstd * w[c] + b[c];
        split2(y, &g_hnh[(size_t)r * DDIM + c], &g_hnl[(size_t)r * DDIM + c]);
    }
}

/* ---------------- depthwise causal conv (k=4) + SiLU -> split -------------- */
__global__ void k_conv(const float* __restrict__ cw, const float* __restrict__ cb) {
    int idx = blockIdx.x * blockDim.x + threadIdx.x;
    if (idx >= BL * DIN) return;
    int d = idx % DIN, r = idx / DIN;
    int b = r / SEQL, l = r % SEQL;
    float acc = cb[d];
    #pragma unroll
    for (int k = 0; k < DCONV; k++) {
        int ll = l - (DCONV - 1) + k;
        if (ll >= 0) acc = fmaf(cw[d * DCONV + k], g_xz[((size_t)(b * SEQL + ll)) * (2 * DIN) + d], acc);
    }
    float y = siluf(acc);
    g_xi[idx] = y;
    split2(y, &g_xih[idx], &g_xil[idx]);
}

/* --------------------------- selective scan -> split ------------------------ */
__global__ void k_scan(const float* __restrict__ alog, const float* __restrict__ Dp) {
    int b = blockIdx.x / 6;
    int d = (blockIdx.x % 6) * 128 + threadIdx.x;
    float A[DSN];
    #pragma unroll
    for (int s = 0; s < DSN; s++) A[s] = -expf(alog[(size_t)d * DSN + s]);
    float Dd = Dp[d];
    float h[DSN];
    #pragma unroll
    for (int s = 0; s < DSN; s++) h[s] = 0.f;
    for (int l = 0; l < SEQL; l++) {
        int r = b * SEQL + l;
        float dt = g_dt[(size_t)r * DIN + d];
        float x  = g_xi[(size_t)r * DIN + d];
        float dtx = dt * x;
        const float* bl = g_bc + (size_t)r * (2 * DSN);
        float y = 0.f;
        #pragma unroll
        for (int s = 0; s < DSN; s++) {
            float dA = __expf(dt * A[s]);
            h[s] = fmaf(dA, h[s], dtx * bl[s]);
            y = fmaf(h[s], bl[DSN + s], y);
        }
        float z = g_xz[(size_t)r * (2 * DIN) + DIN + d];
        float u = (y + x * Dd) * siluf(z);
        split2(u, &g_uh[(size_t)r * DIN + d], &g_ul[(size_t)r * DIN + d]);
    }
}

/* ----------------------- final residual + double LN ------------------------ */
__global__ void k_final(float* __restrict__ out,
                        const float* __restrict__ w1, const float* __restrict__ b1,
                        const float* __restrict__ w2, const float* __restrict__ b2) {
    int r = blockIdx.x, tid = threadIdx.x;
    float v[3], s1 = 0.f, s2 = 0.f;
    #pragma unroll
    for (int i = 0; i < 3; i++) {
        int c = tid + i * 128;
        float x = g_res[(size_t)r * DDIM + c] + g_h[(size_t)r * DDIM + c];
        v[i] = x; s1 += x; s2 += x * x;
    }
    reduce2_128(s1, s2);
    float mu = s1 * (1.f / DDIM);
    float rstd = rsqrtf(s2 * (1.f / DDIM) - mu * mu + EPSV);
    s1 = 0.f; s2 = 0.f;
    #pragma unroll
    for (int i = 0; i < 3; i++) {
        int c = tid + i * 128;
        v[i] = (v[i] - mu) * rstd * w1[c] + b1[c];
        s1 += v[i]; s2 += v[i] * v[i];
    }
    reduce2_128(s1, s2);
    mu = s1 * (1.f / DDIM);
    rstd = rsqrtf(s2 * (1.f / DDIM) - mu * mu + EPSV);
    #pragma unroll
    for (int i = 0; i < 3; i++) {
        int c = tid + i * 128;
        out[(size_t)r * DDIM + c] = (v[i] - mu) * rstd * w2[c] + b2[c];
    }
}

/* -------------------------- mask -> output tail ---------------------------- */
__global__ void k_maskout(const unsigned char* __restrict__ m8, float* __restrict__ out, int out_size) {
    if (out_size < OUTH + BB * GG) return;
    __shared__ int use8;
    if (threadIdx.x == 0) {
        int c = 0;
        for (int g = 0; g < GG; g++) c += (m8[g] != 0);
        use8 = (c == NMASK);
    }
    __syncthreads();
    const int* m32 = (const int*)m8;
    for (int i = threadIdx.x; i < BB * GG; i += blockDim.x) {
        float v = use8 ? (m8[i] ? 1.f : 0.f) : (m32[i] ? 1.f : 0.f);
        out[OUTH + i] = v;
    }
}

/* ------------------------------- host driver ------------------------------- */
#define SMEM_128 (2 * 65536)          /* 128x128 double buffer */
#define SMEM_64x128 (2 * 49152)
#define SMEM_64x64 (2 * 32768)
#define MT64 13                        /* ceil(824/64) M tiles for mamba */

extern "C" void kernel_launch(void* const* d_in, const int* in_sizes, int n_in,
                              void* d_out, int out_size) {
    (void)in_sizes; (void)n_in;
    const float* nb     = (const float*)d_in[0];
    const float* center = (const float*)d_in[1];
    const unsigned char* mask = (const unsigned char*)d_in[2];
    const float* c1w = (const float*)d_in[3];
    const float* c1b = (const float*)d_in[4];
    const float* bng = (const float*)d_in[5];
    const float* bnb = (const float*)d_in[6];
    const float* bnm = (const float*)d_in[7];
    const float* bnv = (const float*)d_in[8];
    const float* c2w = (const float*)d_in[9];
    const float* c2b = (const float*)d_in[10];
    const float* pw1 = (const float*)d_in[11];
    const float* pb1 = (const float*)d_in[12];
    const float* pw2 = (const float*)d_in[13];
    const float* pb2 = (const float*)d_in[14];
    const float* ipw = (const float*)d_in[15];
    const float* cw  = (const float*)d_in[16];
    const float* cb  = (const float*)d_in[17];
    const float* xpw = (const float*)d_in[18];
    const float* dpw = (const float*)d_in[19];
    const float* dpb = (const float*)d_in[20];
    const float* alog= (const float*)d_in[21];
    const float* Dp  = (const float*)d_in[22];
    const float* opw = (const float*)d_in[23];
    const float* lnw = (const float*)d_in[24];
    const float* lnb = (const float*)d_in[25];
    const float* nfw = (const float*)d_in[26];
    const float* nfb = (const float*)d_in[27];
    const float* n2w = (const float*)d_in[28];
    const float* n2b = (const float*)d_in[29];
    float* out = (float*)d_out;

    cudaFuncSetAttribute(k_mma<1, 128, 128, 16>, cudaFuncAttributeMaxDynamicSharedMemorySize, SMEM_128);
    cudaFuncSetAttribute(k_mma<2, 128, 128, 16>, cudaFuncAttributeMaxDynamicSharedMemorySize, SMEM_128);
    cudaFuncSetAttribute(k_mma<0, 64, 128, 8>,   cudaFuncAttributeMaxDynamicSharedMemorySize, SMEM_64x128);
    cudaFuncSetAttribute(k_mma<0, 64, 64, 8>,    cudaFuncAttributeMaxDynamicSharedMemorySize, SMEM_64x64);
    cudaFuncSetAttribute(k_mma<3, 64, 64, 8>,    cudaFuncAttributeMaxDynamicSharedMemorySize, SMEM_64x64);

    float *be, *tok, *xz, *xi, *dtb, *bc, *hb;
    cudaGetSymbolAddress((void**)&be,  g_biaseff);
    cudaGetSymbolAddress((void**)&tok, g_tokens);
    cudaGetSymbolAddress((void**)&xz,  g_xz);
    cudaGetSymbolAddress((void**)&xi,  g_xi);
    cudaGetSymbolAddress((void**)&dtb, g_dt);
    cudaGetSymbolAddress((void**)&bc,  g_bc);
    cudaGetSymbolAddress((void**)&hb,  g_h);
    __nv_bfloat16 *fgh, *fgl, *w0h, *w0l, *nbh, *nbl, *w1h, *w1l, *w2h, *w2l, *h1h, *h1l;
    __nv_bfloat16 *ipwh, *ipwl, *wch, *wcl, *opwh, *opwl;
    __nv_bfloat16 *hnh, *hnl, *xih, *xil, *uh, *ul;
    cudaGetSymbolAddress((void**)&fgh, g_fgh);  cudaGetSymbolAddress((void**)&fgl, g_fgl);
    cudaGetSymbolAddress((void**)&w0h, g_w0h);  cudaGetSymbolAddress((void**)&w0l, g_w0l);
    cudaGetSymbolAddress((void**)&nbh, g_nbh);  cudaGetSymbolAddress((void**)&nbl, g_nbl);
    cudaGetSymbolAddress((void**)&w1h, g_w1h);  cudaGetSymbolAddress((void**)&w1l, g_w1l);
    cudaGetSymbolAddress((void**)&w2h, g_w2h);  cudaGetSymbolAddress((void**)&w2l, g_w2l);
    cudaGetSymbolAddress((void**)&h1h, g_h1h);  cudaGetSymbolAddress((void**)&h1l, g_h1l);
    cudaGetSymbolAddress((void**)&ipwh, g_ipwh); cudaGetSymbolAddress((void**)&ipwl, g_ipwl);
    cudaGetSymbolAddress((void**)&wch, g_wch);  cudaGetSymbolAddress((void**)&wcl, g_wcl);
    cudaGetSymbolAddress((void**)&opwh, g_opwh); cudaGetSymbolAddress((void**)&opwl, g_opwl);
    cudaGetSymbolAddress((void**)&hnh, g_hnh);  cudaGetSymbolAddress((void**)&hnl, g_hnl);
    cudaGetSymbolAddress((void**)&xih, g_xih);  cudaGetSymbolAddress((void**)&xil, g_xil);
    cudaGetSymbolAddress((void**)&uh,  g_uh);   cudaGetSymbolAddress((void**)&ul,  g_ul);

    /* -------- weight & input split prepasses -------- */
    auto splitN = [](long long total) { return (int)((total + 255) / 256); };
    long long tNB = (long long)NCOL * K1P;
    k_split<<<splitN(tNB), 256>>>(nb, FEAT, 0, NCOL, FEAT, nbh, nbl, K1P, tNB);
    long long tW1 = (long long)M1P * K1P;
    k_split<<<splitN(tW1), 256>>>(c1w, 2 * FEAT, 0, CH, FEAT, w0h, w0l, K1P, tW1);
    k_split<<<splitN(tW1), 256>>>(c1w, 2 * FEAT, FEAT, CH, FEAT, w1h, w1l, K1P, tW1);
    long long tW2 = (long long)ENCD * K2P;
    k_split<<<splitN(tW2), 256>>>(c2w, CH, 0, ENCD, CH, w2h, w2l, K2P, tW2);
    long long tIP = (long long)DEPTH * 2 * DIN * DDIM;
    k_split<<<splitN(tIP), 256>>>(ipw, DDIM, 0, DEPTH * 2 * DIN, DDIM, ipwh, ipwl, DDIM, tIP);
    long long tOP = (long long)DEPTH * DDIM * DIN;
    k_split<<<splitN(tOP), 256>>>(opw, DIN, 0, DEPTH * DDIM, DIN, opwh, opwl, DIN, tOP);
    k_wcomb<<<splitN((long long)DEPTH * NXPP * DIN), 256>>>(dpw, xpw);
    k_h1pad<<<NCOL / 8, 256>>>();

    /* -------- encoder -------- */
    k_fg<<<BGC, 256>>>(nb);
    /* bias-eff: be[546,2048] = c1w[:, :273] @ fg^T */
    k_mma<0, 64, 128, 8><<<dim3(M1P / 64, BGC / 128), 256, SMEM_64x128>>>(
        w0h, w0l, K1P, fgh, fgl, K1P, K1P / 64,
        nullptr, nullptr, nullptr, nullptr, nullptr,
        be, BGC, nullptr, nullptr, nullptr, CH, BGC);
    /* GEMM1: D[640,65536] -> H1T split (512 threads, staged epilogue) */
    k_mma<1, 128, 128, 16><<<dim3(M1P / 128, NCOL / 128), 512, SMEM_128>>>(
        w1h, w1l, K1P, nbh, nbl, K1P, K1P / 64,
        be, bnm, bnv, bng, bnb, nullptr, 0, nullptr, h1h, h1l, CH, NCOL);
    /* GEMM2: D[384,65536] -> tokens (512 threads, fused maxpool) */
    k_mma<2, 128, 128, 16><<<dim3(ENCD / 128, NCOL / 128), 512, SMEM_128>>>(
        w2h, w2l, K2P, h1h, h1l, K2P, K2P / 64,
        c2b, nullptr, nullptr, nullptr, nullptr, tok, 0, nullptr, nullptr, nullptr, ENCD, NCOL);

    /* -------- gather + pos embed -------- */
    k_visidx<<<BB, 32>>>(mask);
    k_pos<<<BL, 128>>>(center, pw1, pb1, pw2, pb2);

    /* -------- mamba stack -------- */
    for (int i = 0; i < DEPTH; i++) {
        k_lnres<<<BL, 128>>>(i, lnw + (size_t)i * DDIM, lnb + (size_t)i * DDIM);
        /* in_proj: xz[824,1536] = hn @ ipw^T  (64x128 tiles, 156 CTAs) */
        k_mma<0, 64, 128, 8><<<dim3(MT64, 2 * DIN / 128), 256, SMEM_64x128>>>(
            hnh, hnl, DDIM, ipwh + (size_t)i * 2 * DIN * DDIM, ipwl + (size_t)i * 2 * DIN * DDIM, DDIM,
            DDIM / 64, nullptr, nullptr, nullptr, nullptr, nullptr,
            xz, 2 * DIN, nullptr, nullptr, nullptr, BL, 2 * DIN);
        k_conv<<<(BL * DIN + 255) / 256, 256>>>(cw + (size_t)i * DIN * DCONV, cb + (size_t)i * DIN);
        /* merged x_proj+dt_proj (64x64 tiles, 182 CTAs) */
        k_mma<3, 64, 64, 8><<<dim3(MT64, NXPP / 64), 256, SMEM_64x64>>>(
            xih, xil, DIN, wch + (size_t)i * NXPP * DIN, wcl + (size_t)i * NXPP * DIN, DIN,
            DIN / 64, dpb + (size_t)i * DIN, nullptr, nullptr, nullptr, nullptr,
            dtb, DIN, bc, nullptr, nullptr, BL, NXP);
        k_scan<<<BB * 6, 128>>>(alog + (size_t)i * DIN * DSN, Dp + (size_t)i * DIN);
        /* out_proj (64x64 tiles, 78 CTAs) */
        k_mma<0, 64, 64, 8><<<dim3(MT64, DDIM / 64), 256, SMEM_64x64>>>(
            uh, ul, DIN, opwh + (size_t)i * DDIM * DIN, opwl + (size_t)i * DDIM * DIN, DIN,
            DIN / 64, nullptr, nullptr, nullptr, nullptr, nullptr,
            hb, DDIM, nullptr, nullptr, nullptr, BL, DDIM);
    }

    /* -------- final norms + outputs -------- */
    k_final<<<BL, 128>>>(out, nfw, nfb, n2w, n2b);
    k_maskout<<<1, 256>>>(mask, out, out_size);
}

// round 8
// speedup vs baseline: 3.9563x; 1.3928x over previous
#include <cuda_runtime.h>
#include <cuda_bf16.h>
#include <cuda_fp16.h>
#include <math.h>
#include <stdint.h>

#define BB 8
#define GG 256
#define NPTS 32
#define FEAT 273
#define CH 546
#define ENCD 384
#define DDIM 384
#define DEPTH 12
#define DIN 768
#define DSN 16
#define DCONV 4
#define DTR 24
#define GVIS 103
#define SEQL 103
#define BL (BB*GVIS)        /* 824 rows */
#define BLP 896             /* buffer pad */
#define BGC (BB*GG)         /* 2048 groups */
#define NCOL (BGC*NPTS)     /* 65536 point columns */
#define NMASK 153
#define OUTH (BL*DDIM)      /* 316416 */
#define NXP (DIN + 2*DSN)   /* 800 */
#define NXPP 896            /* padded */
#define K1P 320             /* FEAT 273 -> padded */
#define M1P 640             /* CH 546 -> padded  */
#define K2P 576             /* CH 546 -> padded  */
#define EPSV 1e-5f

/* ------------------------- scratch (device globals) ------------------------ */
__device__ float g_biaseff[(size_t)CH * BGC];
__device__ float g_tokens[(size_t)BGC * ENCD];
__device__ int   g_vis[BL];
__device__ float g_h[BL * DDIM];
__device__ float g_res[BL * DDIM];
__device__ float g_xz[BL * 2 * DIN];
__device__ float g_xi[BL * DIN];
__device__ float g_dt[BL * DIN];
__device__ float g_bc[BL * 2 * DSN];

/* fp16 encoder operands */
__device__ __align__(256) __half g_fgh[(size_t)BGC * K1P];
__device__ __align__(256) __half g_w0h[(size_t)M1P * K1P];
__device__ __align__(256) __half g_w0l[(size_t)M1P * K1P];
__device__ __align__(256) __half g_nbh[(size_t)NCOL * K1P];
__device__ __align__(256) __half g_w1h[(size_t)M1P * K1P];
__device__ __align__(256) __half g_w1l[(size_t)M1P * K1P];
__device__ __align__(256) __half g_w2h[(size_t)ENCD * K2P];
__device__ __align__(256) __half g_w2l[(size_t)ENCD * K2P];
__device__ __align__(256) __half g_h1h[(size_t)NCOL * K2P];

/* bf16-split mamba operands */
__device__ __align__(256) __nv_bfloat16 g_ipwh[(size_t)DEPTH * 2 * DIN * DDIM];
__device__ __align__(256) __nv_bfloat16 g_ipwl[(size_t)DEPTH * 2 * DIN * DDIM];
__device__ __align__(256) __nv_bfloat16 g_wch[(size_t)DEPTH * NXPP * DIN];
__device__ __align__(256) __nv_bfloat16 g_wcl[(size_t)DEPTH * NXPP * DIN];
__device__ __align__(256) __nv_bfloat16 g_opwh[(size_t)DEPTH * DDIM * DIN];
__device__ __align__(256) __nv_bfloat16 g_opwl[(size_t)DEPTH * DDIM * DIN];
__device__ __align__(256) __nv_bfloat16 g_hnh[(size_t)BLP * DDIM];
__device__ __align__(256) __nv_bfloat16 g_hnl[(size_t)BLP * DDIM];
__device__ __align__(256) __nv_bfloat16 g_xih[(size_t)BLP * DIN];
__device__ __align__(256) __nv_bfloat16 g_xil[(size_t)BLP * DIN];
__device__ __align__(256) __nv_bfloat16 g_uh[(size_t)BLP * DIN];
__device__ __align__(256) __nv_bfloat16 g_ul[(size_t)BLP * DIN];

/* ------------------------------ small helpers ----------------------------- */
__device__ __forceinline__ float siluf(float x) { return x / (1.f + expf(-x)); }
__device__ __forceinline__ float geluf(float x) { return 0.5f * x * (1.f + erff(x * 0.70710678118654752f)); }
__device__ __forceinline__ float softplusf(float x) { return (x > 20.f) ? x : log1pf(expf(x)); }
__device__ __forceinline__ void split2(float v, __nv_bfloat16* h, __nv_bfloat16* l) {
    __nv_bfloat16 hh = __float2bfloat16(v);
    *h = hh;
    *l = __float2bfloat16(v - __bfloat162float(hh));
}
__device__ __forceinline__ void split2h(float v, __half* h, __half* l) {
    __half hh = __float2half(v);
    *h = hh;
    *l = __float2half(v - __half2float(hh));
}

__device__ __forceinline__ void reduce2_128(float& s1, float& s2) {
    #pragma unroll
    for (int o = 16; o; o >>= 1) {
        s1 += __shfl_xor_sync(0xffffffffu, s1, o);
        s2 += __shfl_xor_sync(0xffffffffu, s2, o);
    }
    __shared__ float ra[4], rb[4];
    int w = threadIdx.x >> 5, l = threadIdx.x & 31;
    if (l == 0) { ra[w] = s1; rb[w] = s2; }
    __syncthreads();
    s1 = ra[0] + ra[1] + ra[2] + ra[3];
    s2 = rb[0] + rb[1] + rb[2] + rb[3];
    __syncthreads();
}

/* --------------------------- PTX wrappers --------------------------------- */
__device__ __forceinline__ uint32_t smem_u32(const void* p) {
    uint32_t a;
    asm("{ .reg .u64 t; cvta.to.shared.u64 t, %1; cvt.u32.u64 %0, t; }" : "=r"(a) : "l"(p));
    return a;
}
#define SWZ128(o) ((o) ^ (((o) >> 3) & 0x70))
#define CP_ASYNC16(d, s) asm volatile("cp.async.cg.shared.global [%0], [%1], 16;" :: "r"(d), "l"(s))
#define CP_COMMIT()      asm volatile("cp.async.commit_group;" ::: "memory")
#define CP_WAIT1()       asm volatile("cp.async.wait_group 1;" ::: "memory")
#define CP_WAIT0()       asm volatile("cp.async.wait_group 0;" ::: "memory")

__device__ __forceinline__ void ldm_x4(uint32_t* r, uint32_t addr) {
    asm volatile("ldmatrix.sync.aligned.m8n8.x4.shared.b16 {%0,%1,%2,%3}, [%4];"
        : "=r"(r[0]), "=r"(r[1]), "=r"(r[2]), "=r"(r[3]) : "r"(addr));
}
__device__ __forceinline__ void mma_bf16(float* c, const uint32_t* a, uint32_t b0, uint32_t b1) {
    asm volatile("mma.sync.aligned.m16n8k16.row.col.f32.bf16.bf16.f32 "
        "{%0,%1,%2,%3}, {%4,%5,%6,%7}, {%8,%9}, {%0,%1,%2,%3};"
        : "+f"(c[0]), "+f"(c[1]), "+f"(c[2]), "+f"(c[3])
        : "r"(a[0]), "r"(a[1]), "r"(a[2]), "r"(a[3]), "r"(b0), "r"(b1));
}
__device__ __forceinline__ void mma_fp16(float* c, const uint32_t* a, uint32_t b0, uint32_t b1) {
    asm volatile("mma.sync.aligned.m16n8k16.row.col.f32.f16.f16.f32 "
        "{%0,%1,%2,%3}, {%4,%5,%6,%7}, {%8,%9}, {%0,%1,%2,%3};"
        : "+f"(c[0]), "+f"(c[1]), "+f"(c[2]), "+f"(c[3])
        : "r"(a[0]), "r"(a[1]), "r"(a[2]), "r"(a[3]), "r"(b0), "r"(b1));
}

/* =================== generic split mma.sync GEMM ===========================
 * PASS==3: bf16, A h/l + B h/l, D = AhBh + AhBl + AlBh
 * PASS==2: fp16, A h/l + B h only, D = AhBh + AlBh
 * D[M,N] = A[M,K] * B[N,K]^T  (K-major, ld = Kpad, elements 2 bytes)
 * grid = (Mtiles, Ntiles); NW warps (8: 2x4, 16: 4x4). CTA tile TM x TN.
 * EPI 0: C[m*ldc+n] = v               (m<Mv, n<Nv)
 * EPI 1: v+=be[m*BGC+grp]; BN+relu -> O1 (fp16 single, staged) [n*K2P+m]
 * EPI 2: group maxpool + p0[m] -> C[grp*ENCD+m]  (TN=128 only)
 * EPI 3: n<DIN: C[m*DIN+n]=softplus(v+p0[n]); n<NXP: C2[m*32+n-DIN]=v
 * ========================================================================= */
template<int EPI, int TM, int TN, int NW, int PASS>
__global__ __launch_bounds__(NW * 32) void k_mma(
    const __nv_bfloat16* __restrict__ Ah, const __nv_bfloat16* __restrict__ Al, int lda,
    const __nv_bfloat16* __restrict__ Bh, const __nv_bfloat16* __restrict__ Bl, int ldb,
    int NKC,
    const float* __restrict__ p0, const float* __restrict__ p1,
    const float* __restrict__ p2, const float* __restrict__ p3,
    const float* __restrict__ p4,
    float* __restrict__ C, int ldc, float* __restrict__ C2,
    __nv_bfloat16* __restrict__ O1, __nv_bfloat16* __restrict__ O2,
    int Mv, int Nv)
{
    constexpr int THREADS = NW * 32;
    constexpr int WR = NW / 4;
    constexpr int WC = 4;
    constexpr int WM = TM / WR;
    constexpr int WN = TN / WC;
    constexpr int MI = WM / 16;
    constexpr int NJ = WN / 8;
    constexpr int NB2 = (NJ + 1) / 2;
    constexpr int LA = TM * 8 / THREADS;
    constexpr int LB = TN * 8 / THREADS;
    constexpr uint32_t ABY = TM * 128;
    constexpr uint32_t BBY = TN * 128;
    constexpr uint32_t BUFSZ = (PASS == 3) ? (2 * ABY + 2 * BBY) : (2 * ABY + BBY);

    extern __shared__ __align__(1024) char smem[];
    const uint32_t sb = smem_u32(smem);
    const int tid = threadIdx.x, wid = tid >> 5, lid = tid & 31;
    const int wrow = wid >> 2, wcol = wid & 3;
    const int quad = lid >> 2, tq = lid & 3;
    const int m0 = blockIdx.x * TM, n0 = blockIdx.y * TN;

    const int lrow = (lid & 7) + 8 * ((lid >> 3) & 1);
    const int lk   = 8 * (lid >> 4);

    float acc[MI][NJ][4];
    #pragma unroll
    for (int i = 0; i < MI; i++)
        #pragma unroll
        for (int j = 0; j < NJ; j++)
            #pragma unroll
            for (int k = 0; k < 4; k++) acc[i][j][k] = 0.f;

    auto loadChunk = [&](int kc, int c) {
        const uint32_t bufb = sb + c * BUFSZ;
        #pragma unroll
        for (int p = 0; p < LA; p++) {
            int idx = tid + p * THREADS;
            int row = idx >> 3, c16 = idx & 7;
            uint32_t sw = SWZ128((uint32_t)(row * 128 + c16 * 16));
            const void* gh = Ah + (size_t)(m0 + row) * lda + kc * 64 + c16 * 8;
            const void* gl = Al + (size_t)(m0 + row) * lda + kc * 64 + c16 * 8;
            CP_ASYNC16(bufb + sw, gh);
            CP_ASYNC16(bufb + ABY + sw, gl);
        }
        #pragma unroll
        for (int p = 0; p < LB; p++) {
            int idx = tid + p * THREADS;
            int row = idx >> 3, c16 = idx & 7;
            uint32_t sw = SWZ128((uint32_t)(row * 128 + c16 * 16));
            const void* gh = Bh + (size_t)(n0 + row) * ldb + kc * 64 + c16 * 8;
            CP_ASYNC16(bufb + 2 * ABY + sw, gh);
            if (PASS == 3) {
                const void* gl = Bl + (size_t)(n0 + row) * ldb + kc * 64 + c16 * 8;
                CP_ASYNC16(bufb + 2 * ABY + BBY + sw, gl);
            }
        }
        CP_COMMIT();
    };

    loadChunk(0, 0);
    if (NKC > 1) loadChunk(1, 1); else CP_COMMIT();

    for (int kc = 0; kc < NKC; kc++) {
        const int c = kc & 1;
        if (kc + 1 < NKC) CP_WAIT1(); else CP_WAIT0();
        __syncthreads();
        const uint32_t ahb = sb + c * BUFSZ;
        const uint32_t alb = ahb + ABY;
        const uint32_t bhb = ahb + 2 * ABY;
        const uint32_t blb = bhb + BBY;
        #pragma unroll
        for (int ks = 0; ks < 4; ks++) {
            const int k0 = ks * 16 + lk;
            uint32_t fah[MI][4], fal[MI][4], fbh[NB2][4], fbl[NB2][4];
            #pragma unroll
            for (int bi = 0; bi < MI; bi++) {
                int r = wrow * WM + bi * 16 + lrow;
                ldm_x4(fah[bi], ahb + SWZ128((uint32_t)(r * 128 + k0 * 2)));
                ldm_x4(fal[bi], alb + SWZ128((uint32_t)(r * 128 + k0 * 2)));
            }
            #pragma unroll
            for (int bj2 = 0; bj2 < NB2; bj2++) {
                int r = wcol * WN + bj2 * 16 + lrow;
                ldm_x4(fbh[bj2], bhb + SWZ128((uint32_t)(r * 128 + k0 * 2)));
                if (PASS == 3)
                    ldm_x4(fbl[bj2], blb + SWZ128((uint32_t)(r * 128 + k0 * 2)));
            }
            #pragma unroll
            for (int bi = 0; bi < MI; bi++) {
                #pragma unroll
                for (int bj = 0; bj < NJ; bj++) {
                    uint32_t bh0 = fbh[bj >> 1][bj & 1], bh1 = fbh[bj >> 1][2 + (bj & 1)];
                    if (PASS == 3) {
                        uint32_t bl0 = fbl[bj >> 1][bj & 1], bl1 = fbl[bj >> 1][2 + (bj & 1)];
                        mma_bf16(acc[bi][bj], fah[bi], bh0, bh1);
                        mma_bf16(acc[bi][bj], fah[bi], bl0, bl1);
                        mma_bf16(acc[bi][bj], fal[bi], bh0, bh1);
                    } else {
                        mma_fp16(acc[bi][bj], fah[bi], bh0, bh1);
                        mma_fp16(acc[bi][bj], fal[bi], bh0, bh1);
                    }
                }
            }
        }
        __syncthreads();
        if (kc + 2 < NKC) loadChunk(kc + 2, c);
    }

    const int grp = (n0 >> 5) + wcol;

    if (EPI == 1) {
        /* staged transposed fp16 store (TM=TN=128): O1[n*K2P+m] */
        const int LDE = 136;
        __half* sh = (__half*)smem;
        const int mlim = (CH - m0 < 128) ? (CH - m0) : 128;
        #pragma unroll
        for (int bi = 0; bi < MI; bi++) {
            #pragma unroll
            for (int h0 = 0; h0 < 2; h0++) {
                const int ml = wrow * WM + bi * 16 + quad + 8 * h0;
                const int m = m0 + ml;
                if (m < CH) {
                    const float be = p0[(size_t)m * BGC + grp];
                    const float bnm = p1[m];
                    const float sc  = rsqrtf(p2[m] + EPSV) * p3[m];
                    const float bb  = p4[m];
                    #pragma unroll
                    for (int bj = 0; bj < NJ; bj++) {
                        #pragma unroll
                        for (int e = 0; e < 2; e++) {
                            int nl = wcol * WN + bj * 8 + 2 * tq + e;
                            float v = acc[bi][bj][h0 * 2 + e] + be;
                            v = fmaxf((v - bnm) * sc + bb, 0.f);
                            sh[nl * LDE + ml] = __float2half(v);
                        }
                    }
                }
            }
        }
        __syncthreads();
        __half* O1h = (__half*)O1;
        for (int idx = tid; idx < 128 * 16; idx += THREADS) {
            int nl = idx >> 4, ch = idx & 15;
            int mbeg = ch * 8;
            if (mbeg < mlim) {
                size_t gbase = (size_t)(n0 + nl) * K2P + m0 + mbeg;
                if (mbeg + 8 <= mlim) {
                    *(uint4*)(&O1h[gbase]) = *(const uint4*)(&sh[nl * LDE + mbeg]);
                } else {
                    for (int t = 0; t < mlim - mbeg; t++)
                        O1h[gbase + t] = sh[nl * LDE + mbeg + t];
                }
            }
        }
        return;
    }

    #pragma unroll
    for (int bi = 0; bi < MI; bi++) {
        #pragma unroll
        for (int h0 = 0; h0 < 2; h0++) {
            const int m = m0 + wrow * WM + bi * 16 + quad + 8 * h0;
            if (EPI == 2) {
                float vm = -INFINITY;
                #pragma unroll
                for (int bj = 0; bj < NJ; bj++) {
                    vm = fmaxf(vm, acc[bi][bj][h0 * 2]);
                    vm = fmaxf(vm, acc[bi][bj][h0 * 2 + 1]);
                }
                vm = fmaxf(vm, __shfl_xor_sync(0xffffffffu, vm, 1));
                vm = fmaxf(vm, __shfl_xor_sync(0xffffffffu, vm, 2));
                if (tq == 0) C[(size_t)grp * ENCD + m] = vm + p0[m];
            } else if (EPI == 0) {
                if (m < Mv) {
                    #pragma unroll
                    for (int bj = 0; bj < NJ; bj++) {
                        #pragma unroll
                        for (int e = 0; e < 2; e++) {
                            int n = n0 + wcol * WN + bj * 8 + 2 * tq + e;
                            if (n < Nv) C[(size_t)m * ldc + n] = acc[bi][bj][h0 * 2 + e];
                        }
                    }
                }
            } else { /* EPI 3 */
                if (m < Mv) {
                    #pragma unroll
                    for (int bj = 0; bj < NJ; bj++) {
                        #pragma unroll
                        for (int e = 0; e < 2; e++) {
                            int n = n0 + wcol * WN + bj * 8 + 2 * tq + e;
                            float v = acc[bi][bj][h0 * 2 + e];
                            if (n < DIN) C[(size_t)m * DIN + n] = softplusf(v + p0[n]);
                            else if (n < NXP) C2[(size_t)m * (2 * DSN) + (n - DIN)] = v;
                        }
                    }
                }
            }
        }
    }
}

/* --------------------------- split prepass kernels ------------------------- */
__global__ void k_split(const float* __restrict__ src, int sld, int soff,
                        int R, int K, __nv_bfloat16* __restrict__ dh,
                        __nv_bfloat16* __restrict__ dl, int Kp, long long total) {
    long long i = (long long)blockIdx.x * 256 + threadIdx.x;
    if (i >= total) return;
    int k = (int)(i % Kp);
    long long r = i / Kp;
    float v = (r < R && k < K) ? src[r * sld + soff + k] : 0.f;
    split2(v, &dh[i], &dl[i]);
}
__global__ void k_split_h2(const float* __restrict__ src, int sld, int soff,
                           int R, int K, __half* __restrict__ dh,
                           __half* __restrict__ dl, int Kp, long long total) {
    long long i = (long long)blockIdx.x * 256 + threadIdx.x;
    if (i >= total) return;
    int k = (int)(i % Kp);
    long long r = i / Kp;
    float v = (r < R && k < K) ? src[r * sld + soff + k] : 0.f;
    split2h(v, &dh[i], &dl[i]);
}
__global__ void k_split_h1(const float* __restrict__ src, int sld, int soff,
                           int R, int K, __half* __restrict__ dh,
                           int Kp, long long total) {
    long long i = (long long)blockIdx.x * 256 + threadIdx.x;
    if (i >= total) return;
    int k = (int)(i % Kp);
    long long r = i / Kp;
    float v = (r < R && k < K) ? src[r * sld + soff + k] : 0.f;
    dh[i] = __float2half(v);
}

__global__ void k_wcomb(const float* __restrict__ dpw, const float* __restrict__ xpw) {
    long long idx = (long long)blockIdx.x * 256 + threadIdx.x;
    if (idx >= (long long)DEPTH * NXPP * DIN) return;
    int col = (int)(idx % DIN);
    int rem = (int)(idx / DIN);
    int row = rem % NXPP;
    int l   = rem / NXPP;
    const float* xp = xpw + (size_t)l * (DTR + 2 * DSN) * DIN;
    float v = 0.f;
    if (row < DIN) {
        const float* dr = dpw + (size_t)l * DIN * DTR + (size_t)row * DTR;
        #pragma unroll
        for (int t = 0; t < DTR; t++) v = fmaf(dr[t], xp[(size_t)t * DIN + col], v);
    } else if (row < NXP) {
        v = xp[(size_t)(DTR + (row - DIN)) * DIN + col];
    }
    split2(v, &g_wch[idx], &g_wcl[idx]);
}

__global__ void k_h1pad() {
    int n = blockIdx.x * 8 + (threadIdx.x >> 5);
    int j = threadIdx.x & 31;
    if (j < (K2P - CH))
        g_h1h[(size_t)n * K2P + CH + j] = __float2half(0.f);
}

/* ---------- encoder: per-group feature max -> fp16 [bg][K1P] --------------- */
__global__ void k_fg(const float* __restrict__ nb) {
    __shared__ float s[NPTS * FEAT];
    int bg = blockIdx.x;
    const float* src = nb + (size_t)bg * NPTS * FEAT;
    for (int t = threadIdx.x; t < NPTS * FEAT; t += blockDim.x) s[t] = src[t];
    __syncthreads();
    for (int c = threadIdx.x; c < K1P; c += blockDim.x) {
        float m = 0.f;
        if (c < FEAT) {
            m = s[c];
            #pragma unroll
            for (int n = 1; n < NPTS; n++) m = fmaxf(m, s[n * FEAT + c]);
        }
        g_fgh[(size_t)bg * K1P + c] = __float2half(m);
    }
}

/* ---------------- visible-index extraction (bool width-robust) ------------ */
__global__ void k_visidx(const unsigned char* __restrict__ m8) {
    if (threadIdx.x != 0) return;
    int b = blockIdx.x;
    int c8 = 0;
    for (int g = 0; g < GG; g++) c8 += (m8[(size_t)b * GG + g] != 0);
    int cnt = 0;
    if (c8 == NMASK) {
        for (int g = 0; g < GG; g++)
            if (!m8[(size_t)b * GG + g]) { if (cnt < GVIS) g_vis[b * GVIS + cnt] = g; cnt++; }
    } else {
        const int* m32 = (const int*)m8;
        for (int g = 0; g < GG; g++)
            if (!m32[(size_t)b * GG + g]) { if (cnt < GVIS) g_vis[b * GVIS + cnt] = g; cnt++; }
    }
}

/* ------------- gather tokens/centers + pos MLP -> initial h ---------------- */
__global__ void k_pos(const float* __restrict__ center,
                      const float* __restrict__ w1, const float* __restrict__ b1,
                      const float* __restrict__ w2, const float* __restrict__ b2) {
    __shared__ float hcache[128];
    __shared__ float cc[3];
    int r = blockIdx.x;
    int b = r / GVIS;
    int g = g_vis[r];
    int tid = threadIdx.x;
    if (tid < 3) cc[tid] = center[((size_t)b * GG + g) * 3 + tid];
    __syncthreads();
    float a = w1[tid * 3] * cc[0] + w1[tid * 3 + 1] * cc[1] + w1[tid * 3 + 2] * cc[2] + b1[tid];
    hcache[tid] = geluf(a);
    __syncthreads();
    const float* tok = g_tokens + ((size_t)b * GG + g) * ENCD;
    for (int e = tid; e < DDIM; e += 128) {
        float acc = b2[e];
        const float* wr = w2 + (size_t)e * 128;
        #pragma unroll 8
        for (int k = 0; k < 128; k++) acc = fmaf(wr[k], hcache[k], acc);
        g_h[(size_t)r * DDIM + e] = acc + tok[e];
    }
}

/* ------------- residual accumulate + LayerNorm -> split bf16 --------------- */
__global__ void k_lnres(int layer, const float* __restrict__ w, const float* __restrict__ b) {
    int r = blockIdx.x, tid = threadIdx.x;
    float* res = g_res + (size_t)r * DDIM;
    const float* h = g_h + (size_t)r * DDIM;
    float v[3], s1 = 0.f, s2 = 0.f;
    #pragma unroll
    for (int i = 0; i < 3; i++) {
        int c = tid + i * 128;
        float x = h[c];
        if (layer > 0) x += res[c];
        v[i] = x; res[c] = x;
        s1 += x; s2 += x * x;
    }
    reduce2_128(s1, s2);
    float mu = s1 * (1.f / DDIM);
    float rstd = rsqrtf(s2 * (1.f / DDIM) - mu * mu + EPSV);
    #pragma unroll
    for (int i = 0; i < 3; i++) {
        int c = tid + i * 128;
        float y = (v[i] - mu) * rstd * w[c] + b[c];
        split2(y, &g_hnh[(size_t)r * DDIM + c], &g_hnl[(size_t)r * DDIM + c]);
    }
}

/* ---------------- depthwise causal conv (k=4) + SiLU -> split -------------- */
__global__ void k_conv(const float* __restrict__ cw, const float* __restrict__ cb) {
    int idx = blockIdx.x * blockDim.x + threadIdx.x;
    if (idx >= BL * DIN) return;
    int d = idx % DIN, r = idx / DIN;
    int b = r / SEQL, l = r % SEQL;
    float acc = cb[d];
    #pragma unroll
    for (int k = 0; k < DCONV; k++) {
        int ll = l - (DCONV - 1) + k;
        if (ll >= 0) acc = fmaf(cw[d * DCONV + k], g_xz[((size_t)(b * SEQL + ll)) * (2 * DIN) + d], acc);
    }
    float y = siluf(acc);
    g_xi[idx] = y;
    split2(y, &g_xih[idx], &g_xil[idx]);
}

/* --------------------------- selective scan -> split ------------------------
 * dA[s] = exp(dt*A[s]); when A[s] == -(s+1) (the dataset's A_log=log(1..16))
 * use dA[s] = q^(s+1) with q = exp(dt*A[0]) -> 1 MUFU/step instead of 16.
 * Software-pipelined: next step's dt/x/z/B/C row prefetched into registers. */
struct ScanIn { float dt, x, z, bl[2 * DSN]; };
__device__ __forceinline__ void scan_load(ScanIn& s, int r, int d) {
    s.dt = g_dt[(size_t)r * DIN + d];
    s.x  = g_xi[(size_t)r * DIN + d];
    s.z  = g_xz[(size_t)r * (2 * DIN) + DIN + d];
    const float4* p = (const float4*)(g_bc + (size_t)r * (2 * DSN));
    #pragma unroll
    for (int i = 0; i < 8; i++) {
        float4 v = p[i];
        s.bl[4 * i] = v.x; s.bl[4 * i + 1] = v.y;
        s.bl[4 * i + 2] = v.z; s.bl[4 * i + 3] = v.w;
    }
}
__global__ void k_scan(const float* __restrict__ alog, const float* __restrict__ Dp) {
    int b = blockIdx.x / 6;
    int d = (blockIdx.x % 6) * 128 + threadIdx.x;
    float A[DSN];
    bool st = true;
    #pragma unroll
    for (int s = 0; s < DSN; s++) {
        A[s] = -expf(alog[(size_t)d * DSN + s]);
        if (fabsf(A[s] + (float)(s + 1)) > 1e-3f) st = false;
    }
    float Dd = Dp[d];
    float h[DSN];
    #pragma unroll
    for (int s = 0; s < DSN; s++) h[s] = 0.f;

    ScanIn cur, nxt;
    scan_load(cur, b * SEQL, d);
    for (int l = 0; l < SEQL; l++) {
        if (l + 1 < SEQL) scan_load(nxt, b * SEQL + l + 1, d);
        float dtx = cur.dt * cur.x;
        float y = 0.f;
        if (st) {
            float q = __expf(cur.dt * A[0]);
            float dA = q;
            #pragma unroll
            for (int s = 0; s < DSN; s++) {
                h[s] = fmaf(dA, h[s], dtx * cur.bl[s]);
                y = fmaf(h[s], cur.bl[DSN + s], y);
                dA *= q;
            }
        } else {
            #pragma unroll
            for (int s = 0; s < DSN; s++) {
                float dA = __expf(cur.dt * A[s]);
                h[s] = fmaf(dA, h[s], dtx * cur.bl[s]);
                y = fmaf(h[s], cur.bl[DSN + s], y);
            }
        }
        float u = (y + cur.x * Dd) * siluf(cur.z);
        size_t o = (size_t)(b * SEQL + l) * DIN + d;
        split2(u, &g_uh[o], &g_ul[o]);
        cur = nxt;
    }
}

/* ----------------------- final residual + double LN ------------------------ */
__global__ void k_final(float* __restrict__ out,
                        const float* __restrict__ w1, const float* __restrict__ b1,
                        const float* __restrict__ w2, const float* __restrict__ b2) {
    int r = blockIdx.x, tid = threadIdx.x;
    float v[3], s1 = 0.f, s2 = 0.f;
    #pragma unroll
    for (int i = 0; i < 3; i++) {
        int c = tid + i * 128;
        float x = g_res[(size_t)r * DDIM + c] + g_h[(size_t)r * DDIM + c];
        v[i] = x; s1 += x; s2 += x * x;
    }
    reduce2_128(s1, s2);
    float mu = s1 * (1.f / DDIM);
    float rstd = rsqrtf(s2 * (1.f / DDIM) - mu * mu + EPSV);
    s1 = 0.f; s2 = 0.f;
    #pragma unroll
    for (int i = 0; i < 3; i++) {
        int c = tid + i * 128;
        v[i] = (v[i] - mu) * rstd * w1[c] + b1[c];
        s1 += v[i]; s2 += v[i] * v[i];
    }
    reduce2_128(s1, s2);
    mu = s1 * (1.f / DDIM);
    rstd = rsqrtf(s2 * (1.f / DDIM) - mu * mu + EPSV);
    #pragma unroll
    for (int i = 0; i < 3; i++) {
        int c = tid + i * 128;
        out[(size_t)r * DDIM + c] = (v[i] - mu) * rstd * w2[c] + b2[c];
    }
}

/* -------------------------- mask -> output tail ---------------------------- */
__global__ void k_maskout(const unsigned char* __restrict__ m8, float* __restrict__ out, int out_size) {
    if (out_size < OUTH + BB * GG) return;
    __shared__ int use8;
    if (threadIdx.x == 0) {
        int c = 0;
        for (int g = 0; g < GG; g++) c += (m8[g] != 0);
        use8 = (c == NMASK);
    }
    __syncthreads();
    const int* m32 = (const int*)m8;
    for (int i = threadIdx.x; i < BB * GG; i += blockDim.x) {
        float v = use8 ? (m8[i] ? 1.f : 0.f) : (m32[i] ? 1.f : 0.f);
        out[OUTH + i] = v;
    }
}

/* ------------------------------- host driver ------------------------------- */
#define SMEM_128P2 (2 * (2 * 16384 + 16384))     /* 98304 */
#define SMEM_64x128P2 (2 * (2 * 8192 + 16384))   /* 65536 */
#define SMEM_64x128P3 (2 * (2 * 8192 + 2 * 16384)) /* 98304 */
#define SMEM_64x64P3 (2 * (2 * 8192 + 2 * 8192))   /* 65536 */
#define MT64 13

extern "C" void kernel_launch(void* const* d_in, const int* in_sizes, int n_in,
                              void* d_out, int out_size) {
    (void)in_sizes; (void)n_in;
    const float* nb     = (const float*)d_in[0];
    const float* center = (const float*)d_in[1];
    const unsigned char* mask = (const unsigned char*)d_in[2];
    const float* c1w = (const float*)d_in[3];
    const float* c1b = (const float*)d_in[4];
    const float* bng = (const float*)d_in[5];
    const float* bnb = (const float*)d_in[6];
    const float* bnm = (const float*)d_in[7];
    const float* bnv = (const float*)d_in[8];
    const float* c2w = (const float*)d_in[9];
    const float* c2b = (const float*)d_in[10];
    const float* pw1 = (const float*)d_in[11];
    const float* pb1 = (const float*)d_in[12];
    const float* pw2 = (const float*)d_in[13];
    const float* pb2 = (const float*)d_in[14];
    const float* ipw = (const float*)d_in[15];
    const float* cw  = (const float*)d_in[16];
    const float* cb  = (const float*)d_in[17];
    const float* xpw = (const float*)d_in[18];
    const float* dpw = (const float*)d_in[19];
    const float* dpb = (const float*)d_in[20];
    const float* alog= (const float*)d_in[21];
    const float* Dp  = (const float*)d_in[22];
    const float* opw = (const float*)d_in[23];
    const float* lnw = (const float*)d_in[24];
    const float* lnb = (const float*)d_in[25];
    const float* nfw = (const float*)d_in[26];
    const float* nfb = (const float*)d_in[27];
    const float* n2w = (const float*)d_in[28];
    const float* n2b = (const float*)d_in[29];
    float* out = (float*)d_out;

    cudaFuncSetAttribute((const void*)k_mma<0, 64, 128, 8, 2>,  cudaFuncAttributeMaxDynamicSharedMemorySize, SMEM_64x128P2);
    cudaFuncSetAttribute((const void*)k_mma<1, 128, 128, 16, 2>, cudaFuncAttributeMaxDynamicSharedMemorySize, SMEM_128P2);
    cudaFuncSetAttribute((const void*)k_mma<2, 128, 128, 16, 2>, cudaFuncAttributeMaxDynamicSharedMemorySize, SMEM_128P2);
    cudaFuncSetAttribute((const void*)k_mma<0, 64, 128, 8, 3>,  cudaFuncAttributeMaxDynamicSharedMemorySize, SMEM_64x128P3);
    cudaFuncSetAttribute((const void*)k_mma<0, 64, 64, 8, 3>,   cudaFuncAttributeMaxDynamicSharedMemorySize, SMEM_64x64P3);
    cudaFuncSetAttribute((const void*)k_mma<3, 64, 64, 8, 3>,   cudaFuncAttributeMaxDynamicSharedMemorySize, SMEM_64x64P3);

    float *be, *tok, *xz, *xi, *dtb, *bc, *hb;
    cudaGetSymbolAddress((void**)&be,  g_biaseff);
    cudaGetSymbolAddress((void**)&tok, g_tokens);
    cudaGetSymbolAddress((void**)&xz,  g_xz);
    cudaGetSymbolAddress((void**)&xi,  g_xi);
    cudaGetSymbolAddress((void**)&dtb, g_dt);
    cudaGetSymbolAddress((void**)&bc,  g_bc);
    cudaGetSymbolAddress((void**)&hb,  g_h);
    __half *fgh, *w0h, *w0l, *nbh, *w1h, *w1l, *w2h, *w2l, *h1h;
    __nv_bfloat16 *ipwh, *ipwl, *wch, *wcl, *opwh, *opwl;
    __nv_bfloat16 *hnh, *hnl, *xih, *xil, *uh, *ul;
    cudaGetSymbolAddress((void**)&fgh, g_fgh);
    cudaGetSymbolAddress((void**)&w0h, g_w0h);  cudaGetSymbolAddress((void**)&w0l, g_w0l);
    cudaGetSymbolAddress((void**)&nbh, g_nbh);
    cudaGetSymbolAddress((void**)&w1h, g_w1h);  cudaGetSymbolAddress((void**)&w1l, g_w1l);
    cudaGetSymbolAddress((void**)&w2h, g_w2h);  cudaGetSymbolAddress((void**)&w2l, g_w2l);
    cudaGetSymbolAddress((void**)&h1h, g_h1h);
    cudaGetSymbolAddress((void**)&ipwh, g_ipwh); cudaGetSymbolAddress((void**)&ipwl, g_ipwl);
    cudaGetSymbolAddress((void**)&wch, g_wch);  cudaGetSymbolAddress((void**)&wcl, g_wcl);
    cudaGetSymbolAddress((void**)&opwh, g_opwh); cudaGetSymbolAddress((void**)&opwl, g_opwl);
    cudaGetSymbolAddress((void**)&hnh, g_hnh);  cudaGetSymbolAddress((void**)&hnl, g_hnl);
    cudaGetSymbolAddress((void**)&xih, g_xih);  cudaGetSymbolAddress((void**)&xil, g_xil);
    cudaGetSymbolAddress((void**)&uh,  g_uh);   cudaGetSymbolAddress((void**)&ul,  g_ul);

    auto splitN = [](long long total) { return (int)((total + 255) / 256); };
    long long tW1 = (long long)M1P * K1P;
    long long tNB = (long long)NCOL * K1P;
    long long tW2 = (long long)ENCD * K2P;

    /* launches 1-5 (so GEMM1 is launch #6 for ncu -s 5 -c 1) */
    k_split_h2<<<splitN(tW1), 256>>>(c1w, 2 * FEAT, 0, CH, FEAT, w0h, w0l, K1P, tW1);
    k_fg<<<BGC, 256>>>(nb);
    k_mma<0, 64, 128, 8, 2><<<dim3(M1P / 64, BGC / 128), 256, SMEM_64x128P2>>>(
        (const __nv_bfloat16*)w0h, (const __nv_bfloat16*)w0l, K1P,
        (const __nv_bfloat16*)fgh, nullptr, K1P, K1P / 64,
        nullptr, nullptr, nullptr, nullptr, nullptr,
        be, BGC, nullptr, nullptr, nullptr, CH, BGC);
    k_split_h1<<<splitN(tNB), 256>>>(nb, FEAT, 0, NCOL, FEAT, nbh, K1P, tNB);
    k_split_h2<<<splitN(tW1), 256>>>(c1w, 2 * FEAT, FEAT, CH, FEAT, w1h, w1l, K1P, tW1);

    /* launch #6: GEMM1 D[640,65536] -> H1 fp16 (profiled) */
    k_mma<1, 128, 128, 16, 2><<<dim3(M1P / 128, NCOL / 128), 512, SMEM_128P2>>>(
        (const __nv_bfloat16*)w1h, (const __nv_bfloat16*)w1l, K1P,
        (const __nv_bfloat16*)nbh, nullptr, K1P, K1P / 64,
        be, bnm, bnv, bng, bnb, nullptr, 0, nullptr,
        (__nv_bfloat16*)h1h, nullptr, CH, NCOL);

    k_h1pad<<<NCOL / 8, 256>>>();
    k_split_h2<<<splitN(tW2), 256>>>(c2w, CH, 0, ENCD, CH, w2h, w2l, K2P, tW2);

    /* GEMM2: D[384,65536] -> tokens (fused maxpool) */
    k_mma<2, 128, 128, 16, 2><<<dim3(ENCD / 128, NCOL / 128), 512, SMEM_128P2>>>(
        (const __nv_bfloat16*)w2h, (const __nv_bfloat16*)w2l, K2P,
        (const __nv_bfloat16*)h1h, nullptr, K2P, K2P / 64,
        c2b, nullptr, nullptr, nullptr, nullptr, tok, 0, nullptr, nullptr, nullptr, ENCD, NCOL);

    /* remaining weight prepasses (mamba bf16) */
    long long tIP = (long long)DEPTH * 2 * DIN * DDIM;
    k_split<<<splitN(tIP), 256>>>(ipw, DDIM, 0, DEPTH * 2 * DIN, DDIM, ipwh, ipwl, DDIM, tIP);
    long long tOP = (long long)DEPTH * DDIM * DIN;
    k_split<<<splitN(tOP), 256>>>(opw, DIN, 0, DEPTH * DDIM, DIN, opwh, opwl, DIN, tOP);
    k_wcomb<<<splitN((long long)DEPTH * NXPP * DIN), 256>>>(dpw, xpw);

    /* gather + pos embed */
    k_visidx<<<BB, 32>>>(mask);
    k_pos<<<BL, 128>>>(center, pw1, pb1, pw2, pb2);

    /* mamba stack */
    for (int i = 0; i < DEPTH; i++) {
        k_lnres<<<BL, 128>>>(i, lnw + (size_t)i * DDIM, lnb + (size_t)i * DDIM);
        k_mma<0, 64, 128, 8, 3><<<dim3(MT64, 2 * DIN / 128), 256, SMEM_64x128P3>>>(
            hnh, hnl, DDIM, ipwh + (size_t)i * 2 * DIN * DDIM, ipwl + (size_t)i * 2 * DIN * DDIM, DDIM,
            DDIM / 64, nullptr, nullptr, nullptr, nullptr, nullptr,
            xz, 2 * DIN, nullptr, nullptr, nullptr, BL, 2 * DIN);
        k_conv<<<(BL * DIN + 255) / 256, 256>>>(cw + (size_t)i * DIN * DCONV, cb + (size_t)i * DIN);
        k_mma<3, 64, 64, 8, 3><<<dim3(MT64, NXPP / 64), 256, SMEM_64x64P3>>>(
            xih, xil, DIN, wch + (size_t)i * NXPP * DIN, wcl + (size_t)i * NXPP * DIN, DIN,
            DIN / 64, dpb + (size_t)i * DIN, nullptr, nullptr, nullptr, nullptr,
            dtb, DIN, bc, nullptr, nullptr, BL, NXP);
        k_scan<<<BB * 6, 128>>>(alog + (size_t)i * DIN * DSN, Dp + (size_t)i * DIN);
        k_mma<0, 64, 64, 8, 3><<<dim3(MT64, DDIM / 64), 256, SMEM_64x64P3>>>(
            uh, ul, DIN, opwh + (size_t)i * DDIM * DIN, opwl + (size_t)i * DDIM * DIN, DIN,
            DIN / 64, nullptr, nullptr, nullptr, nullptr, nullptr,
            hb, DDIM, nullptr, nullptr, nullptr, BL, DDIM);
    }

    /* final norms + outputs */
    k_final<<<BL, 128>>>(out, nfw, nfb, n2w, n2b);
    k_maskout<<<1, 256>>>(mask, out, out_size);
}

// round 9
// speedup vs baseline: 4.2625x; 1.0774x over previous
#include <cuda_runtime.h>
#include <cuda_bf16.h>
#include <cuda_fp16.h>
#include <math.h>
#include <stdint.h>

#define BB 8
#define GG 256
#define NPTS 32
#define FEAT 273
#define CH 546
#define ENCD 384
#define DDIM 384
#define DEPTH 12
#define DIN 768
#define DSN 16
#define DCONV 4
#define DTR 24
#define GVIS 103
#define SEQL 103
#define BL (BB*GVIS)        /* 824 rows */
#define BLP 896             /* buffer pad */
#define BGC (BB*GG)         /* 2048 groups */
#define NCOL (BGC*NPTS)     /* 65536 point columns */
#define NMASK 153
#define OUTH (BL*DDIM)      /* 316416 */
#define NXP (DIN + 2*DSN)   /* 800 */
#define NXPP 896            /* padded */
#define K1P 320             /* FEAT 273 -> padded */
#define M1P 640             /* CH 546 -> padded  */
#define K2P 576             /* CH 546 -> padded  */
#define EPSV 1e-5f

/* ------------------------- scratch (device globals) ------------------------ */
__device__ float g_biaseff[(size_t)CH * BGC];
__device__ float g_tokens[(size_t)BGC * ENCD];
__device__ int   g_vis[BL];
__device__ float g_h[BL * DDIM];
__device__ float g_res[BL * DDIM];
__device__ float g_xz[BL * 2 * DIN];
__device__ float g_xi[BL * DIN];
__device__ float g_dt[BL * DIN];
__device__ float g_bc[BL * 2 * DSN];

/* fp16 encoder operands */
__device__ __align__(256) __half g_fgh[(size_t)BGC * K1P];
__device__ __align__(256) __half g_w0h[(size_t)M1P * K1P];
__device__ __align__(256) __half g_w0l[(size_t)M1P * K1P];
__device__ __align__(256) __half g_nbh[(size_t)NCOL * K1P];
__device__ __align__(256) __half g_w1h[(size_t)M1P * K1P];
__device__ __align__(256) __half g_w1l[(size_t)M1P * K1P];
__device__ __align__(256) __half g_w2h[(size_t)ENCD * K2P];
__device__ __align__(256) __half g_w2l[(size_t)ENCD * K2P];
__device__ __align__(256) __half g_h1h[(size_t)NCOL * K2P];

/* mamba operands: in/out_proj fp16 2-pass, xproj bf16 3-pass */
__device__ __align__(256) __half g_ipwh[(size_t)DEPTH * 2 * DIN * DDIM];
__device__ __align__(256) __half g_opwh[(size_t)DEPTH * DDIM * DIN];
__device__ __align__(256) __half g_hnh[(size_t)BLP * DDIM];
__device__ __align__(256) __half g_hnl[(size_t)BLP * DDIM];
__device__ __align__(256) __half g_uh[(size_t)BLP * DIN];
__device__ __align__(256) __half g_ul[(size_t)BLP * DIN];
__device__ __align__(256) __nv_bfloat16 g_wch[(size_t)DEPTH * NXPP * DIN];
__device__ __align__(256) __nv_bfloat16 g_wcl[(size_t)DEPTH * NXPP * DIN];
__device__ __align__(256) __nv_bfloat16 g_xih[(size_t)BLP * DIN];
__device__ __align__(256) __nv_bfloat16 g_xil[(size_t)BLP * DIN];

/* ------------------------------ small helpers ----------------------------- */
__device__ __forceinline__ float siluf(float x) { return x / (1.f + expf(-x)); }
__device__ __forceinline__ float geluf(float x) { return 0.5f * x * (1.f + erff(x * 0.70710678118654752f)); }
__device__ __forceinline__ float softplusf(float x) { return (x > 20.f) ? x : log1pf(expf(x)); }
__device__ __forceinline__ void split2(float v, __nv_bfloat16* h, __nv_bfloat16* l) {
    __nv_bfloat16 hh = __float2bfloat16(v);
    *h = hh;
    *l = __float2bfloat16(v - __bfloat162float(hh));
}
__device__ __forceinline__ void split2h(float v, __half* h, __half* l) {
    __half hh = __float2half(v);
    *h = hh;
    *l = __float2half(v - __half2float(hh));
}

__device__ __forceinline__ void reduce2_128(float& s1, float& s2) {
    #pragma unroll
    for (int o = 16; o; o >>= 1) {
        s1 += __shfl_xor_sync(0xffffffffu, s1, o);
        s2 += __shfl_xor_sync(0xffffffffu, s2, o);
    }
    __shared__ float ra[4], rb[4];
    int w = threadIdx.x >> 5, l = threadIdx.x & 31;
    if (l == 0) { ra[w] = s1; rb[w] = s2; }
    __syncthreads();
    s1 = ra[0] + ra[1] + ra[2] + ra[3];
    s2 = rb[0] + rb[1] + rb[2] + rb[3];
    __syncthreads();
}

/* --------------------------- PTX wrappers --------------------------------- */
__device__ __forceinline__ uint32_t smem_u32(const void* p) {
    uint32_t a;
    asm("{ .reg .u64 t; cvta.to.shared.u64 t, %1; cvt.u32.u64 %0, t; }" : "=r"(a) : "l"(p));
    return a;
}
#define SWZ128(o) ((o) ^ (((o) >> 3) & 0x70))
#define CP_ASYNC16(d, s) asm volatile("cp.async.cg.shared.global [%0], [%1], 16;" :: "r"(d), "l"(s))
#define CP_COMMIT()      asm volatile("cp.async.commit_group;" ::: "memory")
#define CP_WAIT1()       asm volatile("cp.async.wait_group 1;" ::: "memory")
#define CP_WAIT0()       asm volatile("cp.async.wait_group 0;" ::: "memory")

__device__ __forceinline__ void ldm_x4(uint32_t* r, uint32_t addr) {
    asm volatile("ldmatrix.sync.aligned.m8n8.x4.shared.b16 {%0,%1,%2,%3}, [%4];"
        : "=r"(r[0]), "=r"(r[1]), "=r"(r[2]), "=r"(r[3]) : "r"(addr));
}
__device__ __forceinline__ void mma_bf16(float* c, const uint32_t* a, uint32_t b0, uint32_t b1) {
    asm volatile("mma.sync.aligned.m16n8k16.row.col.f32.bf16.bf16.f32 "
        "{%0,%1,%2,%3}, {%4,%5,%6,%7}, {%8,%9}, {%0,%1,%2,%3};"
        : "+f"(c[0]), "+f"(c[1]), "+f"(c[2]), "+f"(c[3])
        : "r"(a[0]), "r"(a[1]), "r"(a[2]), "r"(a[3]), "r"(b0), "r"(b1));
}
__device__ __forceinline__ void mma_fp16(float* c, const uint32_t* a, uint32_t b0, uint32_t b1) {
    asm volatile("mma.sync.aligned.m16n8k16.row.col.f32.f16.f16.f32 "
        "{%0,%1,%2,%3}, {%4,%5,%6,%7}, {%8,%9}, {%0,%1,%2,%3};"
        : "+f"(c[0]), "+f"(c[1]), "+f"(c[2]), "+f"(c[3])
        : "r"(a[0]), "r"(a[1]), "r"(a[2]), "r"(a[3]), "r"(b0), "r"(b1));
}

/* =================== generic split mma.sync GEMM ===========================
 * PASS==3: bf16, A h/l + B h/l, D = AhBh + AhBl + AlBh
 * PASS==2: fp16, A h/l + B h only, D = AhBh + AlBh
 * D[M,N] = A[M,K] * B[N,K]^T  (K-major, ld = Kpad, elements 2 bytes)
 * grid = (Mtiles, Ntiles); NW warps (8: 2x4, 16: 4x4). CTA tile TM x TN.
 * EPI 0: C[m*ldc+n] = v               (m<Mv, n<Nv)
 * EPI 1: v+=be[m*BGC+grp]; BN+relu -> O1 (fp16 single, staged) [n*K2P+m]
 * EPI 2: group maxpool + p0[m] -> C[grp*ENCD+m]  (TN=128 only)
 * EPI 3: n<DIN: C[m*DIN+n]=softplus(v+p0[n]); n<NXP: C2[m*32+n-DIN]=v
 * ========================================================================= */
template<int EPI, int TM, int TN, int NW, int PASS>
__global__ __launch_bounds__(NW * 32) void k_mma(
    const __nv_bfloat16* __restrict__ Ah, const __nv_bfloat16* __restrict__ Al, int lda,
    const __nv_bfloat16* __restrict__ Bh, const __nv_bfloat16* __restrict__ Bl, int ldb,
    int NKC,
    const float* __restrict__ p0, const float* __restrict__ p1,
    const float* __restrict__ p2, const float* __restrict__ p3,
    const float* __restrict__ p4,
    float* __restrict__ C, int ldc, float* __restrict__ C2,
    __nv_bfloat16* __restrict__ O1, __nv_bfloat16* __restrict__ O2,
    int Mv, int Nv)
{
    constexpr int THREADS = NW * 32;
    constexpr int WR = NW / 4;
    constexpr int WC = 4;
    constexpr int WM = TM / WR;
    constexpr int WN = TN / WC;
    constexpr int MI = WM / 16;
    constexpr int NJ = WN / 8;
    constexpr int NB2 = (NJ + 1) / 2;
    constexpr int LA = TM * 8 / THREADS;
    constexpr int LB = TN * 8 / THREADS;
    constexpr uint32_t ABY = TM * 128;
    constexpr uint32_t BBY = TN * 128;
    constexpr uint32_t BUFSZ = (PASS == 3) ? (2 * ABY + 2 * BBY) : (2 * ABY + BBY);

    extern __shared__ __align__(1024) char smem[];
    const uint32_t sb = smem_u32(smem);
    const int tid = threadIdx.x, wid = tid >> 5, lid = tid & 31;
    const int wrow = wid >> 2, wcol = wid & 3;
    const int quad = lid >> 2, tq = lid & 3;
    const int m0 = blockIdx.x * TM, n0 = blockIdx.y * TN;

    const int lrow = (lid & 7) + 8 * ((lid >> 3) & 1);
    const int lk   = 8 * (lid >> 4);

    float acc[MI][NJ][4];
    #pragma unroll
    for (int i = 0; i < MI; i++)
        #pragma unroll
        for (int j = 0; j < NJ; j++)
            #pragma unroll
            for (int k = 0; k < 4; k++) acc[i][j][k] = 0.f;

    auto loadChunk = [&](int kc, int c) {
        const uint32_t bufb = sb + c * BUFSZ;
        #pragma unroll
        for (int p = 0; p < LA; p++) {
            int idx = tid + p * THREADS;
            int row = idx >> 3, c16 = idx & 7;
            uint32_t sw = SWZ128((uint32_t)(row * 128 + c16 * 16));
            const void* gh = Ah + (size_t)(m0 + row) * lda + kc * 64 + c16 * 8;
            const void* gl = Al + (size_t)(m0 + row) * lda + kc * 64 + c16 * 8;
            CP_ASYNC16(bufb + sw, gh);
            CP_ASYNC16(bufb + ABY + sw, gl);
        }
        #pragma unroll
        for (int p = 0; p < LB; p++) {
            int idx = tid + p * THREADS;
            int row = idx >> 3, c16 = idx & 7;
            uint32_t sw = SWZ128((uint32_t)(row * 128 + c16 * 16));
            const void* gh = Bh + (size_t)(n0 + row) * ldb + kc * 64 + c16 * 8;
            CP_ASYNC16(bufb + 2 * ABY + sw, gh);
            if (PASS == 3) {
                const void* gl = Bl + (size_t)(n0 + row) * ldb + kc * 64 + c16 * 8;
                CP_ASYNC16(bufb + 2 * ABY + BBY + sw, gl);
            }
        }
        CP_COMMIT();
    };

    loadChunk(0, 0);
    if (NKC > 1) loadChunk(1, 1); else CP_COMMIT();

    for (int kc = 0; kc < NKC; kc++) {
        const int c = kc & 1;
        if (kc + 1 < NKC) CP_WAIT1(); else CP_WAIT0();
        __syncthreads();
        const uint32_t ahb = sb + c * BUFSZ;
        const uint32_t alb = ahb + ABY;
        const uint32_t bhb = ahb + 2 * ABY;
        const uint32_t blb = bhb + BBY;
        #pragma unroll
        for (int ks = 0; ks < 4; ks++) {
            const int k0 = ks * 16 + lk;
            uint32_t fah[MI][4], fal[MI][4], fbh[NB2][4], fbl[NB2][4];
            #pragma unroll
            for (int bi = 0; bi < MI; bi++) {
                int r = wrow * WM + bi * 16 + lrow;
                ldm_x4(fah[bi], ahb + SWZ128((uint32_t)(r * 128 + k0 * 2)));
                ldm_x4(fal[bi], alb + SWZ128((uint32_t)(r * 128 + k0 * 2)));
            }
            #pragma unroll
            for (int bj2 = 0; bj2 < NB2; bj2++) {
                int r = wcol * WN + bj2 * 16 + lrow;
                ldm_x4(fbh[bj2], bhb + SWZ128((uint32_t)(r * 128 + k0 * 2)));
                if (PASS == 3)
                    ldm_x4(fbl[bj2], blb + SWZ128((uint32_t)(r * 128 + k0 * 2)));
            }
            #pragma unroll
            for (int bi = 0; bi < MI; bi++) {
                #pragma unroll
                for (int bj = 0; bj < NJ; bj++) {
                    uint32_t bh0 = fbh[bj >> 1][bj & 1], bh1 = fbh[bj >> 1][2 + (bj & 1)];
                    if (PASS == 3) {
                        uint32_t bl0 = fbl[bj >> 1][bj & 1], bl1 = fbl[bj >> 1][2 + (bj & 1)];
                        mma_bf16(acc[bi][bj], fah[bi], bh0, bh1);
                        mma_bf16(acc[bi][bj], fah[bi], bl0, bl1);
                        mma_bf16(acc[bi][bj], fal[bi], bh0, bh1);
                    } else {
                        mma_fp16(acc[bi][bj], fah[bi], bh0, bh1);
                        mma_fp16(acc[bi][bj], fal[bi], bh0, bh1);
                    }
                }
            }
        }
        __syncthreads();
        if (kc + 2 < NKC) loadChunk(kc + 2, c);
    }

    const int grp = (n0 >> 5) + wcol;

    if (EPI == 1) {
        /* staged transposed fp16 store (TM=TN=128): O1[n*K2P+m] */
        const int LDE = 136;
        __half* sh = (__half*)smem;
        const int mlim = (CH - m0 < 128) ? (CH - m0) : 128;
        #pragma unroll
        for (int bi = 0; bi < MI; bi++) {
            #pragma unroll
            for (int h0 = 0; h0 < 2; h0++) {
                const int ml = wrow * WM + bi * 16 + quad + 8 * h0;
                const int m = m0 + ml;
                if (m < CH) {
                    const float be = p0[(size_t)m * BGC + grp];
                    const float bnm = p1[m];
                    const float sc  = rsqrtf(p2[m] + EPSV) * p3[m];
                    const float bb  = p4[m];
                    #pragma unroll
                    for (int bj = 0; bj < NJ; bj++) {
                        #pragma unroll
                        for (int e = 0; e < 2; e++) {
                            int nl = wcol * WN + bj * 8 + 2 * tq + e;
                            float v = acc[bi][bj][h0 * 2 + e] + be;
                            v = fmaxf((v - bnm) * sc + bb, 0.f);
                            sh[nl * LDE + ml] = __float2half(v);
                        }
                    }
                }
            }
        }
        __syncthreads();
        __half* O1h = (__half*)O1;
        for (int idx = tid; idx < 128 * 16; idx += THREADS) {
            int nl = idx >> 4, ch = idx & 15;
            int mbeg = ch * 8;
            if (mbeg < mlim) {
                size_t gbase = (size_t)(n0 + nl) * K2P + m0 + mbeg;
                if (mbeg + 8 <= mlim) {
                    *(uint4*)(&O1h[gbase]) = *(const uint4*)(&sh[nl * LDE + mbeg]);
                } else {
                    for (int t = 0; t < mlim - mbeg; t++)
                        O1h[gbase + t] = sh[nl * LDE + mbeg + t];
                }
            }
        }
        return;
    }

    #pragma unroll
    for (int bi = 0; bi < MI; bi++) {
        #pragma unroll
        for (int h0 = 0; h0 < 2; h0++) {
            const int m = m0 + wrow * WM + bi * 16 + quad + 8 * h0;
            if (EPI == 2) {
                float vm = -INFINITY;
                #pragma unroll
                for (int bj = 0; bj < NJ; bj++) {
                    vm = fmaxf(vm, acc[bi][bj][h0 * 2]);
                    vm = fmaxf(vm, acc[bi][bj][h0 * 2 + 1]);
                }
                vm = fmaxf(vm, __shfl_xor_sync(0xffffffffu, vm, 1));
                vm = fmaxf(vm, __shfl_xor_sync(0xffffffffu, vm, 2));
                if (tq == 0) C[(size_t)grp * ENCD + m] = vm + p0[m];
            } else if (EPI == 0) {
                if (m < Mv) {
                    #pragma unroll
                    for (int bj = 0; bj < NJ; bj++) {
                        #pragma unroll
                        for (int e = 0; e < 2; e++) {
                            int n = n0 + wcol * WN + bj * 8 + 2 * tq + e;
                            if (n < Nv) C[(size_t)m * ldc + n] = acc[bi][bj][h0 * 2 + e];
                        }
                    }
                }
            } else { /* EPI 3 */
                if (m < Mv) {
                    #pragma unroll
                    for (int bj = 0; bj < NJ; bj++) {
                        #pragma unroll
                        for (int e = 0; e < 2; e++) {
                            int n = n0 + wcol * WN + bj * 8 + 2 * tq + e;
                            float v = acc[bi][bj][h0 * 2 + e];
                            if (n < DIN) C[(size_t)m * DIN + n] = softplusf(v + p0[n]);
                            else if (n < NXP) C2[(size_t)m * (2 * DSN) + (n - DIN)] = v;
                        }
                    }
                }
            }
        }
    }
}

/* --------------------------- split / convert prepasses --------------------- */
__global__ void k_split(const float* __restrict__ src, int sld, int soff,
                        int R, int K, __nv_bfloat16* __restrict__ dh,
                        __nv_bfloat16* __restrict__ dl, int Kp, long long total) {
    long long i = (long long)blockIdx.x * 256 + threadIdx.x;
    if (i >= total) return;
    int k = (int)(i % Kp);
    long long r = i / Kp;
    float v = (r < R && k < K) ? src[r * sld + soff + k] : 0.f;
    split2(v, &dh[i], &dl[i]);
}
__global__ void k_split_h2(const float* __restrict__ src, int sld, int soff,
                           int R, int K, __half* __restrict__ dh,
                           __half* __restrict__ dl, int Kp, long long total) {
    long long i = (long long)blockIdx.x * 256 + threadIdx.x;
    if (i >= total) return;
    int k = (int)(i % Kp);
    long long r = i / Kp;
    float v = (r < R && k < K) ? src[r * sld + soff + k] : 0.f;
    split2h(v, &dh[i], &dl[i]);
}
/* vectorized padded fp32->fp16: 8 halves/thread (Kp % 8 == 0) */
__global__ void k_split_h1v(const float* __restrict__ src, int sld, int soff,
                            int R, int K, __half* __restrict__ dh,
                            int Kp, long long total8) {
    long long i = (long long)blockIdx.x * 256 + threadIdx.x;
    if (i >= total8) return;
    long long base = i * 8;
    int k = (int)(base % Kp);
    long long r = base / Kp;
    const float* sr = src + r * sld + soff;
    __half hb[8];
    #pragma unroll
    for (int j = 0; j < 8; j++)
        hb[j] = __float2half((r < R && (k + j) < K) ? sr[k + j] : 0.f);
    *(uint4*)(dh + base) = *(const uint4*)hb;
}
/* contiguous fp32 -> fp16, 8/thread */
__global__ void k_cvt8(const float* __restrict__ src, __half* __restrict__ dst,
                       long long total8) {
    long long i = (long long)blockIdx.x * 256 + threadIdx.x;
    if (i >= total8) return;
    const float4* s = (const float4*)src + i * 2;
    float4 a = s[0], b = s[1];
    __half hb[8] = {
        __float2half(a.x), __float2half(a.y), __float2half(a.z), __float2half(a.w),
        __float2half(b.x), __float2half(b.y), __float2half(b.z), __float2half(b.w)
    };
    *(uint4*)(dst + i * 8) = *(const uint4*)hb;
}

__global__ void k_wcomb(const float* __restrict__ dpw, const float* __restrict__ xpw) {
    long long idx = (long long)blockIdx.x * 256 + threadIdx.x;
    if (idx >= (long long)DEPTH * NXPP * DIN) return;
    int col = (int)(idx % DIN);
    int rem = (int)(idx / DIN);
    int row = rem % NXPP;
    int l   = rem / NXPP;
    const float* xp = xpw + (size_t)l * (DTR + 2 * DSN) * DIN;
    float v = 0.f;
    if (row < DIN) {
        const float* dr = dpw + (size_t)l * DIN * DTR + (size_t)row * DTR;
        #pragma unroll
        for (int t = 0; t < DTR; t++) v = fmaf(dr[t], xp[(size_t)t * DIN + col], v);
    } else if (row < NXP) {
        v = xp[(size_t)(DTR + (row - DIN)) * DIN + col];
    }
    split2(v, &g_wch[idx], &g_wcl[idx]);
}

__global__ void k_h1pad() {
    int n = blockIdx.x * 8 + (threadIdx.x >> 5);
    int j = threadIdx.x & 31;
    if (j < (K2P - CH))
        g_h1h[(size_t)n * K2P + CH + j] = __float2half(0.f);
}

/* ---------- encoder: per-group feature max -> fp16 [bg][K1P] --------------- */
__global__ void k_fg(const float* __restrict__ nb) {
    __shared__ float s[NPTS * FEAT];
    int bg = blockIdx.x;
    const float* src = nb + (size_t)bg * NPTS * FEAT;
    for (int t = threadIdx.x; t < NPTS * FEAT; t += blockDim.x) s[t] = src[t];
    __syncthreads();
    for (int c = threadIdx.x; c < K1P; c += blockDim.x) {
        float m = 0.f;
        if (c < FEAT) {
            m = s[c];
            #pragma unroll
            for (int n = 1; n < NPTS; n++) m = fmaxf(m, s[n * FEAT + c]);
        }
        g_fgh[(size_t)bg * K1P + c] = __float2half(m);
    }
}

/* ---------------- visible-index extraction (bool width-robust) ------------ */
__global__ void k_visidx(const unsigned char* __restrict__ m8) {
    if (threadIdx.x != 0) return;
    int b = blockIdx.x;
    int c8 = 0;
    for (int g = 0; g < GG; g++) c8 += (m8[(size_t)b * GG + g] != 0);
    int cnt = 0;
    if (c8 == NMASK) {
        for (int g = 0; g < GG; g++)
            if (!m8[(size_t)b * GG + g]) { if (cnt < GVIS) g_vis[b * GVIS + cnt] = g; cnt++; }
    } else {
        const int* m32 = (const int*)m8;
        for (int g = 0; g < GG; g++)
            if (!m32[(size_t)b * GG + g]) { if (cnt < GVIS) g_vis[b * GVIS + cnt] = g; cnt++; }
    }
}

/* ------------- gather tokens/centers + pos MLP -> initial h ---------------- */
__global__ void k_pos(const float* __restrict__ center,
                      const float* __restrict__ w1, const float* __restrict__ b1,
                      const float* __restrict__ w2, const float* __restrict__ b2) {
    __shared__ float hcache[128];
    __shared__ float cc[3];
    int r = blockIdx.x;
    int b = r / GVIS;
    int g = g_vis[r];
    int tid = threadIdx.x;
    if (tid < 3) cc[tid] = center[((size_t)b * GG + g) * 3 + tid];
    __syncthreads();
    float a = w1[tid * 3] * cc[0] + w1[tid * 3 + 1] * cc[1] + w1[tid * 3 + 2] * cc[2] + b1[tid];
    hcache[tid] = geluf(a);
    __syncthreads();
    const float* tok = g_tokens + ((size_t)b * GG + g) * ENCD;
    for (int e = tid; e < DDIM; e += 128) {
        float acc = b2[e];
        const float* wr = w2 + (size_t)e * 128;
        #pragma unroll 8
        for (int k = 0; k < 128; k++) acc = fmaf(wr[k], hcache[k], acc);
        g_h[(size_t)r * DDIM + e] = acc + tok[e];
    }
}

/* ------------- residual accumulate + LayerNorm -> split fp16 --------------- */
__global__ void k_lnres(int layer, const float* __restrict__ w, const float* __restrict__ b) {
    int r = blockIdx.x, tid = threadIdx.x;
    float* res = g_res + (size_t)r * DDIM;
    const float* h = g_h + (size_t)r * DDIM;
    float v[3], s1 = 0.f, s2 = 0.f;
    #pragma unroll
    for (int i = 0; i < 3; i++) {
        int c = tid + i * 128;
        float x = h[c];
        if (layer > 0) x += res[c];
        v[i] = x; res[c] = x;
        s1 += x; s2 += x * x;
    }
    reduce2_128(s1, s2);
    float mu = s1 * (1.f / DDIM);
    float rstd = rsqrtf(s2 * (1.f / DDIM) - mu * mu + EPSV);
    #pragma unroll
    for (int i = 0; i < 3; i++) {
        int c = tid + i * 128;
        float y = (v[i] - mu) * rstd * w[c] + b[c];
        split2h(y, &g_hnh[(size_t)r * DDIM + c], &g_hnl[(size_t)r * DDIM + c]);
    }
}

/* ---------------- depthwise causal conv (k=4) + SiLU -> bf16 split --------- */
__global__ void k_conv(const float* __restrict__ cw, const float* __restrict__ cb) {
    int idx = blockIdx.x * blockDim.x + threadIdx.x;
    if (idx >= BL * DIN) return;
    int d = idx % DIN, r = idx / DIN;
    int b = r / SEQL, l = r % SEQL;
    float acc = cb[d];
    #pragma unroll
    for (int k = 0; k < DCONV; k++) {
        int ll = l - (DCONV - 1) + k;
        if (ll >= 0) acc = fmaf(cw[d * DCONV + k], g_xz[((size_t)(b * SEQL + ll)) * (2 * DIN) + d], acc);
    }
    float y = siluf(acc);
    g_xi[idx] = y;
    split2(y, &g_xih[idx], &g_xil[idx]);
}

/* --------------------------- selective scan -> fp16 split ------------------- */
struct ScanIn { float dt, x, z, bl[2 * DSN]; };
__device__ __forceinline__ void scan_load(ScanIn& s, int r, int d) {
    s.dt = g_dt[(size_t)r * DIN + d];
    s.x  = g_xi[(size_t)r * DIN + d];
    s.z  = g_xz[(size_t)r * (2 * DIN) + DIN + d];
    const float4* p = (const float4*)(g_bc + (size_t)r * (2 * DSN));
    #pragma unroll
    for (int i = 0; i < 8; i++) {
        float4 v = p[i];
        s.bl[4 * i] = v.x; s.bl[4 * i + 1] = v.y;
        s.bl[4 * i + 2] = v.z; s.bl[4 * i + 3] = v.w;
    }
}
__global__ void k_scan(const float* __restrict__ alog, const float* __restrict__ Dp) {
    int b = blockIdx.x / 6;
    int d = (blockIdx.x % 6) * 128 + threadIdx.x;
    float A[DSN];
    bool st = true;
    #pragma unroll
    for (int s = 0; s < DSN; s++) {
        A[s] = -expf(alog[(size_t)d * DSN + s]);
        if (fabsf(A[s] + (float)(s + 1)) > 1e-3f) st = false;
    }
    float Dd = Dp[d];
    float h[DSN];
    #pragma unroll
    for (int s = 0; s < DSN; s++) h[s] = 0.f;

    ScanIn cur, nxt;
    scan_load(cur, b * SEQL, d);
    for (int l = 0; l < SEQL; l++) {
        if (l + 1 < SEQL) scan_load(nxt, b * SEQL + l + 1, d);
        float dtx = cur.dt * cur.x;
        float y = 0.f;
        if (st) {
            float q = __expf(cur.dt * A[0]);
            float dA = q;
            #pragma unroll
            for (int s = 0; s < DSN; s++) {
                h[s] = fmaf(dA, h[s], dtx * cur.bl[s]);
                y = fmaf(h[s], cur.bl[DSN + s], y);
                dA *= q;
            }
        } else {
            #pragma unroll
            for (int s = 0; s < DSN; s++) {
                float dA = __expf(cur.dt * A[s]);
                h[s] = fmaf(dA, h[s], dtx * cur.bl[s]);
                y = fmaf(h[s], cur.bl[DSN + s], y);
            }
        }
        float u = (y + cur.x * Dd) * siluf(cur.z);
        size_t o = (size_t)(b * SEQL + l) * DIN + d;
        split2h(u, &g_uh[o], &g_ul[o]);
        cur = nxt;
    }
}

/* ----------------------- final residual + double LN ------------------------ */
__global__ void k_final(float* __restrict__ out,
                        const float* __restrict__ w1, const float* __restrict__ b1,
                        const float* __restrict__ w2, const float* __restrict__ b2) {
    int r = blockIdx.x, tid = threadIdx.x;
    float v[3], s1 = 0.f, s2 = 0.f;
    #pragma unroll
    for (int i = 0; i < 3; i++) {
        int c = tid + i * 128;
        float x = g_res[(size_t)r * DDIM + c] + g_h[(size_t)r * DDIM + c];
        v[i] = x; s1 += x; s2 += x * x;
    }
    reduce2_128(s1, s2);
    float mu = s1 * (1.f / DDIM);
    float rstd = rsqrtf(s2 * (1.f / DDIM) - mu * mu + EPSV);
    s1 = 0.f; s2 = 0.f;
    #pragma unroll
    for (int i = 0; i < 3; i++) {
        int c = tid + i * 128;
        v[i] = (v[i] - mu) * rstd * w1[c] + b1[c];
        s1 += v[i]; s2 += v[i] * v[i];
    }
    reduce2_128(s1, s2);
    mu = s1 * (1.f / DDIM);
    rstd = rsqrtf(s2 * (1.f / DDIM) - mu * mu + EPSV);
    #pragma unroll
    for (int i = 0; i < 3; i++) {
        int c = tid + i * 128;
        out[(size_t)r * DDIM + c] = (v[i] - mu) * rstd * w2[c] + b2[c];
    }
}

/* -------------------------- mask -> output tail ---------------------------- */
__global__ void k_maskout(const unsigned char* __restrict__ m8, float* __restrict__ out, int out_size) {
    if (out_size < OUTH + BB * GG) return;
    __shared__ int use8;
    if (threadIdx.x == 0) {
        int c = 0;
        for (int g = 0; g < GG; g++) c += (m8[g] != 0);
        use8 = (c == NMASK);
    }
    __syncthreads();
    const int* m32 = (const int*)m8;
    for (int i = threadIdx.x; i < BB * GG; i += blockDim.x) {
        float v = use8 ? (m8[i] ? 1.f : 0.f) : (m32[i] ? 1.f : 0.f);
        out[OUTH + i] = v;
    }
}

/* ------------------------------- host driver ------------------------------- */
#define SMEM_128P2 (2 * (2 * 16384 + 16384))       /* 98304 */
#define SMEM_64x128P2 (2 * (2 * 8192 + 16384))     /* 65536 */
#define SMEM_64x64P2 (2 * (2 * 8192 + 8192))       /* 49152 */
#define SMEM_64x64P3 (2 * (2 * 8192 + 2 * 8192))   /* 65536 */
#define MT64 13

extern "C" void kernel_launch(void* const* d_in, const int* in_sizes, int n_in,
                              void* d_out, int out_size) {
    (void)in_sizes; (void)n_in;
    const float* nb     = (const float*)d_in[0];
    const float* center = (const float*)d_in[1];
    const unsigned char* mask = (const unsigned char*)d_in[2];
    const float* c1w = (const float*)d_in[3];
    const float* c1b = (const float*)d_in[4];
    const float* bng = (const float*)d_in[5];
    const float* bnb = (const float*)d_in[6];
    const float* bnm = (const float*)d_in[7];
    const float* bnv = (const float*)d_in[8];
    const float* c2w = (const float*)d_in[9];
    const float* c2b = (const float*)d_in[10];
    const float* pw1 = (const float*)d_in[11];
    const float* pb1 = (const float*)d_in[12];
    const float* pw2 = (const float*)d_in[13];
    const float* pb2 = (const float*)d_in[14];
    const float* ipw = (const float*)d_in[15];
    const float* cw  = (const float*)d_in[16];
    const float* cb  = (const float*)d_in[17];
    const float* xpw = (const float*)d_in[18];
    const float* dpw = (const float*)d_in[19];
    const float* dpb = (const float*)d_in[20];
    const float* alog= (const float*)d_in[21];
    const float* Dp  = (const float*)d_in[22];
    const float* opw = (const float*)d_in[23];
    const float* lnw = (const float*)d_in[24];
    const float* lnb = (const float*)d_in[25];
    const float* nfw = (const float*)d_in[26];
    const float* nfb = (const float*)d_in[27];
    const float* n2w = (const float*)d_in[28];
    const float* n2b = (const float*)d_in[29];
    float* out = (float*)d_out;

    cudaFuncSetAttribute((const void*)k_mma<0, 64, 128, 8, 2>,  cudaFuncAttributeMaxDynamicSharedMemorySize, SMEM_64x128P2);
    cudaFuncSetAttribute((const void*)k_mma<1, 128, 128, 16, 2>, cudaFuncAttributeMaxDynamicSharedMemorySize, SMEM_128P2);
    cudaFuncSetAttribute((const void*)k_mma<2, 128, 128, 16, 2>, cudaFuncAttributeMaxDynamicSharedMemorySize, SMEM_128P2);
    cudaFuncSetAttribute((const void*)k_mma<0, 64, 64, 8, 2>,   cudaFuncAttributeMaxDynamicSharedMemorySize, SMEM_64x64P2);
    cudaFuncSetAttribute((const void*)k_mma<3, 64, 64, 8, 3>,   cudaFuncAttributeMaxDynamicSharedMemorySize, SMEM_64x64P3);

    float *be, *tok, *xz, *xi, *dtb, *bc, *hb;
    cudaGetSymbolAddress((void**)&be,  g_biaseff);
    cudaGetSymbolAddress((void**)&tok, g_tokens);
    cudaGetSymbolAddress((void**)&xz,  g_xz);
    cudaGetSymbolAddress((void**)&xi,  g_xi);
    cudaGetSymbolAddress((void**)&dtb, g_dt);
    cudaGetSymbolAddress((void**)&bc,  g_bc);
    cudaGetSymbolAddress((void**)&hb,  g_h);
    __half *fgh, *w0h, *w0l, *nbh, *w1h, *w1l, *w2h, *w2l, *h1h;
    __half *ipwh, *opwh, *hnh, *hnl, *uh, *ul;
    __nv_bfloat16 *wch, *wcl, *xih, *xil;
    cudaGetSymbolAddress((void**)&fgh, g_fgh);
    cudaGetSymbolAddress((void**)&w0h, g_w0h);  cudaGetSymbolAddress((void**)&w0l, g_w0l);
    cudaGetSymbolAddress((void**)&nbh, g_nbh);
    cudaGetSymbolAddress((void**)&w1h, g_w1h);  cudaGetSymbolAddress((void**)&w1l, g_w1l);
    cudaGetSymbolAddress((void**)&w2h, g_w2h);  cudaGetSymbolAddress((void**)&w2l, g_w2l);
    cudaGetSymbolAddress((void**)&h1h, g_h1h);
    cudaGetSymbolAddress((void**)&ipwh, g_ipwh);
    cudaGetSymbolAddress((void**)&opwh, g_opwh);
    cudaGetSymbolAddress((void**)&wch, g_wch);  cudaGetSymbolAddress((void**)&wcl, g_wcl);
    cudaGetSymbolAddress((void**)&hnh, g_hnh);  cudaGetSymbolAddress((void**)&hnl, g_hnl);
    cudaGetSymbolAddress((void**)&xih, g_xih);  cudaGetSymbolAddress((void**)&xil, g_xil);
    cudaGetSymbolAddress((void**)&uh,  g_uh);   cudaGetSymbolAddress((void**)&ul,  g_ul);

    auto splitN = [](long long total) { return (int)((total + 255) / 256); };
    long long tW1 = (long long)M1P * K1P;
    long long tNB8 = (long long)NCOL * K1P / 8;
    long long tW2 = (long long)ENCD * K2P;

    /* launches 1-5 (so GEMM1 is launch #6 for ncu -s 5 -c 1) */
    k_split_h2<<<splitN(tW1), 256>>>(c1w, 2 * FEAT, 0, CH, FEAT, w0h, w0l, K1P, tW1);
    k_fg<<<BGC, 256>>>(nb);
    k_mma<0, 64, 128, 8, 2><<<dim3(M1P / 64, BGC / 128), 256, SMEM_64x128P2>>>(
        (const __nv_bfloat16*)w0h, (const __nv_bfloat16*)w0l, K1P,
        (const __nv_bfloat16*)fgh, nullptr, K1P, K1P / 64,
        nullptr, nullptr, nullptr, nullptr, nullptr,
        be, BGC, nullptr, nullptr, nullptr, CH, BGC);
    k_split_h1v<<<splitN(tNB8), 256>>>(nb, FEAT, 0, NCOL, FEAT, nbh, K1P, tNB8);
    k_split_h2<<<splitN(tW1), 256>>>(c1w, 2 * FEAT, FEAT, CH, FEAT, w1h, w1l, K1P, tW1);

    /* launch #6: GEMM1 D[640,65536] -> H1 fp16 (profiled) */
    k_mma<1, 128, 128, 16, 2><<<dim3(M1P / 128, NCOL / 128), 512, SMEM_128P2>>>(
        (const __nv_bfloat16*)w1h, (const __nv_bfloat16*)w1l, K1P,
        (const __nv_bfloat16*)nbh, nullptr, K1P, K1P / 64,
        be, bnm, bnv, bng, bnb, nullptr, 0, nullptr,
        (__nv_bfloat16*)h1h, nullptr, CH, NCOL);

    k_h1pad<<<NCOL / 8, 256>>>();
    k_split_h2<<<splitN(tW2), 256>>>(c2w, CH, 0, ENCD, CH, w2h, w2l, K2P, tW2);

    /* GEMM2: D[384,65536] -> tokens (fused maxpool) */
    k_mma<2, 128, 128, 16, 2><<<dim3(ENCD / 128, NCOL / 128), 512, SMEM_128P2>>>(
        (const __nv_bfloat16*)w2h, (const __nv_bfloat16*)w2l, K2P,
        (const __nv_bfloat16*)h1h, nullptr, K2P, K2P / 64,
        c2b, nullptr, nullptr, nullptr, nullptr, tok, 0, nullptr, nullptr, nullptr, ENCD, NCOL);

    /* mamba weight prepasses */
    long long tIP8 = (long long)DEPTH * 2 * DIN * DDIM / 8;
    k_cvt8<<<splitN(tIP8), 256>>>(ipw, ipwh, tIP8);
    long long tOP8 = (long long)DEPTH * DDIM * DIN / 8;
    k_cvt8<<<splitN(tOP8), 256>>>(opw, opwh, tOP8);
    k_wcomb<<<splitN((long long)DEPTH * NXPP * DIN), 256>>>(dpw, xpw);

    /* gather + pos embed */
    k_visidx<<<BB, 32>>>(mask);
    k_pos<<<BL, 128>>>(center, pw1, pb1, pw2, pb2);

    /* mamba stack */
    for (int i = 0; i < DEPTH; i++) {
        k_lnres<<<BL, 128>>>(i, lnw + (size_t)i * DDIM, lnb + (size_t)i * DDIM);
        /* in_proj (fp16 2-pass) */
        k_mma<0, 64, 128, 8, 2><<<dim3(MT64, 2 * DIN / 128), 256, SMEM_64x128P2>>>(
            (const __nv_bfloat16*)hnh, (const __nv_bfloat16*)hnl, DDIM,
            (const __nv_bfloat16*)(ipwh + (size_t)i * 2 * DIN * DDIM), nullptr, DDIM,
            DDIM / 64, nullptr, nullptr, nullptr, nullptr, nullptr,
            xz, 2 * DIN, nullptr, nullptr, nullptr, BL, 2 * DIN);
        k_conv<<<(BL * DIN + 255) / 256, 256>>>(cw + (size_t)i * DIN * DCONV, cb + (size_t)i * DIN);
        /* merged x_proj+dt_proj (bf16 3-pass, precision-critical dt path) */
        k_mma<3, 64, 64, 8, 3><<<dim3(MT64, NXPP / 64), 256, SMEM_64x64P3>>>(
            xih, xil, DIN, wch + (size_t)i * NXPP * DIN, wcl + (size_t)i * NXPP * DIN, DIN,
            DIN / 64, dpb + (size_t)i * DIN, nullptr, nullptr, nullptr, nullptr,
            dtb, DIN, bc, nullptr, nullptr, BL, NXP);
        k_scan<<<BB * 6, 128>>>(alog + (size_t)i * DIN * DSN, Dp + (size_t)i * DIN);
        /* out_proj (fp16 2-pass) */
        k_mma<0, 64, 64, 8, 2><<<dim3(MT64, DDIM / 64), 256, SMEM_64x64P2>>>(
            (const __nv_bfloat16*)uh, (const __nv_bfloat16*)ul, DIN,
            (const __nv_bfloat16*)(opwh + (size_t)i * DDIM * DIN), nullptr, DIN,
            DIN / 64, nullptr, nullptr, nullptr, nullptr, nullptr,
            hb, DDIM, nullptr, nullptr, nullptr, BL, DDIM);
    }

    /* final norms + outputs */
    k_final<<<BL, 128>>>(out, nfw, nfb, n2w, n2b);
    k_maskout<<<1, 256>>>(mask, out, out_size);
}

// round 10
// speedup vs baseline: 4.3092x; 1.0109x over previous
#include <cuda_runtime.h>
#include <cuda_bf16.h>
#include <cuda_fp16.h>
#include <math.h>
#include <stdint.h>

#define BB 8
#define GG 256
#define NPTS 32
#define FEAT 273
#define CH 546
#define ENCD 384
#define DDIM 384
#define DEPTH 12
#define DIN 768
#define DSN 16
#define DCONV 4
#define DTR 24
#define GVIS 103
#define SEQL 103
#define BL (BB*GVIS)        /* 824 rows */
#define BLP 896             /* buffer pad */
#define BGC (BB*GG)         /* 2048 groups */
#define NCOL (BGC*NPTS)     /* 65536 point columns */
#define NMASK 153
#define OUTH (BL*DDIM)      /* 316416 */
#define NXP (DIN + 2*DSN)   /* 800 */
#define NXPP 896            /* padded */
#define K1P 320             /* FEAT 273 -> padded */
#define M1P 640             /* CH 546 -> padded  */
#define K2P 576             /* CH 546 -> padded  */
#define EPSV 1e-5f

/* ------------------------- scratch (device globals) ------------------------ */
__device__ float g_biaseff[(size_t)CH * BGC];
__device__ float g_tokens[(size_t)BGC * ENCD];
__device__ int   g_vis[BL];
__device__ float g_h[BL * DDIM];
__device__ float g_res[BL * DDIM];
__device__ float g_xz[BL * 2 * DIN];
__device__ float g_xi[BL * DIN];
__device__ float g_dt[BL * DIN];
__device__ float g_bc[BL * 2 * DSN];

/* fp16 encoder operands */
__device__ __align__(256) __half g_fgh[(size_t)BGC * K1P];
__device__ __align__(256) __half g_w0h[(size_t)M1P * K1P];
__device__ __align__(256) __half g_w0l[(size_t)M1P * K1P];
__device__ __align__(256) __half g_nbh[(size_t)NCOL * K1P];
__device__ __align__(256) __half g_w1h[(size_t)M1P * K1P];
__device__ __align__(256) __half g_w1l[(size_t)M1P * K1P];
__device__ __align__(256) __half g_w2h[(size_t)ENCD * K2P];
__device__ __align__(256) __half g_w2l[(size_t)ENCD * K2P];
__device__ __align__(256) __half g_h1h[(size_t)NCOL * K2P];

/* fp16 mamba operands (all GEMMs 2-pass fp16 now) */
__device__ __align__(256) __half g_ipwh[(size_t)DEPTH * 2 * DIN * DDIM];
__device__ __align__(256) __half g_opwh[(size_t)DEPTH * DDIM * DIN];
__device__ __align__(256) __half g_wch[(size_t)DEPTH * NXPP * DIN];
__device__ __align__(256) __half g_hnh[(size_t)BLP * DDIM];
__device__ __align__(256) __half g_hnl[(size_t)BLP * DDIM];
__device__ __align__(256) __half g_xih[(size_t)BLP * DIN];
__device__ __align__(256) __half g_xil[(size_t)BLP * DIN];
__device__ __align__(256) __half g_uh[(size_t)BLP * DIN];
__device__ __align__(256) __half g_ul[(size_t)BLP * DIN];

/* ------------------------------ small helpers ----------------------------- */
__device__ __forceinline__ float siluf(float x) { return x / (1.f + expf(-x)); }
__device__ __forceinline__ float geluf(float x) { return 0.5f * x * (1.f + erff(x * 0.70710678118654752f)); }
__device__ __forceinline__ float softplusf(float x) { return (x > 20.f) ? x : log1pf(expf(x)); }
__device__ __forceinline__ void split2h(float v, __half* h, __half* l) {
    __half hh = __float2half(v);
    *h = hh;
    *l = __float2half(v - __half2float(hh));
}

__device__ __forceinline__ void reduce2_128(float& s1, float& s2) {
    #pragma unroll
    for (int o = 16; o; o >>= 1) {
        s1 += __shfl_xor_sync(0xffffffffu, s1, o);
        s2 += __shfl_xor_sync(0xffffffffu, s2, o);
    }
    __shared__ float ra[4], rb[4];
    int w = threadIdx.x >> 5, l = threadIdx.x & 31;
    if (l == 0) { ra[w] = s1; rb[w] = s2; }
    __syncthreads();
    s1 = ra[0] + ra[1] + ra[2] + ra[3];
    s2 = rb[0] + rb[1] + rb[2] + rb[3];
    __syncthreads();
}

/* --------------------------- PTX wrappers --------------------------------- */
__device__ __forceinline__ uint32_t smem_u32(const void* p) {
    uint32_t a;
    asm("{ .reg .u64 t; cvta.to.shared.u64 t, %1; cvt.u32.u64 %0, t; }" : "=r"(a) : "l"(p));
    return a;
}
#define SWZ128(o) ((o) ^ (((o) >> 3) & 0x70))
#define CP_ASYNC16(d, s) asm volatile("cp.async.cg.shared.global [%0], [%1], 16;" :: "r"(d), "l"(s))
#define CP_COMMIT()      asm volatile("cp.async.commit_group;" ::: "memory")
#define CP_WAIT1()       asm volatile("cp.async.wait_group 1;" ::: "memory")
#define CP_WAIT0()       asm volatile("cp.async.wait_group 0;" ::: "memory")

__device__ __forceinline__ void ldm_x4(uint32_t* r, uint32_t addr) {
    asm volatile("ldmatrix.sync.aligned.m8n8.x4.shared.b16 {%0,%1,%2,%3}, [%4];"
        : "=r"(r[0]), "=r"(r[1]), "=r"(r[2]), "=r"(r[3]) : "r"(addr));
}
__device__ __forceinline__ void mma_fp16(float* c, const uint32_t* a, uint32_t b0, uint32_t b1) {
    asm volatile("mma.sync.aligned.m16n8k16.row.col.f32.f16.f16.f32 "
        "{%0,%1,%2,%3}, {%4,%5,%6,%7}, {%8,%9}, {%0,%1,%2,%3};"
        : "+f"(c[0]), "+f"(c[1]), "+f"(c[2]), "+f"(c[3])
        : "r"(a[0]), "r"(a[1]), "r"(a[2]), "r"(a[3]), "r"(b0), "r"(b1));
}

/* =================== generic fp16 split mma.sync GEMM ======================
 * D[M,N] = A[M,K] * B[N,K]^T;  A = Ah + Al (fp16 split), B = Bh (single fp16)
 * D = AhBh + AlBh (2 passes, fp32 accumulate).
 * K-major, ld = Kpad. grid = (Mtiles, Ntiles), M fastest (B-tile L2 reuse).
 * NW warps (8: 2x4, 16: 4x4). CTA tile TM x TN.
 * EPI 0: C[m*ldc+n] = v               (m<Mv, n<Nv)
 * EPI 1: v+=be[m*BGC+grp]; BN+relu -> O1 fp16 staged [n*K2P+m]; zero-pads m>=CH
 * EPI 2: group maxpool + p0[m] -> C[grp*ENCD+m]  (TN=128 only)
 * EPI 3: n<DIN: C[m*DIN+n]=softplus(v+p0[n]); n<NXP: C2[m*32+n-DIN]=v
 * ========================================================================= */
template<int EPI, int TM, int TN, int NW>
__global__ __launch_bounds__(NW * 32) void k_mma(
    const __half* __restrict__ Ah, const __half* __restrict__ Al, int lda,
    const __half* __restrict__ Bh, int ldb,
    int NKC,
    const float* __restrict__ p0, const float* __restrict__ p1,
    const float* __restrict__ p2, const float* __restrict__ p3,
    const float* __restrict__ p4,
    float* __restrict__ C, int ldc, float* __restrict__ C2,
    __half* __restrict__ O1,
    int Mv, int Nv)
{
    constexpr int THREADS = NW * 32;
    constexpr int WR = NW / 4;
    constexpr int WC = 4;
    constexpr int WM = TM / WR;
    constexpr int WN = TN / WC;
    constexpr int MI = WM / 16;
    constexpr int NJ = WN / 8;
    constexpr int NB2 = (NJ + 1) / 2;
    constexpr int LA = TM * 8 / THREADS;
    constexpr int LB = TN * 8 / THREADS;
    constexpr uint32_t ABY = TM * 128;
    constexpr uint32_t BBY = TN * 128;
    constexpr uint32_t BUFSZ = 2 * ABY + BBY;

    extern __shared__ __align__(1024) char smem[];
    const uint32_t sb = smem_u32(smem);
    const int tid = threadIdx.x, wid = tid >> 5, lid = tid & 31;
    const int wrow = wid >> 2, wcol = wid & 3;
    const int quad = lid >> 2, tq = lid & 3;
    const int m0 = blockIdx.x * TM, n0 = blockIdx.y * TN;

    const int lrow = (lid & 7) + 8 * ((lid >> 3) & 1);
    const int lk   = 8 * (lid >> 4);

    float acc[MI][NJ][4];
    #pragma unroll
    for (int i = 0; i < MI; i++)
        #pragma unroll
        for (int j = 0; j < NJ; j++)
            #pragma unroll
            for (int k = 0; k < 4; k++) acc[i][j][k] = 0.f;

    auto loadChunk = [&](int kc, int c) {
        const uint32_t bufb = sb + c * BUFSZ;
        #pragma unroll
        for (int p = 0; p < LA; p++) {
            int idx = tid + p * THREADS;
            int row = idx >> 3, c16 = idx & 7;
            uint32_t sw = SWZ128((uint32_t)(row * 128 + c16 * 16));
            const void* gh = Ah + (size_t)(m0 + row) * lda + kc * 64 + c16 * 8;
            const void* gl = Al + (size_t)(m0 + row) * lda + kc * 64 + c16 * 8;
            CP_ASYNC16(bufb + sw, gh);
            CP_ASYNC16(bufb + ABY + sw, gl);
        }
        #pragma unroll
        for (int p = 0; p < LB; p++) {
            int idx = tid + p * THREADS;
            int row = idx >> 3, c16 = idx & 7;
            uint32_t sw = SWZ128((uint32_t)(row * 128 + c16 * 16));
            const void* gh = Bh + (size_t)(n0 + row) * ldb + kc * 64 + c16 * 8;
            CP_ASYNC16(bufb + 2 * ABY + sw, gh);
        }
        CP_COMMIT();
    };

    loadChunk(0, 0);
    if (NKC > 1) loadChunk(1, 1); else CP_COMMIT();

    for (int kc = 0; kc < NKC; kc++) {
        const int c = kc & 1;
        if (kc + 1 < NKC) CP_WAIT1(); else CP_WAIT0();
        __syncthreads();
        const uint32_t ahb = sb + c * BUFSZ;
        const uint32_t alb = ahb + ABY;
        const uint32_t bhb = ahb + 2 * ABY;
        #pragma unroll
        for (int ks = 0; ks < 4; ks++) {
            const int k0 = ks * 16 + lk;
            uint32_t fah[MI][4], fal[MI][4], fbh[NB2][4];
            #pragma unroll
            for (int bi = 0; bi < MI; bi++) {
                int r = wrow * WM + bi * 16 + lrow;
                ldm_x4(fah[bi], ahb + SWZ128((uint32_t)(r * 128 + k0 * 2)));
                ldm_x4(fal[bi], alb + SWZ128((uint32_t)(r * 128 + k0 * 2)));
            }
            #pragma unroll
            for (int bj2 = 0; bj2 < NB2; bj2++) {
                int r = wcol * WN + bj2 * 16 + lrow;
                ldm_x4(fbh[bj2], bhb + SWZ128((uint32_t)(r * 128 + k0 * 2)));
            }
            #pragma unroll
            for (int bi = 0; bi < MI; bi++) {
                #pragma unroll
                for (int bj = 0; bj < NJ; bj++) {
                    uint32_t bh0 = fbh[bj >> 1][bj & 1], bh1 = fbh[bj >> 1][2 + (bj & 1)];
                    mma_fp16(acc[bi][bj], fah[bi], bh0, bh1);
                    mma_fp16(acc[bi][bj], fal[bi], bh0, bh1);
                }
            }
        }
        __syncthreads();
        if (kc + 2 < NKC) loadChunk(kc + 2, c);
    }

    const int grp = (n0 >> 5) + wcol;

    if (EPI == 1) {
        /* staged transposed fp16 store (TM=TN=128): O1[n*K2P+m], zero-pad m>=CH */
        const int LDE = 136;
        __half* sh = (__half*)smem;
        const int mlim = (CH - m0 < 128) ? (CH - m0 < 0 ? 0 : CH - m0) : 128;
        const int zlim = (K2P - m0 < 128) ? (K2P - m0 < 0 ? 0 : K2P - m0) : 128;
        #pragma unroll
        for (int bi = 0; bi < MI; bi++) {
            #pragma unroll
            for (int h0 = 0; h0 < 2; h0++) {
                const int ml = wrow * WM + bi * 16 + quad + 8 * h0;
                const int m = m0 + ml;
                if (m < CH) {
                    const float be = p0[(size_t)m * BGC + grp];
                    const float bnm = p1[m];
                    const float sc  = rsqrtf(p2[m] + EPSV) * p3[m];
                    const float bb  = p4[m];
                    #pragma unroll
                    for (int bj = 0; bj < NJ; bj++) {
                        #pragma unroll
                        for (int e = 0; e < 2; e++) {
                            int nl = wcol * WN + bj * 8 + 2 * tq + e;
                            float v = acc[bi][bj][h0 * 2 + e] + be;
                            v = fmaxf((v - bnm) * sc + bb, 0.f);
                            sh[nl * LDE + ml] = __float2half(v);
                        }
                    }
                }
            }
        }
        __syncthreads();
        for (int idx = tid; idx < 128 * 16; idx += THREADS) {
            int nl = idx >> 4, ch = idx & 15;
            int mbeg = ch * 8;
            if (mbeg < zlim) {
                size_t gbase = (size_t)(n0 + nl) * K2P + m0 + mbeg;
                __half tmp[8];
                #pragma unroll
                for (int t = 0; t < 8; t++)
                    tmp[t] = (mbeg + t < mlim) ? sh[nl * LDE + mbeg + t] : __float2half(0.f);
                *(uint4*)(&O1[gbase]) = *(const uint4*)tmp;
            }
        }
        return;
    }

    #pragma unroll
    for (int bi = 0; bi < MI; bi++) {
        #pragma unroll
        for (int h0 = 0; h0 < 2; h0++) {
            const int m = m0 + wrow * WM + bi * 16 + quad + 8 * h0;
            if (EPI == 2) {
                float vm = -INFINITY;
                #pragma unroll
                for (int bj = 0; bj < NJ; bj++) {
                    vm = fmaxf(vm, acc[bi][bj][h0 * 2]);
                    vm = fmaxf(vm, acc[bi][bj][h0 * 2 + 1]);
                }
                vm = fmaxf(vm, __shfl_xor_sync(0xffffffffu, vm, 1));
                vm = fmaxf(vm, __shfl_xor_sync(0xffffffffu, vm, 2));
                if (tq == 0) C[(size_t)grp * ENCD + m] = vm + p0[m];
            } else if (EPI == 0) {
                if (m < Mv) {
                    #pragma unroll
                    for (int bj = 0; bj < NJ; bj++) {
                        #pragma unroll
                        for (int e = 0; e < 2; e++) {
                            int n = n0 + wcol * WN + bj * 8 + 2 * tq + e;
                            if (n < Nv) C[(size_t)m * ldc + n] = acc[bi][bj][h0 * 2 + e];
                        }
                    }
                }
            } else { /* EPI 3 */
                if (m < Mv) {
                    #pragma unroll
                    for (int bj = 0; bj < NJ; bj++) {
                        #pragma unroll
                        for (int e = 0; e < 2; e++) {
                            int n = n0 + wcol * WN + bj * 8 + 2 * tq + e;
                            float v = acc[bi][bj][h0 * 2 + e];
                            if (n < DIN) C[(size_t)m * DIN + n] = softplusf(v + p0[n]);
                            else if (n < NXP) C2[(size_t)m * (2 * DSN) + (n - DIN)] = v;
                        }
                    }
                }
            }
        }
    }
}

/* --------------------------- prepass kernels ------------------------------- */
/* fused w0/w1 split: one read of c1w rows */
__global__ void k_split_w01(const float* __restrict__ c1w, long long total) {
    long long i = (long long)blockIdx.x * 256 + threadIdx.x;
    if (i >= total) return;
    int k = (int)(i % K1P);
    long long r = i / K1P;
    float v0 = 0.f, v1 = 0.f;
    if (r < CH && k < FEAT) {
        v0 = c1w[r * (2 * FEAT) + k];
        v1 = c1w[r * (2 * FEAT) + FEAT + k];
    }
    split2h(v0, &g_w0h[i], &g_w0l[i]);
    split2h(v1, &g_w1h[i], &g_w1l[i]);
}
__global__ void k_split_h2(const float* __restrict__ src, int sld, int soff,
                           int R, int K, __half* __restrict__ dh,
                           __half* __restrict__ dl, int Kp, long long total) {
    long long i = (long long)blockIdx.x * 256 + threadIdx.x;
    if (i >= total) return;
    int k = (int)(i % Kp);
    long long r = i / Kp;
    float v = (r < R && k < K) ? src[r * sld + soff + k] : 0.f;
    split2h(v, &dh[i], &dl[i]);
}
/* contiguous fp32 -> fp16, 8/thread */
__global__ void k_cvt8(const float* __restrict__ src, __half* __restrict__ dst,
                       long long total8) {
    long long i = (long long)blockIdx.x * 256 + threadIdx.x;
    if (i >= total8) return;
    const float4* s = (const float4*)src + i * 2;
    float4 a = s[0], b = s[1];
    __half hb[8] = {
        __float2half(a.x), __float2half(a.y), __float2half(a.z), __float2half(a.w),
        __float2half(b.x), __float2half(b.y), __float2half(b.z), __float2half(b.w)
    };
    *(uint4*)(dst + i * 8) = *(const uint4*)hb;
}

/* combined dt/x_proj weights -> single fp16 */
__global__ void k_wcomb(const float* __restrict__ dpw, const float* __restrict__ xpw) {
    long long idx = (long long)blockIdx.x * 256 + threadIdx.x;
    if (idx >= (long long)DEPTH * NXPP * DIN) return;
    int col = (int)(idx % DIN);
    int rem = (int)(idx / DIN);
    int row = rem % NXPP;
    int l   = rem / NXPP;
    const float* xp = xpw + (size_t)l * (DTR + 2 * DSN) * DIN;
    float v = 0.f;
    if (row < DIN) {
        const float* dr = dpw + (size_t)l * DIN * DTR + (size_t)row * DTR;
        #pragma unroll
        for (int t = 0; t < DTR; t++) v = fmaf(dr[t], xp[(size_t)t * DIN + col], v);
    } else if (row < NXP) {
        v = xp[(size_t)(DTR + (row - DIN)) * DIN + col];
    }
    g_wch[idx] = __float2half(v);
}

/* ---------- fused encoder prep: group max -> fgh  AND  nb -> nbh fp16 ------ */
__global__ void k_fgnb(const float* __restrict__ nb) {
    __shared__ float s[NPTS * FEAT];
    int bg = blockIdx.x;
    const float* src = nb + (size_t)bg * NPTS * FEAT;
    for (int t = threadIdx.x; t < NPTS * FEAT; t += blockDim.x) s[t] = src[t];
    __syncthreads();
    /* per-feature max over the 32 points */
    for (int c = threadIdx.x; c < K1P; c += blockDim.x) {
        float m = 0.f;
        if (c < FEAT) {
            m = s[c];
            #pragma unroll
            for (int n = 1; n < NPTS; n++) m = fmaxf(m, s[n * FEAT + c]);
        }
        g_fgh[(size_t)bg * K1P + c] = __float2half(m);
    }
    /* padded fp16 copy of the 32 rows (8 halves/thread, vectorized store) */
    __half* dst = g_nbh + (size_t)bg * NPTS * K1P;
    for (int i8 = threadIdx.x; i8 < NPTS * K1P / 8; i8 += blockDim.x) {
        int base = i8 * 8;
        int row = base / K1P, c = base % K1P;
        __half hb[8];
        #pragma unroll
        for (int j = 0; j < 8; j++)
            hb[j] = (c + j < FEAT) ? __float2half(s[row * FEAT + c + j]) : __float2half(0.f);
        *(uint4*)(dst + base) = *(const uint4*)hb;
    }
}

/* ---------------- visible-index extraction (bool width-robust) ------------ */
__global__ void k_visidx(const unsigned char* __restrict__ m8) {
    if (threadIdx.x != 0) return;
    int b = blockIdx.x;
    int c8 = 0;
    for (int g = 0; g < GG; g++) c8 += (m8[(size_t)b * GG + g] != 0);
    int cnt = 0;
    if (c8 == NMASK) {
        for (int g = 0; g < GG; g++)
            if (!m8[(size_t)b * GG + g]) { if (cnt < GVIS) g_vis[b * GVIS + cnt] = g; cnt++; }
    } else {
        const int* m32 = (const int*)m8;
        for (int g = 0; g < GG; g++)
            if (!m32[(size_t)b * GG + g]) { if (cnt < GVIS) g_vis[b * GVIS + cnt] = g; cnt++; }
    }
}

/* ------------- gather tokens/centers + pos MLP -> initial h ---------------- */
__global__ void k_pos(const float* __restrict__ center,
                      const float* __restrict__ w1, const float* __restrict__ b1,
                      const float* __restrict__ w2, const float* __restrict__ b2) {
    __shared__ float hcache[128];
    __shared__ float cc[3];
    int r = blockIdx.x;
    int b = r / GVIS;
    int g = g_vis[r];
    int tid = threadIdx.x;
    if (tid < 3) cc[tid] = center[((size_t)b * GG + g) * 3 + tid];
    __syncthreads();
    float a = w1[tid * 3] * cc[0] + w1[tid * 3 + 1] * cc[1] + w1[tid * 3 + 2] * cc[2] + b1[tid];
    hcache[tid] = geluf(a);
    __syncthreads();
    const float* tok = g_tokens + ((size_t)b * GG + g) * ENCD;
    for (int e = tid; e < DDIM; e += 128) {
        float acc = b2[e];
        const float* wr = w2 + (size_t)e * 128;
        #pragma unroll 8
        for (int k = 0; k < 128; k++) acc = fmaf(wr[k], hcache[k], acc);
        g_h[(size_t)r * DDIM + e] = acc + tok[e];
    }
}

/* ------------- residual accumulate + LayerNorm -> split fp16 --------------- */
__global__ void k_lnres(int layer, const float* __restrict__ w, const float* __restrict__ b) {
    int r = blockIdx.x, tid = threadIdx.x;
    float* res = g_res + (size_t)r * DDIM;
    const float* h = g_h + (size_t)r * DDIM;
    float v[3], s1 = 0.f, s2 = 0.f;
    #pragma unroll
    for (int i = 0; i < 3; i++) {
        int c = tid + i * 128;
        float x = h[c];
        if (layer > 0) x += res[c];
        v[i] = x; res[c] = x;
        s1 += x; s2 += x * x;
    }
    reduce2_128(s1, s2);
    float mu = s1 * (1.f / DDIM);
    float rstd = rsqrtf(s2 * (1.f / DDIM) - mu * mu + EPSV);
    #pragma unroll
    for (int i = 0; i < 3; i++) {
        int c = tid + i * 128;
        float y = (v[i] - mu) * rstd * w[c] + b[c];
        split2h(y, &g_hnh[(size_t)r * DDIM + c], &g_hnl[(size_t)r * DDIM + c]);
    }
}

/* ---------------- depthwise causal conv (k=4) + SiLU -> fp16 split --------- */
__global__ void k_conv(const float* __restrict__ cw, const float* __restrict__ cb) {
    int idx = blockIdx.x * blockDim.x + threadIdx.x;
    if (idx >= BL * DIN) return;
    int d = idx % DIN, r = idx / DIN;
    int b = r / SEQL, l = r % SEQL;
    float acc = cb[d];
    #pragma unroll
    for (int k = 0; k < DCONV; k++) {
        int ll = l - (DCONV - 1) + k;
        if (ll >= 0) acc = fmaf(cw[d * DCONV + k], g_xz[((size_t)(b * SEQL + ll)) * (2 * DIN) + d], acc);
    }
    float y = siluf(acc);
    g_xi[idx] = y;
    split2h(y, &g_xih[idx], &g_xil[idx]);
}

/* --------------------------- selective scan -> fp16 split ------------------- */
struct ScanIn { float dt, x, z, bl[2 * DSN]; };
__device__ __forceinline__ void scan_load(ScanIn& s, int r, int d) {
    s.dt = g_dt[(size_t)r * DIN + d];
    s.x  = g_xi[(size_t)r * DIN + d];
    s.z  = g_xz[(size_t)r * (2 * DIN) + DIN + d];
    const float4* p = (const float4*)(g_bc + (size_t)r * (2 * DSN));
    #pragma unroll
    for (int i = 0; i < 8; i++) {
        float4 v = p[i];
        s.bl[4 * i] = v.x; s.bl[4 * i + 1] = v.y;
        s.bl[4 * i + 2] = v.z; s.bl[4 * i + 3] = v.w;
    }
}
__global__ void k_scan(const float* __restrict__ alog, const float* __restrict__ Dp) {
    int b = blockIdx.x / 6;
    int d = (blockIdx.x % 6) * 128 + threadIdx.x;
    float A[DSN];
    bool st = true;
    #pragma unroll
    for (int s = 0; s < DSN; s++) {
        A[s] = -expf(alog[(size_t)d * DSN + s]);
        if (fabsf(A[s] + (float)(s + 1)) > 1e-3f) st = false;
    }
    float Dd = Dp[d];
    float h[DSN];
    #pragma unroll
    for (int s = 0; s < DSN; s++) h[s] = 0.f;

    ScanIn cur, nxt;
    scan_load(cur, b * SEQL, d);
    for (int l = 0; l < SEQL; l++) {
        if (l + 1 < SEQL) scan_load(nxt, b * SEQL + l + 1, d);
        float dtx = cur.dt * cur.x;
        float y = 0.f;
        if (st) {
            float q = __expf(cur.dt * A[0]);
            float dA = q;
            #pragma unroll
            for (int s = 0; s < DSN; s++) {
                h[s] = fmaf(dA, h[s], dtx * cur.bl[s]);
                y = fmaf(h[s], cur.bl[DSN + s], y);
                dA *= q;
            }
        } else {
            #pragma unroll
            for (int s = 0; s < DSN; s++) {
                float dA = __expf(cur.dt * A[s]);
                h[s] = fmaf(dA, h[s], dtx * cur.bl[s]);
                y = fmaf(h[s], cur.bl[DSN + s], y);
            }
        }
        float u = (y + cur.x * Dd) * siluf(cur.z);
        size_t o = (size_t)(b * SEQL + l) * DIN + d;
        split2h(u, &g_uh[o], &g_ul[o]);
        cur = nxt;
    }
}

/* ----------------------- final residual + double LN ------------------------ */
__global__ void k_final(float* __restrict__ out,
                        const float* __restrict__ w1, const float* __restrict__ b1,
                        const float* __restrict__ w2, const float* __restrict__ b2) {
    int r = blockIdx.x, tid = threadIdx.x;
    float v[3], s1 = 0.f, s2 = 0.f;
    #pragma unroll
    for (int i = 0; i < 3; i++) {
        int c = tid + i * 128;
        float x = g_res[(size_t)r * DDIM + c] + g_h[(size_t)r * DDIM + c];
        v[i] = x; s1 += x; s2 += x * x;
    }
    reduce2_128(s1, s2);
    float mu = s1 * (1.f / DDIM);
    float rstd = rsqrtf(s2 * (1.f / DDIM) - mu * mu + EPSV);
    s1 = 0.f; s2 = 0.f;
    #pragma unroll
    for (int i = 0; i < 3; i++) {
        int c = tid + i * 128;
        v[i] = (v[i] - mu) * rstd * w1[c] + b1[c];
        s1 += v[i]; s2 += v[i] * v[i];
    }
    reduce2_128(s1, s2);
    mu = s1 * (1.f / DDIM);
    rstd = rsqrtf(s2 * (1.f / DDIM) - mu * mu + EPSV);
    #pragma unroll
    for (int i = 0; i < 3; i++) {
        int c = tid + i * 128;
        out[(size_t)r * DDIM + c] = (v[i] - mu) * rstd * w2[c] + b2[c];
    }
}

/* -------------------------- mask -> output tail ---------------------------- */
__global__ void k_maskout(const unsigned char* __restrict__ m8, float* __restrict__ out, int out_size) {
    if (out_size < OUTH + BB * GG) return;
    __shared__ int use8;
    if (threadIdx.x == 0) {
        int c = 0;
        for (int g = 0; g < GG; g++) c += (m8[g] != 0);
        use8 = (c == NMASK);
    }
    __syncthreads();
    const int* m32 = (const int*)m8;
    for (int i = threadIdx.x; i < BB * GG; i += blockDim.x) {
        float v = use8 ? (m8[i] ? 1.f : 0.f) : (m32[i] ? 1.f : 0.f);
        out[OUTH + i] = v;
    }
}

/* ------------------------------- host driver ------------------------------- */
#define SMEM_128P2 (2 * (2 * 16384 + 16384))       /* 98304 */
#define SMEM_64x128P2 (2 * (2 * 8192 + 16384))     /* 65536 */
#define SMEM_64x64P2 (2 * (2 * 8192 + 8192))       /* 49152 */
#define MT64 13

extern "C" void kernel_launch(void* const* d_in, const int* in_sizes, int n_in,
                              void* d_out, int out_size) {
    (void)in_sizes; (void)n_in;
    const float* nb     = (const float*)d_in[0];
    const float* center = (const float*)d_in[1];
    const unsigned char* mask = (const unsigned char*)d_in[2];
    const float* c1w = (const float*)d_in[3];
    const float* c1b = (const float*)d_in[4];
    const float* bng = (const float*)d_in[5];
    const float* bnb = (const float*)d_in[6];
    const float* bnm = (const float*)d_in[7];
    const float* bnv = (const float*)d_in[8];
    const float* c2w = (const float*)d_in[9];
    const float* c2b = (const float*)d_in[10];
    const float* pw1 = (const float*)d_in[11];
    const float* pb1 = (const float*)d_in[12];
    const float* pw2 = (const float*)d_in[13];
    const float* pb2 = (const float*)d_in[14];
    const float* ipw = (const float*)d_in[15];
    const float* cw  = (const float*)d_in[16];
    const float* cb  = (const float*)d_in[17];
    const float* xpw = (const float*)d_in[18];
    const float* dpw = (const float*)d_in[19];
    const float* dpb = (const float*)d_in[20];
    const float* alog= (const float*)d_in[21];
    const float* Dp  = (const float*)d_in[22];
    const float* opw = (const float*)d_in[23];
    const float* lnw = (const float*)d_in[24];
    const float* lnb = (const float*)d_in[25];
    const float* nfw = (const float*)d_in[26];
    const float* nfb = (const float*)d_in[27];
    const float* n2w = (const float*)d_in[28];
    const float* n2b = (const float*)d_in[29];
    float* out = (float*)d_out;

    cudaFuncSetAttribute((const void*)k_mma<0, 64, 128, 8>,  cudaFuncAttributeMaxDynamicSharedMemorySize, SMEM_64x128P2);
    cudaFuncSetAttribute((const void*)k_mma<1, 128, 128, 16>, cudaFuncAttributeMaxDynamicSharedMemorySize, SMEM_128P2);
    cudaFuncSetAttribute((const void*)k_mma<2, 128, 128, 16>, cudaFuncAttributeMaxDynamicSharedMemorySize, SMEM_128P2);
    cudaFuncSetAttribute((const void*)k_mma<0, 64, 64, 8>,   cudaFuncAttributeMaxDynamicSharedMemorySize, SMEM_64x64P2);
    cudaFuncSetAttribute((const void*)k_mma<3, 64, 64, 8>,   cudaFuncAttributeMaxDynamicSharedMemorySize, SMEM_64x64P2);

    float *be, *tok, *xz, *xi, *dtb, *bc, *hb;
    cudaGetSymbolAddress((void**)&be,  g_biaseff);
    cudaGetSymbolAddress((void**)&tok, g_tokens);
    cudaGetSymbolAddress((void**)&xz,  g_xz);
    cudaGetSymbolAddress((void**)&xi,  g_xi);
    cudaGetSymbolAddress((void**)&dtb, g_dt);
    cudaGetSymbolAddress((void**)&bc,  g_bc);
    cudaGetSymbolAddress((void**)&hb,  g_h);
    __half *fgh, *w0h, *w0l, *nbh, *w1h, *w1l, *w2h, *w2l, *h1h;
    __half *ipwh, *opwh, *wch, *hnh, *hnl, *xih, *xil, *uh, *ul;
    cudaGetSymbolAddress((void**)&fgh, g_fgh);
    cudaGetSymbolAddress((void**)&w0h, g_w0h);  cudaGetSymbolAddress((void**)&w0l, g_w0l);
    cudaGetSymbolAddress((void**)&nbh, g_nbh);
    cudaGetSymbolAddress((void**)&w1h, g_w1h);  cudaGetSymbolAddress((void**)&w1l, g_w1l);
    cudaGetSymbolAddress((void**)&w2h, g_w2h);  cudaGetSymbolAddress((void**)&w2l, g_w2l);
    cudaGetSymbolAddress((void**)&h1h, g_h1h);
    cudaGetSymbolAddress((void**)&ipwh, g_ipwh);
    cudaGetSymbolAddress((void**)&opwh, g_opwh);
    cudaGetSymbolAddress((void**)&wch, g_wch);
    cudaGetSymbolAddress((void**)&hnh, g_hnh);  cudaGetSymbolAddress((void**)&hnl, g_hnl);
    cudaGetSymbolAddress((void**)&xih, g_xih);  cudaGetSymbolAddress((void**)&xil, g_xil);
    cudaGetSymbolAddress((void**)&uh,  g_uh);   cudaGetSymbolAddress((void**)&ul,  g_ul);

    auto splitN = [](long long total) { return (int)((total + 255) / 256); };
    long long tW1 = (long long)M1P * K1P;
    long long tW2 = (long long)ENCD * K2P;

    /* launches 1-3, then GEMM1 at my slot #4 (ncu -s 5 -c 1 lands there) */
    k_split_w01<<<splitN(tW1), 256>>>(c1w, tW1);
    k_fgnb<<<BGC, 256>>>(nb);
    /* bias-eff: be[546,2048] = c1w[:, :273] @ fg^T */
    k_mma<0, 64, 128, 8><<<dim3(M1P / 64, BGC / 128), 256, SMEM_64x128P2>>>(
        w0h, w0l, K1P, fgh, K1P, K1P / 64,
        nullptr, nullptr, nullptr, nullptr, nullptr,
        be, BGC, nullptr, nullptr, CH, BGC);
    /* GEMM1: D[640,65536] -> H1 fp16 (BN+relu, transposed staged store, pad-zeroed) */
    k_mma<1, 128, 128, 16><<<dim3(M1P / 128, NCOL / 128), 512, SMEM_128P2>>>(
        w1h, w1l, K1P, nbh, K1P, K1P / 64,
        be, bnm, bnv, bng, bnb, nullptr, 0, nullptr, h1h, CH, NCOL);

    k_split_h2<<<splitN(tW2), 256>>>(c2w, CH, 0, ENCD, CH, w2h, w2l, K2P, tW2);
    /* GEMM2: D[384,65536] -> tokens (fused maxpool) */
    k_mma<2, 128, 128, 16><<<dim3(ENCD / 128, NCOL / 128), 512, SMEM_128P2>>>(
        w2h, w2l, K2P, h1h, K2P, K2P / 64,
        c2b, nullptr, nullptr, nullptr, nullptr, tok, 0, nullptr, nullptr, ENCD, NCOL);

    /* mamba weight prepasses */
    long long tIP8 = (long long)DEPTH * 2 * DIN * DDIM / 8;
    k_cvt8<<<splitN(tIP8), 256>>>(ipw, ipwh, tIP8);
    long long tOP8 = (long long)DEPTH * DDIM * DIN / 8;
    k_cvt8<<<splitN(tOP8), 256>>>(opw, opwh, tOP8);
    k_wcomb<<<splitN((long long)DEPTH * NXPP * DIN), 256>>>(dpw, xpw);

    /* gather + pos embed */
    k_visidx<<<BB, 32>>>(mask);
    k_pos<<<BL, 128>>>(center, pw1, pb1, pw2, pb2);

    /* mamba stack */
    for (int i = 0; i < DEPTH; i++) {
        k_lnres<<<BL, 128>>>(i, lnw + (size_t)i * DDIM, lnb + (size_t)i * DDIM);
        /* in_proj (fp16 2-pass) */
        k_mma<0, 64, 128, 8><<<dim3(MT64, 2 * DIN / 128), 256, SMEM_64x128P2>>>(
            hnh, hnl, DDIM, ipwh + (size_t)i * 2 * DIN * DDIM, DDIM,
            DDIM / 64, nullptr, nullptr, nullptr, nullptr, nullptr,
            xz, 2 * DIN, nullptr, nullptr, BL, 2 * DIN);
        k_conv<<<(BL * DIN + 255) / 256, 256>>>(cw + (size_t)i * DIN * DCONV, cb + (size_t)i * DIN);
        /* merged x_proj+dt_proj (fp16 2-pass; dt dominated by fp32 bias) */
        k_mma<3, 64, 64, 8><<<dim3(MT64, NXPP / 64), 256, SMEM_64x64P2>>>(
            xih, xil, DIN, wch + (size_t)i * NXPP * DIN, DIN,
            DIN / 64, dpb + (size_t)i * DIN, nullptr, nullptr, nullptr, nullptr,
            dtb, DIN, bc, nullptr, BL, NXP);
        k_scan<<<BB * 6, 128>>>(alog + (size_t)i * DIN * DSN, Dp + (size_t)i * DIN);
        /* out_proj (fp16 2-pass) */
        k_mma<0, 64, 64, 8><<<dim3(MT64, DDIM / 64), 256, SMEM_64x64P2>>>(
            uh, ul, DIN, opwh + (size_t)i * DDIM * DIN, DIN,
            DIN / 64, nullptr, nullptr, nullptr, nullptr, nullptr,
            hb, DDIM, nullptr, nullptr, BL, DDIM);
    }

    /* final norms + outputs */
    k_final<<<BL, 128>>>(out, nfw, nfb, n2w, n2b);
    k_maskout<<<1, 256>>>(mask, out, out_size);
}

// round 11
// speedup vs baseline: 4.4470x; 1.0320x over previous
#include <cuda_runtime.h>
#include <cuda_bf16.h>
#include <cuda_fp16.h>
#include <math.h>
#include <stdint.h>

#define BB 8
#define GG 256
#define NPTS 32
#define FEAT 273
#define CH 546
#define ENCD 384
#define DDIM 384
#define DEPTH 12
#define DIN 768
#define DSN 16
#define DCONV 4
#define DTR 24
#define GVIS 103
#define SEQL 103
#define BL (BB*GVIS)        /* 824 rows */
#define BLP 896             /* buffer pad */
#define BGC (BB*GG)         /* 2048 groups */
#define NCOL (BGC*NPTS)     /* 65536 point columns */
#define NMASK 153
#define OUTH (BL*DDIM)      /* 316416 */
#define NXP (DIN + 2*DSN)   /* 800 */
#define NXPP 896            /* padded */
#define K1P 320             /* FEAT 273 -> padded */
#define M1P 640             /* CH 546 -> padded  */
#define K2P 576             /* CH 546 -> padded  */
#define EPSV 1e-5f

/* ------------------------- scratch (device globals) ------------------------ */
__device__ float g_biaseff[(size_t)CH * BGC];
__device__ float g_tokens[(size_t)BGC * ENCD];
__device__ int   g_vis[BL];
__device__ float g_h[BL * DDIM];
__device__ float g_res[BL * DDIM];
__device__ float g_xz[BL * 2 * DIN];
__device__ float g_xi[BL * DIN];
__device__ float g_dt[BL * DIN];
__device__ float g_bc[BL * 2 * DSN];

/* fp16 encoder operands */
__device__ __align__(256) __half g_fgh[(size_t)BGC * K1P];
__device__ __align__(256) __half g_w0h[(size_t)M1P * K1P];
__device__ __align__(256) __half g_w0l[(size_t)M1P * K1P];
__device__ __align__(256) __half g_nbh[(size_t)NCOL * K1P];
__device__ __align__(256) __half g_w1h[(size_t)M1P * K1P];
__device__ __align__(256) __half g_w1l[(size_t)M1P * K1P];
__device__ __align__(256) __half g_w2h[(size_t)ENCD * K2P];
__device__ __align__(256) __half g_w2l[(size_t)ENCD * K2P];
__device__ __align__(256) __half g_h1h[(size_t)NCOL * K2P];

/* fp16 mamba operands */
__device__ __align__(256) __half g_ipwh[(size_t)DEPTH * 2 * DIN * DDIM];
__device__ __align__(256) __half g_opwh[(size_t)DEPTH * DDIM * DIN];
__device__ __align__(256) __half g_wch[(size_t)DEPTH * NXPP * DIN];
__device__ __align__(256) __half g_hnh[(size_t)BLP * DDIM];
__device__ __align__(256) __half g_hnl[(size_t)BLP * DDIM];
__device__ __align__(256) __half g_xih[(size_t)BLP * DIN];
__device__ __align__(256) __half g_xil[(size_t)BLP * DIN];
__device__ __align__(256) __half g_uh[(size_t)BLP * DIN];
__device__ __align__(256) __half g_ul[(size_t)BLP * DIN];

/* ------------------------------ small helpers ----------------------------- */
__device__ __forceinline__ float siluf(float x) { return x / (1.f + expf(-x)); }
__device__ __forceinline__ float geluf(float x) { return 0.5f * x * (1.f + erff(x * 0.70710678118654752f)); }
__device__ __forceinline__ float softplusf(float x) { return (x > 20.f) ? x : log1pf(expf(x)); }
__device__ __forceinline__ void split2h(float v, __half* h, __half* l) {
    __half hh = __float2half(v);
    *h = hh;
    *l = __float2half(v - __half2float(hh));
}

__device__ __forceinline__ void reduce2_128(float& s1, float& s2) {
    #pragma unroll
    for (int o = 16; o; o >>= 1) {
        s1 += __shfl_xor_sync(0xffffffffu, s1, o);
        s2 += __shfl_xor_sync(0xffffffffu, s2, o);
    }
    __shared__ float ra[4], rb[4];
    int w = threadIdx.x >> 5, l = threadIdx.x & 31;
    if (l == 0) { ra[w] = s1; rb[w] = s2; }
    __syncthreads();
    s1 = ra[0] + ra[1] + ra[2] + ra[3];
    s2 = rb[0] + rb[1] + rb[2] + rb[3];
    __syncthreads();
}

/* --------------------------- PTX wrappers --------------------------------- */
__device__ __forceinline__ uint32_t smem_u32(const void* p) {
    uint32_t a;
    asm("{ .reg .u64 t; cvta.to.shared.u64 t, %1; cvt.u32.u64 %0, t; }" : "=r"(a) : "l"(p));
    return a;
}
#define SWZ128(o) ((o) ^ (((o) >> 3) & 0x70))
#define CP_ASYNC16(d, s) asm volatile("cp.async.cg.shared.global [%0], [%1], 16;" :: "r"(d), "l"(s))
#define CP_COMMIT()      asm volatile("cp.async.commit_group;" ::: "memory")
#define CP_WAIT1()       asm volatile("cp.async.wait_group 1;" ::: "memory")
#define CP_WAIT0()       asm volatile("cp.async.wait_group 0;" ::: "memory")

__device__ __forceinline__ void ldm_x4(uint32_t* r, uint32_t addr) {
    asm volatile("ldmatrix.sync.aligned.m8n8.x4.shared.b16 {%0,%1,%2,%3}, [%4];"
        : "=r"(r[0]), "=r"(r[1]), "=r"(r[2]), "=r"(r[3]) : "r"(addr));
}
__device__ __forceinline__ void mma_fp16(float* c, const uint32_t* a, uint32_t b0, uint32_t b1) {
    asm volatile("mma.sync.aligned.m16n8k16.row.col.f32.f16.f16.f32 "
        "{%0,%1,%2,%3}, {%4,%5,%6,%7}, {%8,%9}, {%0,%1,%2,%3};"
        : "+f"(c[0]), "+f"(c[1]), "+f"(c[2]), "+f"(c[3])
        : "r"(a[0]), "r"(a[1]), "r"(a[2]), "r"(a[3]), "r"(b0), "r"(b1));
}

/* =================== generic fp16 split mma.sync GEMM ======================
 * D[M,N] = A[M,K] * B[N,K]^T;  A = Ah + Al (fp16 split), B = Bh (single fp16)
 * D = AhBh + AlBh (2 passes, fp32 accumulate).
 * K-major, ld = Kpad. grid = (Mtiles, Ntiles), M fastest (B-tile L2 reuse).
 * NW warps (8: 2x4, 16: 4x4). CTA tile TM x TN. MINB = min CTAs/SM target.
 * EPI 0: C[m*ldc+n] = v               (m<Mv, n<Nv)
 * EPI 1: v+=be[m*BGC+grp]; BN+relu -> O1 fp16 staged [n*K2P+m]; zero-pads m>=CH
 * EPI 2: group maxpool + p0[m] -> C[grp*ENCD+m]  (TN=128 only)
 * EPI 3: n<DIN: C[m*DIN+n]=softplus(v+p0[n]); n<NXP: C2[m*32+n-DIN]=v
 * ========================================================================= */
template<int EPI, int TM, int TN, int NW, int MINB>
__global__ __launch_bounds__(NW * 32, MINB) void k_mma(
    const __half* __restrict__ Ah, const __half* __restrict__ Al, int lda,
    const __half* __restrict__ Bh, int ldb,
    int NKC,
    const float* __restrict__ p0, const float* __restrict__ p1,
    const float* __restrict__ p2, const float* __restrict__ p3,
    const float* __restrict__ p4,
    float* __restrict__ C, int ldc, float* __restrict__ C2,
    __half* __restrict__ O1,
    int Mv, int Nv)
{
    constexpr int THREADS = NW * 32;
    constexpr int WR = NW / 4;
    constexpr int WC = 4;
    constexpr int WM = TM / WR;
    constexpr int WN = TN / WC;
    constexpr int MI = WM / 16;
    constexpr int NJ = WN / 8;
    constexpr int NB2 = (NJ + 1) / 2;
    constexpr int LA = TM * 8 / THREADS;
    constexpr int LB = TN * 8 / THREADS;
    constexpr uint32_t ABY = TM * 128;
    constexpr uint32_t BBY = TN * 128;
    constexpr uint32_t BUFSZ = 2 * ABY + BBY;

    extern __shared__ __align__(1024) char smem[];
    const uint32_t sb = smem_u32(smem);
    const int tid = threadIdx.x, wid = tid >> 5, lid = tid & 31;
    const int wrow = wid >> 2, wcol = wid & 3;
    const int quad = lid >> 2, tq = lid & 3;
    const int m0 = blockIdx.x * TM, n0 = blockIdx.y * TN;

    const int lrow = (lid & 7) + 8 * ((lid >> 3) & 1);
    const int lk   = 8 * (lid >> 4);

    float acc[MI][NJ][4];
    #pragma unroll
    for (int i = 0; i < MI; i++)
        #pragma unroll
        for (int j = 0; j < NJ; j++)
            #pragma unroll
            for (int k = 0; k < 4; k++) acc[i][j][k] = 0.f;

    auto loadChunk = [&](int kc, int c) {
        const uint32_t bufb = sb + c * BUFSZ;
        #pragma unroll
        for (int p = 0; p < LA; p++) {
            int idx = tid + p * THREADS;
            int row = idx >> 3, c16 = idx & 7;
            uint32_t sw = SWZ128((uint32_t)(row * 128 + c16 * 16));
            const void* gh = Ah + (size_t)(m0 + row) * lda + kc * 64 + c16 * 8;
            const void* gl = Al + (size_t)(m0 + row) * lda + kc * 64 + c16 * 8;
            CP_ASYNC16(bufb + sw, gh);
            CP_ASYNC16(bufb + ABY + sw, gl);
        }
        #pragma unroll
        for (int p = 0; p < LB; p++) {
            int idx = tid + p * THREADS;
            int row = idx >> 3, c16 = idx & 7;
            uint32_t sw = SWZ128((uint32_t)(row * 128 + c16 * 16));
            const void* gh = Bh + (size_t)(n0 + row) * ldb + kc * 64 + c16 * 8;
            CP_ASYNC16(bufb + 2 * ABY + sw, gh);
        }
        CP_COMMIT();
    };

    loadChunk(0, 0);
    if (NKC > 1) loadChunk(1, 1); else CP_COMMIT();

    for (int kc = 0; kc < NKC; kc++) {
        const int c = kc & 1;
        if (kc + 1 < NKC) CP_WAIT1(); else CP_WAIT0();
        __syncthreads();
        const uint32_t ahb = sb + c * BUFSZ;
        const uint32_t alb = ahb + ABY;
        const uint32_t bhb = ahb + 2 * ABY;
        #pragma unroll
        for (int ks = 0; ks < 4; ks++) {
            const int k0 = ks * 16 + lk;
            uint32_t fah[MI][4], fal[MI][4], fbh[NB2][4];
            #pragma unroll
            for (int bi = 0; bi < MI; bi++) {
                int r = wrow * WM + bi * 16 + lrow;
                ldm_x4(fah[bi], ahb + SWZ128((uint32_t)(r * 128 + k0 * 2)));
                ldm_x4(fal[bi], alb + SWZ128((uint32_t)(r * 128 + k0 * 2)));
            }
            #pragma unroll
            for (int bj2 = 0; bj2 < NB2; bj2++) {
                int r = wcol * WN + bj2 * 16 + lrow;
                ldm_x4(fbh[bj2], bhb + SWZ128((uint32_t)(r * 128 + k0 * 2)));
            }
            #pragma unroll
            for (int bi = 0; bi < MI; bi++) {
                #pragma unroll
                for (int bj = 0; bj < NJ; bj++) {
                    uint32_t bh0 = fbh[bj >> 1][bj & 1], bh1 = fbh[bj >> 1][2 + (bj & 1)];
                    mma_fp16(acc[bi][bj], fah[bi], bh0, bh1);
                    mma_fp16(acc[bi][bj], fal[bi], bh0, bh1);
                }
            }
        }
        __syncthreads();
        if (kc + 2 < NKC) loadChunk(kc + 2, c);
    }

    const int grp = (n0 >> 5) + wcol;

    if (EPI == 1) {
        /* staged transposed fp16 store (TM=TN=128): O1[n*K2P+m], zero-pad m>=CH */
        const int LDE = 136;
        __half* sh = (__half*)smem;
        const int mlim = (CH - m0 < 128) ? (CH - m0 < 0 ? 0 : CH - m0) : 128;
        const int zlim = (K2P - m0 < 128) ? (K2P - m0 < 0 ? 0 : K2P - m0) : 128;
        #pragma unroll
        for (int bi = 0; bi < MI; bi++) {
            #pragma unroll
            for (int h0 = 0; h0 < 2; h0++) {
                const int ml = wrow * WM + bi * 16 + quad + 8 * h0;
                const int m = m0 + ml;
                if (m < CH) {
                    const float be = p0[(size_t)m * BGC + grp];
                    const float bnm = p1[m];
                    const float sc  = rsqrtf(p2[m] + EPSV) * p3[m];
                    const float bb  = p4[m];
                    #pragma unroll
                    for (int bj = 0; bj < NJ; bj++) {
                        #pragma unroll
                        for (int e = 0; e < 2; e++) {
                            int nl = wcol * WN + bj * 8 + 2 * tq + e;
                            float v = acc[bi][bj][h0 * 2 + e] + be;
                            v = fmaxf((v - bnm) * sc + bb, 0.f);
                            sh[nl * LDE + ml] = __float2half(v);
                        }
                    }
                }
            }
        }
        __syncthreads();
        for (int idx = tid; idx < 128 * 16; idx += THREADS) {
            int nl = idx >> 4, ch = idx & 15;
            int mbeg = ch * 8;
            if (mbeg < zlim) {
                size_t gbase = (size_t)(n0 + nl) * K2P + m0 + mbeg;
                __half tmp[8];
                #pragma unroll
                for (int t = 0; t < 8; t++)
                    tmp[t] = (mbeg + t < mlim) ? sh[nl * LDE + mbeg + t] : __float2half(0.f);
                *(uint4*)(&O1[gbase]) = *(const uint4*)tmp;
            }
        }
        return;
    }

    #pragma unroll
    for (int bi = 0; bi < MI; bi++) {
        #pragma unroll
        for (int h0 = 0; h0 < 2; h0++) {
            const int m = m0 + wrow * WM + bi * 16 + quad + 8 * h0;
            if (EPI == 2) {
                float vm = -INFINITY;
                #pragma unroll
                for (int bj = 0; bj < NJ; bj++) {
                    vm = fmaxf(vm, acc[bi][bj][h0 * 2]);
                    vm = fmaxf(vm, acc[bi][bj][h0 * 2 + 1]);
                }
                vm = fmaxf(vm, __shfl_xor_sync(0xffffffffu, vm, 1));
                vm = fmaxf(vm, __shfl_xor_sync(0xffffffffu, vm, 2));
                if (tq == 0) C[(size_t)grp * ENCD + m] = vm + p0[m];
            } else if (EPI == 0) {
                if (m < Mv) {
                    #pragma unroll
                    for (int bj = 0; bj < NJ; bj++) {
                        #pragma unroll
                        for (int e = 0; e < 2; e++) {
                            int n = n0 + wcol * WN + bj * 8 + 2 * tq + e;
                            if (n < Nv) C[(size_t)m * ldc + n] = acc[bi][bj][h0 * 2 + e];
                        }
                    }
                }
            } else { /* EPI 3 */
                if (m < Mv) {
                    #pragma unroll
                    for (int bj = 0; bj < NJ; bj++) {
                        #pragma unroll
                        for (int e = 0; e < 2; e++) {
                            int n = n0 + wcol * WN + bj * 8 + 2 * tq + e;
                            float v = acc[bi][bj][h0 * 2 + e];
                            if (n < DIN) C[(size_t)m * DIN + n] = softplusf(v + p0[n]);
                            else if (n < NXP) C2[(size_t)m * (2 * DSN) + (n - DIN)] = v;
                        }
                    }
                }
            }
        }
    }
}

/* --------------------------- prepass kernels ------------------------------- */
__global__ void k_split_w01(const float* __restrict__ c1w, long long total) {
    long long i = (long long)blockIdx.x * 256 + threadIdx.x;
    if (i >= total) return;
    int k = (int)(i % K1P);
    long long r = i / K1P;
    float v0 = 0.f, v1 = 0.f;
    if (r < CH && k < FEAT) {
        v0 = c1w[r * (2 * FEAT) + k];
        v1 = c1w[r * (2 * FEAT) + FEAT + k];
    }
    split2h(v0, &g_w0h[i], &g_w0l[i]);
    split2h(v1, &g_w1h[i], &g_w1l[i]);
}
__global__ void k_split_h2(const float* __restrict__ src, int sld, int soff,
                           int R, int K, __half* __restrict__ dh,
                           __half* __restrict__ dl, int Kp, long long total) {
    long long i = (long long)blockIdx.x * 256 + threadIdx.x;
    if (i >= total) return;
    int k = (int)(i % Kp);
    long long r = i / Kp;
    float v = (r < R && k < K) ? src[r * sld + soff + k] : 0.f;
    split2h(v, &dh[i], &dl[i]);
}
__global__ void k_cvt8(const float* __restrict__ src, __half* __restrict__ dst,
                       long long total8) {
    long long i = (long long)blockIdx.x * 256 + threadIdx.x;
    if (i >= total8) return;
    const float4* s = (const float4*)src + i * 2;
    float4 a = s[0], b = s[1];
    __half hb[8] = {
        __float2half(a.x), __float2half(a.y), __float2half(a.z), __float2half(a.w),
        __float2half(b.x), __float2half(b.y), __float2half(b.z), __float2half(b.w)
    };
    *(uint4*)(dst + i * 8) = *(const uint4*)hb;
}

__global__ void k_wcomb(const float* __restrict__ dpw, const float* __restrict__ xpw) {
    long long idx = (long long)blockIdx.x * 256 + threadIdx.x;
    if (idx >= (long long)DEPTH * NXPP * DIN) return;
    int col = (int)(idx % DIN);
    int rem = (int)(idx / DIN);
    int row = rem % NXPP;
    int l   = rem / NXPP;
    const float* xp = xpw + (size_t)l * (DTR + 2 * DSN) * DIN;
    float v = 0.f;
    if (row < DIN) {
        const float* dr = dpw + (size_t)l * DIN * DTR + (size_t)row * DTR;
        #pragma unroll
        for (int t = 0; t < DTR; t++) v = fmaf(dr[t], xp[(size_t)t * DIN + col], v);
    } else if (row < NXP) {
        v = xp[(size_t)(DTR + (row - DIN)) * DIN + col];
    }
    g_wch[idx] = __float2half(v);
}

/* ---------- fused encoder prep: group max -> fgh  AND  nb -> nbh fp16 ------ */
__global__ void k_fgnb(const float* __restrict__ nb) {
    __shared__ float s[NPTS * FEAT];
    int bg = blockIdx.x;
    const float* src = nb + (size_t)bg * NPTS * FEAT;
    for (int t = threadIdx.x; t < NPTS * FEAT; t += blockDim.x) s[t] = src[t];
    __syncthreads();
    for (int c = threadIdx.x; c < K1P; c += blockDim.x) {
        float m = 0.f;
        if (c < FEAT) {
            m = s[c];
            #pragma unroll
            for (int n = 1; n < NPTS; n++) m = fmaxf(m, s[n * FEAT + c]);
        }
        g_fgh[(size_t)bg * K1P + c] = __float2half(m);
    }
    __half* dst = g_nbh + (size_t)bg * NPTS * K1P;
    for (int i8 = threadIdx.x; i8 < NPTS * K1P / 8; i8 += blockDim.x) {
        int base = i8 * 8;
        int row = base / K1P, c = base % K1P;
        __half hb[8];
        #pragma unroll
        for (int j = 0; j < 8; j++)
            hb[j] = (c + j < FEAT) ? __float2half(s[row * FEAT + c + j]) : __float2half(0.f);
        *(uint4*)(dst + base) = *(const uint4*)hb;
    }
}

/* ---------------- visible-index extraction (bool width-robust) ------------ */
__global__ void k_visidx(const unsigned char* __restrict__ m8) {
    if (threadIdx.x != 0) return;
    int b = blockIdx.x;
    int c8 = 0;
    for (int g = 0; g < GG; g++) c8 += (m8[(size_t)b * GG + g] != 0);
    int cnt = 0;
    if (c8 == NMASK) {
        for (int g = 0; g < GG; g++)
            if (!m8[(size_t)b * GG + g]) { if (cnt < GVIS) g_vis[b * GVIS + cnt] = g; cnt++; }
    } else {
        const int* m32 = (const int*)m8;
        for (int g = 0; g < GG; g++)
            if (!m32[(size_t)b * GG + g]) { if (cnt < GVIS) g_vis[b * GVIS + cnt] = g; cnt++; }
    }
}

/* ------------- gather tokens/centers + pos MLP -> initial h ---------------- */
__global__ void k_pos(const float* __restrict__ center,
                      const float* __restrict__ w1, const float* __restrict__ b1,
                      const float* __restrict__ w2, const float* __restrict__ b2) {
    __shared__ float hcache[128];
    __shared__ float cc[3];
    int r = blockIdx.x;
    int b = r / GVIS;
    int g = g_vis[r];
    int tid = threadIdx.x;
    if (tid < 3) cc[tid] = center[((size_t)b * GG + g) * 3 + tid];
    __syncthreads();
    float a = w1[tid * 3] * cc[0] + w1[tid * 3 + 1] * cc[1] + w1[tid * 3 + 2] * cc[2] + b1[tid];
    hcache[tid] = geluf(a);
    __syncthreads();
    const float* tok = g_tokens + ((size_t)b * GG + g) * ENCD;
    for (int e = tid; e < DDIM; e += 128) {
        float acc = b2[e];
        const float* wr = w2 + (size_t)e * 128;
        #pragma unroll 8
        for (int k = 0; k < 128; k++) acc = fmaf(wr[k], hcache[k], acc);
        g_h[(size_t)r * DDIM + e] = acc + tok[e];
    }
}

/* ------------- residual accumulate + LayerNorm -> split fp16 --------------- */
__global__ void k_lnres(int layer, const float* __restrict__ w, const float* __restrict__ b) {
    int r = blockIdx.x, tid = threadIdx.x;
    float* res = g_res + (size_t)r * DDIM;
    const float* h = g_h + (size_t)r * DDIM;
    float v[3], s1 = 0.f, s2 = 0.f;
    #pragma unroll
    for (int i = 0; i < 3; i++) {
        int c = tid + i * 128;
        float x = h[c];
        if (layer > 0) x += res[c];
        v[i] = x; res[c] = x;
        s1 += x; s2 += x * x;
    }
    reduce2_128(s1, s2);
    float mu = s1 * (1.f / DDIM);
    float rstd = rsqrtf(s2 * (1.f / DDIM) - mu * mu + EPSV);
    #pragma unroll
    for (int i = 0; i < 3; i++) {
        int c = tid + i * 128;
        float y = (v[i] - mu) * rstd * w[c] + b[c];
        split2h(y, &g_hnh[(size_t)r * DDIM + c], &g_hnl[(size_t)r * DDIM + c]);
    }
}

/* ---------------- depthwise causal conv (k=4) + SiLU -> fp16 split --------- */
__global__ void k_conv(const float* __restrict__ cw, const float* __restrict__ cb) {
    int idx = blockIdx.x * blockDim.x + threadIdx.x;
    if (idx >= BL * DIN) return;
    int d = idx % DIN, r = idx / DIN;
    int b = r / SEQL, l = r % SEQL;
    float acc = cb[d];
    #pragma unroll
    for (int k = 0; k < DCONV; k++) {
        int ll = l - (DCONV - 1) + k;
        if (ll >= 0) acc = fmaf(cw[d * DCONV + k], g_xz[((size_t)(b * SEQL + ll)) * (2 * DIN) + d], acc);
    }
    float y = siluf(acc);
    g_xi[idx] = y;
    split2h(y, &g_xih[idx], &g_xil[idx]);
}

/* --------------------------- selective scan -> fp16 split ------------------- */
struct ScanIn { float dt, x, z, bl[2 * DSN]; };
__device__ __forceinline__ void scan_load(ScanIn& s, int r, int d) {
    s.dt = g_dt[(size_t)r * DIN + d];
    s.x  = g_xi[(size_t)r * DIN + d];
    s.z  = g_xz[(size_t)r * (2 * DIN) + DIN + d];
    const float4* p = (const float4*)(g_bc + (size_t)r * (2 * DSN));
    #pragma unroll
    for (int i = 0; i < 8; i++) {
        float4 v = p[i];
        s.bl[4 * i] = v.x; s.bl[4 * i + 1] = v.y;
        s.bl[4 * i + 2] = v.z; s.bl[4 * i + 3] = v.w;
    }
}
__global__ void k_scan(const float* __restrict__ alog, const float* __restrict__ Dp) {
    int b = blockIdx.x / 6;
    int d = (blockIdx.x % 6) * 128 + threadIdx.x;
    float A[DSN];
    bool st = true;
    #pragma unroll
    for (int s = 0; s < DSN; s++) {
        A[s] = -expf(alog[(size_t)d * DSN + s]);
        if (fabsf(A[s] + (float)(s + 1)) > 1e-3f) st = false;
    }
    float Dd = Dp[d];
    float h[DSN];
    #pragma unroll
    for (int s = 0; s < DSN; s++) h[s] = 0.f;

    ScanIn cur, nxt;
    scan_load(cur, b * SEQL, d);
    for (int l = 0; l < SEQL; l++) {
        if (l + 1 < SEQL) scan_load(nxt, b * SEQL + l + 1, d);
        float dtx = cur.dt * cur.x;
        float y = 0.f;
        if (st) {
            float q = __expf(cur.dt * A[0]);
            float dA = q;
            #pragma unroll
            for (int s = 0; s < DSN; s++) {
                h[s] = fmaf(dA, h[s], dtx * cur.bl[s]);
                y = fmaf(h[s], cur.bl[DSN + s], y);
                dA *= q;
            }
        } else {
            #pragma unroll
            for (int s = 0; s < DSN; s++) {
                float dA = __expf(cur.dt * A[s]);
                h[s] = fmaf(dA, h[s], dtx * cur.bl[s]);
                y = fmaf(h[s], cur.bl[DSN + s], y);
            }
        }
        float u = (y + cur.x * Dd) * siluf(cur.z);
        size_t o = (size_t)(b * SEQL + l) * DIN + d;
        split2h(u, &g_uh[o], &g_ul[o]);
        cur = nxt;
    }
}

/* ----------------------- final residual + double LN ------------------------ */
__global__ void k_final(float* __restrict__ out,
                        const float* __restrict__ w1, const float* __restrict__ b1,
                        const float* __restrict__ w2, const float* __restrict__ b2) {
    int r = blockIdx.x, tid = threadIdx.x;
    float v[3], s1 = 0.f, s2 = 0.f;
    #pragma unroll
    for (int i = 0; i < 3; i++) {
        int c = tid + i * 128;
        float x = g_res[(size_t)r * DDIM + c] + g_h[(size_t)r * DDIM + c];
        v[i] = x; s1 += x; s2 += x * x;
    }
    reduce2_128(s1, s2);
    float mu = s1 * (1.f / DDIM);
    float rstd = rsqrtf(s2 * (1.f / DDIM) - mu * mu + EPSV);
    s1 = 0.f; s2 = 0.f;
    #pragma unroll
    for (int i = 0; i < 3; i++) {
        int c = tid + i * 128;
        v[i] = (v[i] - mu) * rstd * w1[c] + b1[c];
        s1 += v[i]; s2 += v[i] * v[i];
    }
    reduce2_128(s1, s2);
    mu = s1 * (1.f / DDIM);
    rstd = rsqrtf(s2 * (1.f / DDIM) - mu * mu + EPSV);
    #pragma unroll
    for (int i = 0; i < 3; i++) {
        int c = tid + i * 128;
        out[(size_t)r * DDIM + c] = (v[i] - mu) * rstd * w2[c] + b2[c];
    }
}

/* -------------------------- mask -> output tail ---------------------------- */
__global__ void k_maskout(const unsigned char* __restrict__ m8, float* __restrict__ out, int out_size) {
    if (out_size < OUTH + BB * GG) return;
    __shared__ int use8;
    if (threadIdx.x == 0) {
        int c = 0;
        for (int g = 0; g < GG; g++) c += (m8[g] != 0);
        use8 = (c == NMASK);
    }
    __syncthreads();
    const int* m32 = (const int*)m8;
    for (int i = threadIdx.x; i < BB * GG; i += blockDim.x) {
        float v = use8 ? (m8[i] ? 1.f : 0.f) : (m32[i] ? 1.f : 0.f);
        out[OUTH + i] = v;
    }
}

/* ------------------------------- host driver ------------------------------- */
#define SMEM_128P2 (2 * (2 * 16384 + 16384))       /* 98304 */
#define SMEM_64x128P2 (2 * (2 * 8192 + 16384))     /* 65536 */
#define SMEM_64x64P2 (2 * (2 * 8192 + 8192))       /* 49152 */
#define MT64 13

extern "C" void kernel_launch(void* const* d_in, const int* in_sizes, int n_in,
                              void* d_out, int out_size) {
    (void)in_sizes; (void)n_in;
    const float* nb     = (const float*)d_in[0];
    const float* center = (const float*)d_in[1];
    const unsigned char* mask = (const unsigned char*)d_in[2];
    const float* c1w = (const float*)d_in[3];
    const float* c1b = (const float*)d_in[4];
    const float* bng = (const float*)d_in[5];
    const float* bnb = (const float*)d_in[6];
    const float* bnm = (const float*)d_in[7];
    const float* bnv = (const float*)d_in[8];
    const float* c2w = (const float*)d_in[9];
    const float* c2b = (const float*)d_in[10];
    const float* pw1 = (const float*)d_in[11];
    const float* pb1 = (const float*)d_in[12];
    const float* pw2 = (const float*)d_in[13];
    const float* pb2 = (const float*)d_in[14];
    const float* ipw = (const float*)d_in[15];
    const float* cw  = (const float*)d_in[16];
    const float* cb  = (const float*)d_in[17];
    const float* xpw = (const float*)d_in[18];
    const float* dpw = (const float*)d_in[19];
    const float* dpb = (const float*)d_in[20];
    const float* alog= (const float*)d_in[21];
    const float* Dp  = (const float*)d_in[22];
    const float* opw = (const float*)d_in[23];
    const float* lnw = (const float*)d_in[24];
    const float* lnb = (const float*)d_in[25];
    const float* nfw = (const float*)d_in[26];
    const float* nfb = (const float*)d_in[27];
    const float* n2w = (const float*)d_in[28];
    const float* n2b = (const float*)d_in[29];
    float* out = (float*)d_out;

    cudaFuncSetAttribute((const void*)k_mma<0, 64, 128, 8, 3>,  cudaFuncAttributeMaxDynamicSharedMemorySize, SMEM_64x128P2);
    cudaFuncSetAttribute((const void*)k_mma<1, 128, 128, 16, 2>, cudaFuncAttributeMaxDynamicSharedMemorySize, SMEM_128P2);
    cudaFuncSetAttribute((const void*)k_mma<2, 128, 128, 16, 2>, cudaFuncAttributeMaxDynamicSharedMemorySize, SMEM_128P2);
    cudaFuncSetAttribute((const void*)k_mma<0, 64, 64, 8, 3>,   cudaFuncAttributeMaxDynamicSharedMemorySize, SMEM_64x64P2);
    cudaFuncSetAttribute((const void*)k_mma<3, 64, 64, 8, 3>,   cudaFuncAttributeMaxDynamicSharedMemorySize, SMEM_64x64P2);

    float *be, *tok, *xz, *xi, *dtb, *bc, *hb;
    cudaGetSymbolAddress((void**)&be,  g_biaseff);
    cudaGetSymbolAddress((void**)&tok, g_tokens);
    cudaGetSymbolAddress((void**)&xz,  g_xz);
    cudaGetSymbolAddress((void**)&xi,  g_xi);
    cudaGetSymbolAddress((void**)&dtb, g_dt);
    cudaGetSymbolAddress((void**)&bc,  g_bc);
    cudaGetSymbolAddress((void**)&hb,  g_h);
    __half *fgh, *w0h, *w0l, *nbh, *w1h, *w1l, *w2h, *w2l, *h1h;
    __half *ipwh, *opwh, *wch, *hnh, *hnl, *xih, *xil, *uh, *ul;
    cudaGetSymbolAddress((void**)&fgh, g_fgh);
    cudaGetSymbolAddress((void**)&w0h, g_w0h);  cudaGetSymbolAddress((void**)&w0l, g_w0l);
    cudaGetSymbolAddress((void**)&nbh, g_nbh);
    cudaGetSymbolAddress((void**)&w1h, g_w1h);  cudaGetSymbolAddress((void**)&w1l, g_w1l);
    cudaGetSymbolAddress((void**)&w2h, g_w2h);  cudaGetSymbolAddress((void**)&w2l, g_w2l);
    cudaGetSymbolAddress((void**)&h1h, g_h1h);
    cudaGetSymbolAddress((void**)&ipwh, g_ipwh);
    cudaGetSymbolAddress((void**)&opwh, g_opwh);
    cudaGetSymbolAddress((void**)&wch, g_wch);
    cudaGetSymbolAddress((void**)&hnh, g_hnh);  cudaGetSymbolAddress((void**)&hnl, g_hnl);
    cudaGetSymbolAddress((void**)&xih, g_xih);  cudaGetSymbolAddress((void**)&xil, g_xil);
    cudaGetSymbolAddress((void**)&uh,  g_uh);   cudaGetSymbolAddress((void**)&ul,  g_ul);

    auto splitN = [](long long total) { return (int)((total + 255) / 256); };
    long long tW1 = (long long)M1P * K1P;
    long long tW2 = (long long)ENCD * K2P;

    /* launches 1-3, then GEMM1 at slot #4 (ncu lands there) */
    k_split_w01<<<splitN(tW1), 256>>>(c1w, tW1);
    k_fgnb<<<BGC, 256>>>(nb);
    /* bias-eff: be[546,2048] = c1w[:, :273] @ fg^T */
    k_mma<0, 64, 128, 8, 3><<<dim3(M1P / 64, BGC / 128), 256, SMEM_64x128P2>>>(
        w0h, w0l, K1P, fgh, K1P, K1P / 64,
        nullptr, nullptr, nullptr, nullptr, nullptr,
        be, BGC, nullptr, nullptr, CH, BGC);
    /* GEMM1: D[640,65536] -> H1 fp16 (BN+relu, transposed staged store) */
    k_mma<1, 128, 128, 16, 2><<<dim3(M1P / 128, NCOL / 128), 512, SMEM_128P2>>>(
        w1h, w1l, K1P, nbh, K1P, K1P / 64,
        be, bnm, bnv, bng, bnb, nullptr, 0, nullptr, h1h, CH, NCOL);

    k_split_h2<<<splitN(tW2), 256>>>(c2w, CH, 0, ENCD, CH, w2h, w2l, K2P, tW2);
    /* GEMM2: D[384,65536] -> tokens (fused maxpool) */
    k_mma<2, 128, 128, 16, 2><<<dim3(ENCD / 128, NCOL / 128), 512, SMEM_128P2>>>(
        w2h, w2l, K2P, h1h, K2P, K2P / 64,
        c2b, nullptr, nullptr, nullptr, nullptr, tok, 0, nullptr, nullptr, ENCD, NCOL);

    /* mamba weight prepasses */
    long long tIP8 = (long long)DEPTH * 2 * DIN * DDIM / 8;
    k_cvt8<<<splitN(tIP8), 256>>>(ipw, ipwh, tIP8);
    long long tOP8 = (long long)DEPTH * DDIM * DIN / 8;
    k_cvt8<<<splitN(tOP8), 256>>>(opw, opwh, tOP8);
    k_wcomb<<<splitN((long long)DEPTH * NXPP * DIN), 256>>>(dpw, xpw);

    /* gather + pos embed */
    k_visidx<<<BB, 32>>>(mask);
    k_pos<<<BL, 128>>>(center, pw1, pb1, pw2, pb2);

    /* mamba stack */
    for (int i = 0; i < DEPTH; i++) {
        k_lnres<<<BL, 128>>>(i, lnw + (size_t)i * DDIM, lnb + (size_t)i * DDIM);
        /* in_proj (fp16 2-pass) */
        k_mma<0, 64, 128, 8, 3><<<dim3(MT64, 2 * DIN / 128), 256, SMEM_64x128P2>>>(
            hnh, hnl, DDIM, ipwh + (size_t)i * 2 * DIN * DDIM, DDIM,
            DDIM / 64, nullptr, nullptr, nullptr, nullptr, nullptr,
            xz, 2 * DIN, nullptr, nullptr, BL, 2 * DIN);
        k_conv<<<(BL * DIN + 255) / 256, 256>>>(cw + (size_t)i * DIN * DCONV, cb + (size_t)i * DIN);
        /* merged x_proj+dt_proj (fp16 2-pass) */
        k_mma<3, 64, 64, 8, 3><<<dim3(MT64, NXPP / 64), 256, SMEM_64x64P2>>>(
            xih, xil, DIN, wch + (size_t)i * NXPP * DIN, DIN,
            DIN / 64, dpb + (size_t)i * DIN, nullptr, nullptr, nullptr, nullptr,
            dtb, DIN, bc, nullptr, BL, NXP);
        k_scan<<<BB * 6, 128>>>(alog + (size_t)i * DIN * DSN, Dp + (size_t)i * DIN);
        /* out_proj (fp16 2-pass) */
        k_mma<0, 64, 64, 8, 3><<<dim3(MT64, DDIM / 64), 256, SMEM_64x64P2>>>(
            uh, ul, DIN, opwh + (size_t)i * DDIM * DIN, DIN,
            DIN / 64, nullptr, nullptr, nullptr, nullptr, nullptr,
            hb, DDIM, nullptr, nullptr, BL, DDIM);
    }

    /* final norms + outputs */
    k_final<<<BL, 128>>>(out, nfw, nfb, n2w, n2b);
    k_maskout<<<1, 256>>>(mask, out, out_size);
}